// round 8
// baseline (speedup 1.0000x reference)
#include <cuda_runtime.h>
#include <cuda_bf16.h>
#include <cstdint>

#define B_  8
#define C_  512
#define H_  32
#define W_  32
#define NH_ 8
#define DH_ 64
#define HW_ 1024
#define C3_ (3*C_)

typedef __nv_bfloat16 bf16;

// ---------------- scratch (device globals; no allocation allowed) ----------
__device__ bf16  g_thi[(size_t)B_*HW_*C_];
__device__ bf16  g_tlo[(size_t)B_*HW_*C_];
__device__ bf16  g_w1hi[(size_t)C3_*C_];
__device__ bf16  g_w1lo[(size_t)C3_*C_];
__device__ bf16  g_w2hi[(size_t)C_*C_];
__device__ bf16  g_w2lo[(size_t)C_*C_];
__device__ bf16  g_w3hi[(size_t)C_*C_];
__device__ bf16  g_w3lo[(size_t)C_*C_];
__device__ float g_rs [(size_t)B_*NH_*DH_];
__device__ float g_psq[(size_t)B_*NH_*16*DH_];
__device__ float g_psk[(size_t)B_*NH_*16*DH_];
__device__ bf16  g_qhi[(size_t)B_*NH_*HW_*DH_];
__device__ bf16  g_qlo[(size_t)B_*NH_*HW_*DH_];
__device__ bf16  g_khi[(size_t)B_*NH_*HW_*DH_];
__device__ bf16  g_klo[(size_t)B_*NH_*HW_*DH_];
__device__ bf16  g_vhi[(size_t)B_*NH_*HW_*DH_];
__device__ bf16  g_vlo[(size_t)B_*NH_*HW_*DH_];
__device__ bf16  g_ohi[(size_t)B_*HW_*C_];
__device__ bf16  g_olo[(size_t)B_*HW_*C_];
__device__ float g_ob [(size_t)B_*HW_*C_];
__device__ float g_y  [(size_t)B_*C_*HW_];
__device__ bf16  g_dThi[(size_t)B_*HW_*C_];
__device__ bf16  g_dTlo[(size_t)B_*HW_*C_];

// ---------------- small PTX helpers -----------------------------------------
__device__ __forceinline__ uint32_t smem_u32(const void* p) {
    uint32_t a;
    asm("{ .reg .u64 t; cvta.to.shared.u64 t, %1; cvt.u32.u64 %0, t; }"
        : "=r"(a) : "l"(p));
    return a;
}
__device__ __forceinline__ void cp16(uint32_t s, const void* g) {
    asm volatile("cp.async.cg.shared.global [%0], [%1], 16;" :: "r"(s), "l"(g));
}
#define SWZ(x) ((x) ^ (((x) >> 3) & 0x70u))

__device__ __forceinline__ void ldsm4(uint32_t* r, uint32_t addr) {
    asm volatile("ldmatrix.sync.aligned.m8n8.x4.shared.b16 {%0,%1,%2,%3}, [%4];"
                 : "=r"(r[0]), "=r"(r[1]), "=r"(r[2]), "=r"(r[3]) : "r"(addr));
}
__device__ __forceinline__ void ldsm4t(uint32_t* r, uint32_t addr) {
    asm volatile("ldmatrix.sync.aligned.m8n8.x4.trans.shared.b16 {%0,%1,%2,%3}, [%4];"
                 : "=r"(r[0]), "=r"(r[1]), "=r"(r[2]), "=r"(r[3]) : "r"(addr));
}
__device__ __forceinline__ void mma16816(float* c, const uint32_t* a,
                                         const uint32_t* b) {
    asm volatile(
        "mma.sync.aligned.m16n8k16.row.col.f32.bf16.bf16.f32 "
        "{%0,%1,%2,%3}, {%4,%5,%6,%7}, {%8,%9}, {%0,%1,%2,%3};"
        : "+f"(c[0]), "+f"(c[1]), "+f"(c[2]), "+f"(c[3])
        : "r"(a[0]), "r"(a[1]), "r"(a[2]), "r"(a[3]), "r"(b[0]), "r"(b[1]));
}
__device__ __forceinline__ void split2(float a, float b, uint32_t& hi, uint32_t& lo) {
    __nv_bfloat16 ha = __float2bfloat16(a), hb = __float2bfloat16(b);
    __nv_bfloat162 h; h.x = ha; h.y = hb;
    hi = *(uint32_t*)&h;
    __nv_bfloat162 l;
    l.x = __float2bfloat16(a - __bfloat162float(ha));
    l.y = __float2bfloat16(b - __bfloat162float(hb));
    lo = *(uint32_t*)&l;
}

// ---------------- HMMA GEMM: D[128,128] = A @ B^T via bf16 hi/lo split ------
#define GTB   16384u
#define GSMEM (1024 + 8 * 16384)

__device__ __forceinline__ void load_chunk(
    uint32_t dst, int tid, int m0, int n0, int K, int kc, bool t3,
    const bf16* __restrict__ Ahi, const bf16* __restrict__ Alo,
    const bf16* __restrict__ Bhi, const bf16* __restrict__ Blo) {
#pragma unroll
    for (int it = 0; it < 4; it++) {
        int idx = it * 256 + tid;
        int r = idx >> 3, cg = idx & 7;
        uint32_t so = SWZ((uint32_t)(r * 128 + cg * 16));
        size_t ga = (size_t)(m0 + r) * K + kc + cg * 8;
        size_t gb = (size_t)(n0 + r) * K + kc + cg * 8;
        cp16(dst            + so, Ahi + ga);
        if (t3) cp16(dst + GTB + so, Alo + ga);
        cp16(dst + 2u * GTB + so, Bhi + gb);
        cp16(dst + 3u * GTB + so, Blo + gb);
    }
    asm volatile("cp.async.commit_group;" ::: "memory");
}

__global__ __launch_bounds__(256, 1)
void gemm_tc(const bf16* __restrict__ Ahi, const bf16* __restrict__ Alo,
             const bf16* __restrict__ Bhi, const bf16* __restrict__ Blo,
             const float* __restrict__ bias, const float* __restrict__ resid,
             float* __restrict__ Cout, int K, int Nld,
             long bBatch, long cBatch, int mode, int n2term) {
    extern __shared__ char smc[];
    uint32_t sb = smem_u32(smc);
    int tid = threadIdx.x, wid = tid >> 5, lane = tid & 31;
    int m0 = blockIdx.y * 128, n0 = blockIdx.x * 128;
    const bool t3 = (n0 >= n2term);
    Bhi += (size_t)blockIdx.z * bBatch;
    Blo += (size_t)blockIdx.z * bBatch;
    if (Cout) Cout += (size_t)blockIdx.z * cBatch;
    const float* res = resid ? resid + (size_t)blockIdx.z * cBatch : nullptr;

    float* bsm = (float*)smc;
    if (tid < 128) bsm[tid] = bias ? bias[n0 + tid] : 0.f;

    const uint32_t t0 = sb + 1024;
    const int nchunk = K >> 6;
    const int mb = (wid & 3) * 32;
    const int nb = (wid >> 2) * 64;

    float acc[2][8][4];
#pragma unroll
    for (int i = 0; i < 2; i++)
#pragma unroll
        for (int j = 0; j < 8; j++)
#pragma unroll
            for (int q = 0; q < 4; q++) acc[i][j][q] = 0.f;

    load_chunk(t0, tid, m0, n0, K, 0, t3, Ahi, Alo, Bhi, Blo);
    for (int c = 0; c < nchunk; c++) {
        if (c + 1 < nchunk) {
            load_chunk(t0 + (uint32_t)((c + 1) & 1) * (4u * GTB), tid, m0, n0, K,
                       (c + 1) << 6, t3, Ahi, Alo, Bhi, Blo);
            asm volatile("cp.async.wait_group 1;" ::: "memory");
        } else {
            asm volatile("cp.async.wait_group 0;" ::: "memory");
        }
        __syncthreads();
        uint32_t bufA = t0 + (uint32_t)(c & 1) * (4u * GTB);
#pragma unroll
        for (int ks = 0; ks < 4; ks++) {
            int kb = ks * 32;
            uint32_t ao = SWZ((uint32_t)((mb + (lane & 15)) * 128 +
                                         (lane >> 4) * 16 + kb));
            uint32_t ahi[4], alo[4];
            ldsm4(ahi, bufA + ao);
            if (t3) ldsm4(alo, bufA + GTB + ao);
            uint32_t ao2 = SWZ((uint32_t)((mb + 16 + (lane & 15)) * 128 +
                                          (lane >> 4) * 16 + kb));
            uint32_t ahi2[4], alo2[4];
            ldsm4(ahi2, bufA + ao2);
            if (t3) ldsm4(alo2, bufA + GTB + ao2);
            uint32_t brow = (uint32_t)((nb + (lane & 7) + ((lane >> 4) & 1) * 8) * 128 +
                                       ((lane >> 3) & 1) * 16 + kb);
#pragma unroll
            for (int ntp = 0; ntp < 4; ntp++) {
                uint32_t bo = SWZ(brow + (uint32_t)(ntp * 16 * 128));
                uint32_t bhi[4], blo[4];
                ldsm4(bhi, bufA + 2u * GTB + bo);
                ldsm4(blo, bufA + 3u * GTB + bo);
#pragma unroll
                for (int half = 0; half < 2; half++) {
                    int nt = ntp * 2 + half;
                    const uint32_t bh[2] = {bhi[half * 2], bhi[half * 2 + 1]};
                    const uint32_t bl[2] = {blo[half * 2], blo[half * 2 + 1]};
                    mma16816(acc[0][nt], ahi, bh);
                    mma16816(acc[0][nt], ahi, bl);
                    mma16816(acc[1][nt], ahi2, bh);
                    mma16816(acc[1][nt], ahi2, bl);
                    if (t3) {
                        mma16816(acc[0][nt], alo, bh);
                        mma16816(acc[1][nt], alo2, bh);
                    }
                }
            }
        }
        __syncthreads();
    }

    int rbase = m0 + mb + (lane >> 2);
    int cbase = nb + (lane & 3) * 2;
#pragma unroll
    for (int mt = 0; mt < 2; mt++) {
#pragma unroll
        for (int nt = 0; nt < 8; nt++) {
            int ncol = cbase + nt * 8;
            int gcol = n0 + ncol;
#pragma unroll
            for (int rr = 0; rr < 2; rr++) {
                int row = rbase + mt * 16 + rr * 8;
                float v0 = acc[mt][nt][rr * 2 + 0];
                float v1 = acc[mt][nt][rr * 2 + 1];
                if (mode == 0) {
                    v0 += bsm[ncol]; v1 += bsm[ncol + 1];
                    size_t idx = (size_t)row * Nld + gcol;
                    if (res) {
                        float2 q = *(const float2*)(res + idx);
                        v0 += q.x; v1 += q.y;
                    }
                    float2 o; o.x = v0; o.y = v1;
                    *(float2*)(Cout + idx) = o;
                } else {
                    int b = row >> 10, tok = row & 1023;
                    int region = gcol >> 9;        // 0=q 1=k 2=v
                    int hd = gcol & 511;
                    int h = hd >> 6, d = hd & 63;
                    size_t dst = (((size_t)(b * NH_ + h) * HW_) + tok) * DH_ + d;
                    uint32_t hi, lo;
                    split2(v0, v1, hi, lo);
                    bf16* ph = (region == 0) ? g_qhi : (region == 1) ? g_khi : g_vhi;
                    bf16* pl = (region == 0) ? g_qlo : (region == 1) ? g_klo : g_vlo;
                    *(uint32_t*)&ph[dst] = hi;
                    *(uint32_t*)&pl[dst] = lo;
                }
            }
        }
    }
}

// ---------------- 1) t = transpose(x) + pos -> bf16 hi/lo --------------------
__global__ void build_t_kernel(const float* __restrict__ x,
                               const float* __restrict__ pos,
                               bf16* __restrict__ thi, bf16* __restrict__ tlo) {
    __shared__ float tile[32][33];
    int b  = blockIdx.z;
    int n0 = blockIdx.x * 32;
    int c0 = blockIdx.y * 32;
    int tx = threadIdx.x, ty = threadIdx.y;
#pragma unroll
    for (int i = 0; i < 4; i++) {
        int c = c0 + ty + i * 8;
        tile[ty + i * 8][tx] = x[((size_t)b * C_ + c) * HW_ + n0 + tx];
    }
    __syncthreads();
#pragma unroll
    for (int i = 0; i < 4; i++) {
        int n = n0 + ty + i * 8;
        int c = c0 + tx;
        float v = tile[tx][ty + i * 8] + pos[(size_t)n * C_ + c];
        bf16 h = __float2bfloat16(v);
        size_t o = ((size_t)b * HW_ + n) * C_ + c;
        thi[o] = h;
        tlo[o] = __float2bfloat16(v - __bfloat162float(h));
    }
}

// ---------------- fused weight splits ----------------------------------------
#define NW1 (C3_*C_)
#define NW2 (C_*C_)
__global__ void splitw_kernel(const float* __restrict__ w1,
                              const float* __restrict__ w2,
                              const float* __restrict__ w3) {
    int i = blockIdx.x * 256 + threadIdx.x;
    const float* src; bf16 *hi, *lo; int idx;
    if (i < NW1)            { src = w1; hi = g_w1hi; lo = g_w1lo; idx = i; }
    else if (i < NW1 + NW2) { src = w2; hi = g_w2hi; lo = g_w2lo; idx = i - NW1; }
    else if (i < NW1+2*NW2) { src = w3; hi = g_w3hi; lo = g_w3lo; idx = i - NW1 - NW2; }
    else return;
    float v = src[idx];
    bf16 h = __float2bfloat16(v);
    hi[idx] = h;
    lo[idx] = __float2bfloat16(v - __bfloat162float(h));
}

// ---------------- rs two-stage reduction (hi-only: norm err ~2^-10) ----------
__global__ void rs1_kernel(float* __restrict__ psq, float* __restrict__ psk) {
    int bx = blockIdx.x;
    int bh = bx >> 4, part = bx & 15;
    int tid = threadIdx.x;
    int d = tid & 63, sub = tid >> 6;
    size_t base = (size_t)bh * HW_ * DH_ + d;
    int n0 = part * 64 + sub * 16;
    float sq = 0.f, sk = 0.f;
#pragma unroll
    for (int n = 0; n < 16; n++) {
        size_t off = base + (size_t)(n0 + n) * DH_;
        float qv = __bfloat162float(g_qhi[off]);
        float kv = __bfloat162float(g_khi[off]);
        sq += qv * qv;
        sk += kv * kv;
    }
    __shared__ float smq[4][64], smk[4][64];
    smq[sub][d] = sq; smk[sub][d] = sk;
    __syncthreads();
    if (tid < 64) {
        float q = (smq[0][d] + smq[1][d]) + (smq[2][d] + smq[3][d]);
        float k = (smk[0][d] + smk[1][d]) + (smk[2][d] + smk[3][d]);
        psq[((size_t)bh * 16 + part) * 64 + d] = q;
        psk[((size_t)bh * 16 + part) * 64 + d] = k;
    }
}

__global__ void rs2_kernel(const float* __restrict__ psq,
                           const float* __restrict__ psk,
                           const float* __restrict__ temp,
                           float* __restrict__ rs) {
    int bh = blockIdx.x, d = threadIdx.x;
    int h = bh % NH_;
    float q = 0.f, k = 0.f;
#pragma unroll
    for (int p = 0; p < 16; p++) {
        q += psq[((size_t)bh * 16 + p) * 64 + d];
        k += psk[((size_t)bh * 16 + p) * 64 + d];
    }
    float qn = fmaxf(sqrtf(q), 1e-12f);
    float kn = fmaxf(sqrtf(k), 1e-12f);
    rs[(size_t)bh * DH_ + d] = temp[h] / (qn * kn);
}

// ---------------- tensor-core fused flash attention --------------------------
// smem: KV double buffer (2x24KB) + persistent Q hi/lo (32KB) + rss.
// occupancy 2: Q frags re-ldsm'd per key tile (keeps regs < 128).
#define FAT_STAGE 24576u
#define FAT_QOFF  49152u
#define FAT_SMEM  (49152 + 32768 + 256)

__device__ __forceinline__ void fat_loadkv(
    uint32_t buf, int tid, size_t kvbase, int kc,
    const bf16* __restrict__ khi,
    const bf16* __restrict__ vhi, const bf16* __restrict__ vlo) {
#pragma unroll
    for (int it = 0; it < 2; it++) {
        int idx = it * 256 + tid;
        int r = idx >> 3, cg = idx & 7;
        uint32_t so = SWZ((uint32_t)(r * 128 + cg * 16));
        size_t g = kvbase + (size_t)(kc + r) * DH_ + cg * 8;
        cp16(buf +     0u + so, khi + g);
        cp16(buf +  8192u + so, vhi + g);
        cp16(buf + 16384u + so, vlo + g);
    }
    asm volatile("cp.async.commit_group;" ::: "memory");
}

__global__ __launch_bounds__(256, 2)
void fat_kernel(const bf16* __restrict__ qhi, const bf16* __restrict__ qlo,
                const float* __restrict__ rs,
                const bf16* __restrict__ khi,
                const bf16* __restrict__ vhi, const bf16* __restrict__ vlo,
                bf16* __restrict__ ohi, bf16* __restrict__ olo) {
    extern __shared__ char smc[];
    uint32_t sb = smem_u32(smc);
    float* rss = (float*)(smc + FAT_QOFF + 32768);
    int bh = blockIdx.y;
    int b = bh >> 3, h = bh & 7;
    int q0 = blockIdx.x * 128;
    int tid = threadIdx.x, wid = tid >> 5, lane = tid & 31;
    int mb = wid * 16;

    if (tid < 64) rss[tid] = rs[bh * DH_ + tid];
    __syncthreads();

    // stage Q (hi+lo recombined, scaled by rs) into persistent smem region
#pragma unroll
    for (int v = 0; v < 8; v++) {
        int idx = v * 256 + tid;
        int row = idx >> 4, dq = (idx & 15) * 4;
        size_t qoff = ((size_t)bh * HW_ + q0 + row) * DH_ + dq;
        __nv_bfloat162 ha = *(const __nv_bfloat162*)&qhi[qoff];
        __nv_bfloat162 hb = *(const __nv_bfloat162*)&qhi[qoff + 2];
        __nv_bfloat162 la = *(const __nv_bfloat162*)&qlo[qoff];
        __nv_bfloat162 lb = *(const __nv_bfloat162*)&qlo[qoff + 2];
        float qx = (__bfloat162float(ha.x) + __bfloat162float(la.x)) * rss[dq];
        float qy = (__bfloat162float(ha.y) + __bfloat162float(la.y)) * rss[dq + 1];
        float qz = (__bfloat162float(hb.x) + __bfloat162float(lb.x)) * rss[dq + 2];
        float qw = (__bfloat162float(hb.y) + __bfloat162float(lb.y)) * rss[dq + 3];
        uint32_t h0, l0, h1, l1;
        split2(qx, qy, h0, l0);
        split2(qz, qw, h1, l1);
        uint32_t off = SWZ((uint32_t)(row * 128 + dq * 2));
        *(uint32_t*)(smc + FAT_QOFF + off)             = h0;
        *(uint32_t*)(smc + FAT_QOFF + off + 4)         = h1;
        *(uint32_t*)(smc + FAT_QOFF + 16384 + off)     = l0;
        *(uint32_t*)(smc + FAT_QOFF + 16384 + off + 4) = l1;
    }
    __syncthreads();

    float o[8][4];
#pragma unroll
    for (int j = 0; j < 8; j++)
#pragma unroll
        for (int q = 0; q < 4; q++) o[j][q] = 0.f;
    float m0 = -1e30f, m1 = -1e30f, l0 = 0.f, l1 = 0.f;
    const size_t kvbase = (size_t)bh * HW_ * DH_;

    fat_loadkv(sb, tid, kvbase, 0, khi, vhi, vlo);
    for (int kt = 0; kt < 16; kt++) {
        uint32_t cur = sb + (uint32_t)(kt & 1) * FAT_STAGE;
        if (kt + 1 < 16) {
            fat_loadkv(sb + (uint32_t)((kt + 1) & 1) * FAT_STAGE, tid, kvbase,
                       (kt + 1) * 64, khi, vhi, vlo);
            asm volatile("cp.async.wait_group 1;" ::: "memory");
        } else {
            asm volatile("cp.async.wait_group 0;" ::: "memory");
        }
        __syncthreads();

        // ---- S = Q.K^T (2-term); Q frags re-loaded from persistent smem
        float s[8][4];
#pragma unroll
        for (int j = 0; j < 8; j++)
#pragma unroll
            for (int q = 0; q < 4; q++) s[j][q] = 0.f;
#pragma unroll
        for (int ks = 0; ks < 4; ks++) {
            uint32_t qao = SWZ((uint32_t)((mb + (lane & 15)) * 128 +
                                          (lane >> 4) * 16 + ks * 32));
            uint32_t qh4[4], ql4[4];
            ldsm4(qh4, sb + FAT_QOFF + qao);
            ldsm4(ql4, sb + FAT_QOFF + 16384u + qao);
            uint32_t brow = (uint32_t)(((lane & 7) + ((lane >> 4) & 1) * 8) * 128 +
                                       ((lane >> 3) & 1) * 16 + ks * 32);
#pragma unroll
            for (int np = 0; np < 4; np++) {
                uint32_t bo = SWZ(brow + (uint32_t)(np * 16 * 128));
                uint32_t kh4[4];
                ldsm4(kh4, cur + bo);
#pragma unroll
                for (int half = 0; half < 2; half++) {
                    int j = np * 2 + half;
                    const uint32_t bhh[2] = {kh4[half * 2], kh4[half * 2 + 1]};
                    mma16816(s[j], qh4, bhh);
                    mma16816(s[j], ql4, bhh);
                }
            }
        }

        // ---- online softmax (rows r=lane>>2 and r+8; quads share rows)
        float mx0 = -1e30f, mx1 = -1e30f;
#pragma unroll
        for (int j = 0; j < 8; j++) {
            mx0 = fmaxf(mx0, fmaxf(s[j][0], s[j][1]));
            mx1 = fmaxf(mx1, fmaxf(s[j][2], s[j][3]));
        }
        mx0 = fmaxf(mx0, __shfl_xor_sync(0xffffffffu, mx0, 1));
        mx0 = fmaxf(mx0, __shfl_xor_sync(0xffffffffu, mx0, 2));
        mx1 = fmaxf(mx1, __shfl_xor_sync(0xffffffffu, mx1, 1));
        mx1 = fmaxf(mx1, __shfl_xor_sync(0xffffffffu, mx1, 2));
        float mn0 = fmaxf(m0, mx0), mn1 = fmaxf(m1, mx1);
        float al0 = __expf(m0 - mn0), al1 = __expf(m1 - mn1);
        float sum0 = 0.f, sum1 = 0.f;
#pragma unroll
        for (int j = 0; j < 8; j++) {
            s[j][0] = __expf(s[j][0] - mn0);
            s[j][1] = __expf(s[j][1] - mn0);
            s[j][2] = __expf(s[j][2] - mn1);
            s[j][3] = __expf(s[j][3] - mn1);
            sum0 += s[j][0] + s[j][1];
            sum1 += s[j][2] + s[j][3];
        }
        sum0 += __shfl_xor_sync(0xffffffffu, sum0, 1);
        sum0 += __shfl_xor_sync(0xffffffffu, sum0, 2);
        sum1 += __shfl_xor_sync(0xffffffffu, sum1, 1);
        sum1 += __shfl_xor_sync(0xffffffffu, sum1, 2);
        l0 = l0 * al0 + sum0; l1 = l1 * al1 + sum1;
        m0 = mn0; m1 = mn1;
#pragma unroll
        for (int j = 0; j < 8; j++) {
            o[j][0] *= al0; o[j][1] *= al0;
            o[j][2] *= al1; o[j][3] *= al1;
        }

        // ---- O += P.V (3-term); P frags packed straight from S frags
#pragma unroll
        for (int ks = 0; ks < 4; ks++) {
            int j0 = 2 * ks, j1 = 2 * ks + 1;
            uint32_t ph[4], pl[4];
            split2(s[j0][0], s[j0][1], ph[0], pl[0]);
            split2(s[j0][2], s[j0][3], ph[1], pl[1]);
            split2(s[j1][0], s[j1][1], ph[2], pl[2]);
            split2(s[j1][2], s[j1][3], ph[3], pl[3]);
            uint32_t vrow = (uint32_t)((ks * 16 + (lane & 7) + ((lane >> 3) & 1) * 8) * 128 +
                                       ((lane >> 4) & 1) * 16);
#pragma unroll
            for (int np = 0; np < 4; np++) {
                uint32_t vo = SWZ(vrow + (uint32_t)(np * 32));
                uint32_t vh4[4], vl4[4];
                ldsm4t(vh4, cur +  8192u + vo);
                ldsm4t(vl4, cur + 16384u + vo);
#pragma unroll
                for (int half = 0; half < 2; half++) {
                    int j = np * 2 + half;
                    const uint32_t bvh[2] = {vh4[half * 2], vh4[half * 2 + 1]};
                    const uint32_t bvl[2] = {vl4[half * 2], vl4[half * 2 + 1]};
                    mma16816(o[j], ph, bvh);
                    mma16816(o[j], ph, bvl);
                    mma16816(o[j], pl, bvh);
                }
            }
        }
        __syncthreads();
    }

    float inv0 = 1.f / l0, inv1 = 1.f / l1;
    int r0 = lane >> 2, cc = (lane & 3) * 2;
    int row0 = q0 + mb + r0, row1 = row0 + 8;
#pragma unroll
    for (int j = 0; j < 8; j++) {
        int col = h * DH_ + j * 8 + cc;
        size_t off0 = ((size_t)(b * HW_ + row0)) * C_ + col;
        size_t off1 = ((size_t)(b * HW_ + row1)) * C_ + col;
        uint32_t hi, lo;
        split2(o[j][0] * inv0, o[j][1] * inv0, hi, lo);
        *(uint32_t*)&ohi[off0] = hi; *(uint32_t*)&olo[off0] = lo;
        split2(o[j][2] * inv1, o[j][3] * inv1, hi, lo);
        *(uint32_t*)&ohi[off1] = hi; *(uint32_t*)&olo[off1] = lo;
    }
}

// ---------------- LayerNorm over C + residual + transpose to [B,C,HW] -------
__global__ void ln_residual_kernel(const float* __restrict__ ob,
                                   const float* __restrict__ x,
                                   const float* __restrict__ g,
                                   const float* __restrict__ be,
                                   float* __restrict__ y) {
    int row = blockIdx.x;
    int b = row >> 10, n = row & 1023;
    const float* pr = ob + (size_t)row * C_;
    int tid = threadIdx.x;
    float v0 = pr[tid], v1 = pr[tid + 256];
    __shared__ float red[256];
    red[tid] = v0 + v1; __syncthreads();
    for (int s = 128; s > 0; s >>= 1) {
        if (tid < s) red[tid] += red[tid + s];
        __syncthreads();
    }
    float mean = red[0] * (1.0f / C_);
    __syncthreads();
    float d0 = v0 - mean, d1 = v1 - mean;
    red[tid] = d0 * d0 + d1 * d1; __syncthreads();
    for (int s = 128; s > 0; s >>= 1) {
        if (tid < s) red[tid] += red[tid + s];
        __syncthreads();
    }
    float rstd = rsqrtf(red[0] * (1.0f / C_) + 1e-5f);
    int c0 = tid, c1 = tid + 256;
    size_t i0 = ((size_t)b * C_ + c0) * HW_ + n;
    size_t i1 = ((size_t)b * C_ + c1) * HW_ + n;
    y[i0] = d0 * rstd * g[c0] + be[c0] + x[i0];
    y[i1] = d1 * rstd * g[c1] + be[c1] + x[i1];
}

// ---------------- fused depthwise 3x3 + transpose + split --------------------
__global__ void dwt_kernel(const float* __restrict__ y,
                           const float* __restrict__ w,
                           const float* __restrict__ bias,
                           bf16* __restrict__ hi, bf16* __restrict__ lo) {
    __shared__ float yt[32][3][33];
    __shared__ float ot[32][33];   // [w][c]
    int hh = blockIdx.x, c0 = blockIdx.y * 32, b = blockIdx.z;
    int tid = threadIdx.x;
    int c = tid >> 3, wg = (tid & 7) * 4;

#pragma unroll
    for (int r = 0; r < 3; r++) {
        int ih = hh + r - 1;
        float4 v = make_float4(0.f, 0.f, 0.f, 0.f);
        if (ih >= 0 && ih < H_)
            v = *(const float4*)&y[((size_t)(b * C_ + c0 + c)) * HW_ + ih * W_ + wg];
        yt[c][r][wg + 0] = v.x; yt[c][r][wg + 1] = v.y;
        yt[c][r][wg + 2] = v.z; yt[c][r][wg + 3] = v.w;
    }
    float wc[9];
#pragma unroll
    for (int i = 0; i < 9; i++) wc[i] = w[(c0 + c) * 9 + i];
    float bs = bias[c0 + c];
    __syncthreads();

#pragma unroll
    for (int j = 0; j < 4; j++) {
        int ww = wg + j;
        float acc = bs;
#pragma unroll
        for (int ki = 0; ki < 3; ki++)
#pragma unroll
            for (int kj = 0; kj < 3; kj++) {
                int iw = ww + kj - 1;
                if (iw >= 0 && iw < W_) acc += wc[ki * 3 + kj] * yt[c][ki][iw];
            }
        ot[ww][c] = acc;
    }
    __syncthreads();

    int w2 = tid >> 3, cg = (tid & 7) * 4;
    int token = hh * W_ + w2;
    size_t base = ((size_t)b * HW_ + token) * C_ + c0 + cg;
    float a0 = ot[w2][cg], a1 = ot[w2][cg + 1];
    float a2 = ot[w2][cg + 2], a3 = ot[w2][cg + 3];
    uint32_t h0, l0, h1, l1;
    split2(a0, a1, h0, l0);
    split2(a2, a3, h1, l1);
    *(uint32_t*)&hi[base]     = h0; *(uint32_t*)&hi[base + 2] = h1;
    *(uint32_t*)&lo[base]     = l0; *(uint32_t*)&lo[base + 2] = l1;
}

// ---------------- launch ------------------------------------------------------
extern "C" void kernel_launch(void* const* d_in, const int* in_sizes, int n_in,
                              void* d_out, int out_size) {
    const float* x      = (const float*)d_in[0];
    const float* qkv_w  = (const float*)d_in[1];
    const float* proj_w = (const float*)d_in[2];
    const float* proj_b = (const float*)d_in[3];
    const float* temper = (const float*)d_in[4];
    const float* ln_g   = (const float*)d_in[5];
    const float* ln_b   = (const float*)d_in[6];
    const float* pos    = (const float*)d_in[7];
    const float* dw_w   = (const float*)d_in[8];
    const float* dw_b   = (const float*)d_in[9];
    const float* pw_w   = (const float*)d_in[10];
    const float* pw_b   = (const float*)d_in[11];
    float* out = (float*)d_out;

    bf16 *thi, *tlo, *w1hi, *w1lo, *w2hi, *w2lo, *w3hi, *w3lo;
    bf16 *ohi, *olo, *dThi, *dTlo, *qhi, *qlo, *khi, *vhi, *vlo;
    float *rs, *ob, *y, *psq, *psk;
    cudaGetSymbolAddress((void**)&thi,  g_thi);
    cudaGetSymbolAddress((void**)&tlo,  g_tlo);
    cudaGetSymbolAddress((void**)&w1hi, g_w1hi);
    cudaGetSymbolAddress((void**)&w1lo, g_w1lo);
    cudaGetSymbolAddress((void**)&w2hi, g_w2hi);
    cudaGetSymbolAddress((void**)&w2lo, g_w2lo);
    cudaGetSymbolAddress((void**)&w3hi, g_w3hi);
    cudaGetSymbolAddress((void**)&w3lo, g_w3lo);
    cudaGetSymbolAddress((void**)&ohi,  g_ohi);
    cudaGetSymbolAddress((void**)&olo,  g_olo);
    cudaGetSymbolAddress((void**)&dThi, g_dThi);
    cudaGetSymbolAddress((void**)&dTlo, g_dTlo);
    cudaGetSymbolAddress((void**)&qhi,  g_qhi);
    cudaGetSymbolAddress((void**)&qlo,  g_qlo);
    cudaGetSymbolAddress((void**)&khi,  g_khi);
    cudaGetSymbolAddress((void**)&vhi,  g_vhi);
    cudaGetSymbolAddress((void**)&vlo,  g_vlo);
    cudaGetSymbolAddress((void**)&rs,   g_rs);
    cudaGetSymbolAddress((void**)&psq,  g_psq);
    cudaGetSymbolAddress((void**)&psk,  g_psk);
    cudaGetSymbolAddress((void**)&ob,   g_ob);
    cudaGetSymbolAddress((void**)&y,    g_y);

    cudaFuncSetAttribute(fat_kernel,
                         cudaFuncAttributeMaxDynamicSharedMemorySize, FAT_SMEM);
    cudaFuncSetAttribute(gemm_tc,
                         cudaFuncAttributeMaxDynamicSharedMemorySize, GSMEM);

    // fused weight splits
    splitw_kernel<<<(NW1 + 2*NW2 + 255)/256, 256>>>(qkv_w, proj_w, pw_w);
    // t = transpose(x) + pos (bf16 split)
    build_t_kernel<<<dim3(HW_/32, C_/32, B_), dim3(32, 8)>>>(x, pos, thi, tlo);
    // qkv GEMM: q,k columns 2-term; v columns 3-term; split head-major output
    gemm_tc<<<dim3(C3_/128, (B_*HW_)/128, 1), 256, GSMEM>>>(
        thi, tlo, w1hi, w1lo, nullptr, nullptr, nullptr, C_, 0, 0, 0,
        1 /*mode=qkv*/, 1024 /*n2term: v cols 3-term*/);
    // rs two-stage reduction (parallel, deterministic, hi-only)
    rs1_kernel<<<B_*NH_*16, 256>>>(psq, psk);
    rs2_kernel<<<B_*NH_, 64>>>(psq, psk, temper, rs);
    // tensor-core fused attention -> o (bf16 split), occupancy 2
    fat_kernel<<<dim3(HW_/128, B_*NH_), 256, FAT_SMEM>>>(
        qhi, qlo, rs, khi, vhi, vlo, ohi, olo);
    // proj = o @ proj_w^T + proj_b (full 3-term)
    gemm_tc<<<dim3(C_/128, (B_*HW_)/128, 1), 256, GSMEM>>>(
        ohi, olo, w2hi, w2lo, proj_b, nullptr, ob, C_, C_, 0, 0, 0, 0);
    // LN + residual + transpose to [B,C,HW]
    ln_residual_kernel<<<B_*HW_, 256>>>(ob, x, ln_g, ln_b, y);
    // fused depthwise 3x3 + transpose + split
    dwt_kernel<<<dim3(H_, C_/32, B_), 256>>>(y, dw_w, dw_b, dThi, dTlo);
    // pointwise (2-term) + bias + residual -> out
    gemm_tc<<<dim3(HW_/128, C_/128, B_), 256, GSMEM>>>(
        w3hi, w3lo, dThi, dTlo, pw_b, y, out, C_, HW_,
        (long)HW_*C_, (long)C_*HW_, 0, 1 << 30);
}

// round 9
// speedup vs baseline: 1.1466x; 1.1466x over previous
#include <cuda_runtime.h>
#include <cuda_fp16.h>
#include <cstdint>

#define B_  8
#define C_  512
#define H_  32
#define W_  32
#define NH_ 8
#define DH_ 64
#define HW_ 1024
#define C3_ (3*C_)

typedef __half h16;

// ---------------- scratch (device globals; no allocation allowed) ----------
__device__ h16   g_thi[(size_t)B_*HW_*C_];
__device__ h16   g_tlo[(size_t)B_*HW_*C_];
__device__ h16   g_w1hi[(size_t)C3_*C_];
__device__ h16   g_w1lo[(size_t)C3_*C_];
__device__ h16   g_w2hi[(size_t)C_*C_];
__device__ h16   g_w2lo[(size_t)C_*C_];
__device__ h16   g_w3hi[(size_t)C_*C_];
__device__ h16   g_w3lo[(size_t)C_*C_];
__device__ float g_rs [(size_t)B_*NH_*DH_];
__device__ float g_psq[(size_t)B_*NH_*16*DH_];
__device__ float g_psk[(size_t)B_*NH_*16*DH_];
__device__ h16   g_qhi[(size_t)B_*NH_*HW_*DH_];
__device__ h16   g_qlo[(size_t)B_*NH_*HW_*DH_];
__device__ h16   g_khi[(size_t)B_*NH_*HW_*DH_];
__device__ h16   g_klo[(size_t)B_*NH_*HW_*DH_];
__device__ h16   g_vhi[(size_t)B_*NH_*HW_*DH_];
__device__ h16   g_vlo[(size_t)B_*NH_*HW_*DH_];
__device__ h16   g_ohi[(size_t)B_*HW_*C_];
__device__ h16   g_olo[(size_t)B_*HW_*C_];
__device__ float g_ob [(size_t)B_*HW_*C_];
__device__ float g_y  [(size_t)B_*C_*HW_];
__device__ h16   g_dThi[(size_t)B_*HW_*C_];
__device__ h16   g_dTlo[(size_t)B_*HW_*C_];

// ---------------- small PTX helpers -----------------------------------------
__device__ __forceinline__ uint32_t smem_u32(const void* p) {
    uint32_t a;
    asm("{ .reg .u64 t; cvta.to.shared.u64 t, %1; cvt.u32.u64 %0, t; }"
        : "=r"(a) : "l"(p));
    return a;
}
__device__ __forceinline__ void cp16(uint32_t s, const void* g) {
    asm volatile("cp.async.cg.shared.global [%0], [%1], 16;" :: "r"(s), "l"(g));
}
#define SWZ(x) ((x) ^ (((x) >> 3) & 0x70u))

__device__ __forceinline__ void ldsm4(uint32_t* r, uint32_t addr) {
    asm volatile("ldmatrix.sync.aligned.m8n8.x4.shared.b16 {%0,%1,%2,%3}, [%4];"
                 : "=r"(r[0]), "=r"(r[1]), "=r"(r[2]), "=r"(r[3]) : "r"(addr));
}
__device__ __forceinline__ void ldsm4t(uint32_t* r, uint32_t addr) {
    asm volatile("ldmatrix.sync.aligned.m8n8.x4.trans.shared.b16 {%0,%1,%2,%3}, [%4];"
                 : "=r"(r[0]), "=r"(r[1]), "=r"(r[2]), "=r"(r[3]) : "r"(addr));
}
__device__ __forceinline__ void mma16816(float* c, const uint32_t* a,
                                         const uint32_t* b) {
    asm volatile(
        "mma.sync.aligned.m16n8k16.row.col.f32.f16.f16.f32 "
        "{%0,%1,%2,%3}, {%4,%5,%6,%7}, {%8,%9}, {%0,%1,%2,%3};"
        : "+f"(c[0]), "+f"(c[1]), "+f"(c[2]), "+f"(c[3])
        : "r"(a[0]), "r"(a[1]), "r"(a[2]), "r"(a[3]), "r"(b[0]), "r"(b[1]));
}
__device__ __forceinline__ void split2(float a, float b, uint32_t& hi, uint32_t& lo) {
    __half ha = __float2half(a), hb = __float2half(b);
    __half2 h; h.x = ha; h.y = hb;
    hi = *(uint32_t*)&h;
    __half2 l;
    l.x = __float2half(a - __half2float(ha));
    l.y = __float2half(b - __half2float(hb));
    lo = *(uint32_t*)&l;
}
__device__ __forceinline__ uint32_t pack2(float a, float b) {
    __half2 h; h.x = __float2half(a); h.y = __float2half(b);
    return *(uint32_t*)&h;
}

// ---------------- HMMA GEMM: D[128,128] = A @ B^T via fp16 hi/lo split ------
// nt per CTA: 1 = ahi*bhi; 2 = + ahi*blo; 3 = + alo*bhi (~fp32 exact).
// nt = (n0 >= n3start) ? 3 : ntLow.
#define GTB   16384u
#define GSMEM (1024 + 8 * 16384)

__device__ __forceinline__ void load_chunk(
    uint32_t dst, int tid, int m0, int n0, int K, int kc, int nt,
    const h16* __restrict__ Ahi, const h16* __restrict__ Alo,
    const h16* __restrict__ Bhi, const h16* __restrict__ Blo) {
#pragma unroll
    for (int it = 0; it < 4; it++) {
        int idx = it * 256 + tid;
        int r = idx >> 3, cg = idx & 7;
        uint32_t so = SWZ((uint32_t)(r * 128 + cg * 16));
        size_t ga = (size_t)(m0 + r) * K + kc + cg * 8;
        size_t gb = (size_t)(n0 + r) * K + kc + cg * 8;
        cp16(dst            + so, Ahi + ga);
        if (nt == 3) cp16(dst + GTB + so, Alo + ga);
        cp16(dst + 2u * GTB + so, Bhi + gb);
        if (nt >= 2) cp16(dst + 3u * GTB + so, Blo + gb);
    }
    asm volatile("cp.async.commit_group;" ::: "memory");
}

__global__ __launch_bounds__(256, 1)
void gemm_tc(const h16* __restrict__ Ahi, const h16* __restrict__ Alo,
             const h16* __restrict__ Bhi, const h16* __restrict__ Blo,
             const float* __restrict__ bias, const float* __restrict__ resid,
             float* __restrict__ Cout, int K, int Nld,
             long bBatch, long cBatch, int mode, int ntLow, int n3start) {
    extern __shared__ char smc[];
    uint32_t sb = smem_u32(smc);
    int tid = threadIdx.x, wid = tid >> 5, lane = tid & 31;
    int m0 = blockIdx.y * 128, n0 = blockIdx.x * 128;
    const int nt = (n0 >= n3start) ? 3 : ntLow;
    Bhi += (size_t)blockIdx.z * bBatch;
    Blo += (size_t)blockIdx.z * bBatch;
    if (Cout) Cout += (size_t)blockIdx.z * cBatch;
    const float* res = resid ? resid + (size_t)blockIdx.z * cBatch : nullptr;

    float* bsm = (float*)smc;
    if (tid < 128) bsm[tid] = bias ? bias[n0 + tid] : 0.f;

    const uint32_t t0 = sb + 1024;
    const int nchunk = K >> 6;
    const int mb = (wid & 3) * 32;
    const int nb = (wid >> 2) * 64;

    float acc[2][8][4];
#pragma unroll
    for (int i = 0; i < 2; i++)
#pragma unroll
        for (int j = 0; j < 8; j++)
#pragma unroll
            for (int q = 0; q < 4; q++) acc[i][j][q] = 0.f;

    load_chunk(t0, tid, m0, n0, K, 0, nt, Ahi, Alo, Bhi, Blo);
    for (int c = 0; c < nchunk; c++) {
        if (c + 1 < nchunk) {
            load_chunk(t0 + (uint32_t)((c + 1) & 1) * (4u * GTB), tid, m0, n0, K,
                       (c + 1) << 6, nt, Ahi, Alo, Bhi, Blo);
            asm volatile("cp.async.wait_group 1;" ::: "memory");
        } else {
            asm volatile("cp.async.wait_group 0;" ::: "memory");
        }
        __syncthreads();
        uint32_t bufA = t0 + (uint32_t)(c & 1) * (4u * GTB);
#pragma unroll
        for (int ks = 0; ks < 4; ks++) {
            int kb = ks * 32;
            uint32_t ao = SWZ((uint32_t)((mb + (lane & 15)) * 128 +
                                         (lane >> 4) * 16 + kb));
            uint32_t ahi[4], alo[4];
            ldsm4(ahi, bufA + ao);
            if (nt == 3) ldsm4(alo, bufA + GTB + ao);
            uint32_t ao2 = SWZ((uint32_t)((mb + 16 + (lane & 15)) * 128 +
                                          (lane >> 4) * 16 + kb));
            uint32_t ahi2[4], alo2[4];
            ldsm4(ahi2, bufA + ao2);
            if (nt == 3) ldsm4(alo2, bufA + GTB + ao2);
            uint32_t brow = (uint32_t)((nb + (lane & 7) + ((lane >> 4) & 1) * 8) * 128 +
                                       ((lane >> 3) & 1) * 16 + kb);
#pragma unroll
            for (int ntp = 0; ntp < 4; ntp++) {
                uint32_t bo = SWZ(brow + (uint32_t)(ntp * 16 * 128));
                uint32_t bhi[4], blo[4];
                ldsm4(bhi, bufA + 2u * GTB + bo);
                if (nt >= 2) ldsm4(blo, bufA + 3u * GTB + bo);
#pragma unroll
                for (int half = 0; half < 2; half++) {
                    int ntile = ntp * 2 + half;
                    const uint32_t bh[2] = {bhi[half * 2], bhi[half * 2 + 1]};
                    mma16816(acc[0][ntile], ahi, bh);
                    mma16816(acc[1][ntile], ahi2, bh);
                    if (nt >= 2) {
                        const uint32_t bl[2] = {blo[half * 2], blo[half * 2 + 1]};
                        mma16816(acc[0][ntile], ahi, bl);
                        mma16816(acc[1][ntile], ahi2, bl);
                    }
                    if (nt == 3) {
                        mma16816(acc[0][ntile], alo, bh);
                        mma16816(acc[1][ntile], alo2, bh);
                    }
                }
            }
        }
        __syncthreads();
    }

    int rbase = m0 + mb + (lane >> 2);
    int cbase = nb + (lane & 3) * 2;
#pragma unroll
    for (int mt = 0; mt < 2; mt++) {
#pragma unroll
        for (int ntile = 0; ntile < 8; ntile++) {
            int ncol = cbase + ntile * 8;
            int gcol = n0 + ncol;
#pragma unroll
            for (int rr = 0; rr < 2; rr++) {
                int row = rbase + mt * 16 + rr * 8;
                float v0 = acc[mt][ntile][rr * 2 + 0];
                float v1 = acc[mt][ntile][rr * 2 + 1];
                if (mode == 0) {
                    v0 += bsm[ncol]; v1 += bsm[ncol + 1];
                    size_t idx = (size_t)row * Nld + gcol;
                    if (res) {
                        float2 q = *(const float2*)(res + idx);
                        v0 += q.x; v1 += q.y;
                    }
                    float2 o; o.x = v0; o.y = v1;
                    *(float2*)(Cout + idx) = o;
                } else {
                    int b = row >> 10, tok = row & 1023;
                    int region = gcol >> 9;        // 0=q 1=k 2=v
                    int hd = gcol & 511;
                    int h = hd >> 6, d = hd & 63;
                    size_t dst = (((size_t)(b * NH_ + h) * HW_) + tok) * DH_ + d;
                    uint32_t hi, lo;
                    split2(v0, v1, hi, lo);
                    h16* ph = (region == 0) ? g_qhi : (region == 1) ? g_khi : g_vhi;
                    h16* pl = (region == 0) ? g_qlo : (region == 1) ? g_klo : g_vlo;
                    *(uint32_t*)&ph[dst] = hi;
                    *(uint32_t*)&pl[dst] = lo;
                }
            }
        }
    }
}

// ---------------- 1) t = transpose(x) + pos -> fp16 hi/lo --------------------
__global__ void build_t_kernel(const float* __restrict__ x,
                               const float* __restrict__ pos,
                               h16* __restrict__ thi, h16* __restrict__ tlo) {
    __shared__ float tile[32][33];
    int b  = blockIdx.z;
    int n0 = blockIdx.x * 32;
    int c0 = blockIdx.y * 32;
    int tx = threadIdx.x, ty = threadIdx.y;
#pragma unroll
    for (int i = 0; i < 4; i++) {
        int c = c0 + ty + i * 8;
        tile[ty + i * 8][tx] = x[((size_t)b * C_ + c) * HW_ + n0 + tx];
    }
    __syncthreads();
#pragma unroll
    for (int i = 0; i < 4; i++) {
        int n = n0 + ty + i * 8;
        int c = c0 + tx;
        float v = tile[tx][ty + i * 8] + pos[(size_t)n * C_ + c];
        __half h = __float2half(v);
        size_t o = ((size_t)b * HW_ + n) * C_ + c;
        thi[o] = h;
        tlo[o] = __float2half(v - __half2float(h));
    }
}

// ---------------- fused weight splits ----------------------------------------
#define NW1 (C3_*C_)
#define NW2 (C_*C_)
__global__ void splitw_kernel(const float* __restrict__ w1,
                              const float* __restrict__ w2,
                              const float* __restrict__ w3) {
    int i = blockIdx.x * 256 + threadIdx.x;
    const float* src; h16 *hi, *lo; int idx;
    if (i < NW1)            { src = w1; hi = g_w1hi; lo = g_w1lo; idx = i; }
    else if (i < NW1 + NW2) { src = w2; hi = g_w2hi; lo = g_w2lo; idx = i - NW1; }
    else if (i < NW1+2*NW2) { src = w3; hi = g_w3hi; lo = g_w3lo; idx = i - NW1 - NW2; }
    else return;
    float v = src[idx];
    __half h = __float2half(v);
    hi[idx] = h;
    lo[idx] = __float2half(v - __half2float(h));
}

// ---------------- rs two-stage reduction (hi-only) ---------------------------
__global__ void rs1_kernel(float* __restrict__ psq, float* __restrict__ psk) {
    int bx = blockIdx.x;
    int bh = bx >> 4, part = bx & 15;
    int tid = threadIdx.x;
    int d = tid & 63, sub = tid >> 6;
    size_t base = (size_t)bh * HW_ * DH_ + d;
    int n0 = part * 64 + sub * 16;
    float sq = 0.f, sk = 0.f;
#pragma unroll
    for (int n = 0; n < 16; n++) {
        size_t off = base + (size_t)(n0 + n) * DH_;
        float qv = __half2float(g_qhi[off]);
        float kv = __half2float(g_khi[off]);
        sq += qv * qv;
        sk += kv * kv;
    }
    __shared__ float smq[4][64], smk[4][64];
    smq[sub][d] = sq; smk[sub][d] = sk;
    __syncthreads();
    if (tid < 64) {
        float q = (smq[0][d] + smq[1][d]) + (smq[2][d] + smq[3][d]);
        float k = (smk[0][d] + smk[1][d]) + (smk[2][d] + smk[3][d]);
        psq[((size_t)bh * 16 + part) * 64 + d] = q;
        psk[((size_t)bh * 16 + part) * 64 + d] = k;
    }
}

__global__ void rs2_kernel(const float* __restrict__ psq,
                           const float* __restrict__ psk,
                           const float* __restrict__ temp,
                           float* __restrict__ rs) {
    int bh = blockIdx.x, d = threadIdx.x;
    int h = bh % NH_;
    float q = 0.f, k = 0.f;
#pragma unroll
    for (int p = 0; p < 16; p++) {
        q += psq[((size_t)bh * 16 + p) * 64 + d];
        k += psk[((size_t)bh * 16 + p) * 64 + d];
    }
    float qn = fmaxf(sqrtf(q), 1e-12f);
    float kn = fmaxf(sqrtf(k), 1e-12f);
    rs[(size_t)bh * DH_ + d] = temp[h] / (qn * kn);
}

// ---------------- tensor-core fused flash attention --------------------------
// S = Qhi.Khi (1 MMA, fp16: abs logit err ~3e-5). O = P.V 3-term (~exact).
// smem: KV double buffer (2x24KB) + persistent Q hi (16KB) + rss.
#define FAT_STAGE 24576u
#define FAT_QOFF  49152u
#define FAT_SMEM  (49152 + 16384 + 256)

__device__ __forceinline__ void fat_loadkv(
    uint32_t buf, int tid, size_t kvbase, int kc,
    const h16* __restrict__ khi,
    const h16* __restrict__ vhi, const h16* __restrict__ vlo) {
#pragma unroll
    for (int it = 0; it < 2; it++) {
        int idx = it * 256 + tid;
        int r = idx >> 3, cg = idx & 7;
        uint32_t so = SWZ((uint32_t)(r * 128 + cg * 16));
        size_t g = kvbase + (size_t)(kc + r) * DH_ + cg * 8;
        cp16(buf +     0u + so, khi + g);
        cp16(buf +  8192u + so, vhi + g);
        cp16(buf + 16384u + so, vlo + g);
    }
    asm volatile("cp.async.commit_group;" ::: "memory");
}

__global__ __launch_bounds__(256, 2)
void fat_kernel(const h16* __restrict__ qhi, const h16* __restrict__ qlo,
                const float* __restrict__ rs,
                const h16* __restrict__ khi,
                const h16* __restrict__ vhi, const h16* __restrict__ vlo,
                h16* __restrict__ ohi, h16* __restrict__ olo) {
    extern __shared__ char smc[];
    uint32_t sb = smem_u32(smc);
    float* rss = (float*)(smc + FAT_QOFF + 16384);
    int bh = blockIdx.y;
    int b = bh >> 3, h = bh & 7;
    int q0 = blockIdx.x * 128;
    int tid = threadIdx.x, wid = tid >> 5, lane = tid & 31;
    int mb = wid * 16;

    if (tid < 64) rss[tid] = rs[bh * DH_ + tid];
    __syncthreads();

    // stage Q (hi+lo recombined, scaled by rs) as fp16 into persistent smem
#pragma unroll
    for (int v = 0; v < 8; v++) {
        int idx = v * 256 + tid;
        int row = idx >> 4, dq = (idx & 15) * 4;
        size_t qoff = ((size_t)bh * HW_ + q0 + row) * DH_ + dq;
        __half2 ha = *(const __half2*)&qhi[qoff];
        __half2 hb = *(const __half2*)&qhi[qoff + 2];
        __half2 la = *(const __half2*)&qlo[qoff];
        __half2 lb = *(const __half2*)&qlo[qoff + 2];
        float qx = (__half2float(ha.x) + __half2float(la.x)) * rss[dq];
        float qy = (__half2float(ha.y) + __half2float(la.y)) * rss[dq + 1];
        float qz = (__half2float(hb.x) + __half2float(lb.x)) * rss[dq + 2];
        float qw = (__half2float(hb.y) + __half2float(lb.y)) * rss[dq + 3];
        uint32_t off = SWZ((uint32_t)(row * 128 + dq * 2));
        *(uint32_t*)(smc + FAT_QOFF + off)     = pack2(qx, qy);
        *(uint32_t*)(smc + FAT_QOFF + off + 4) = pack2(qz, qw);
    }
    __syncthreads();

    float o[8][4];
#pragma unroll
    for (int j = 0; j < 8; j++)
#pragma unroll
        for (int q = 0; q < 4; q++) o[j][q] = 0.f;
    float m0 = -1e30f, m1 = -1e30f, l0 = 0.f, l1 = 0.f;
    const size_t kvbase = (size_t)bh * HW_ * DH_;

    fat_loadkv(sb, tid, kvbase, 0, khi, vhi, vlo);
    for (int kt = 0; kt < 16; kt++) {
        uint32_t cur = sb + (uint32_t)(kt & 1) * FAT_STAGE;
        if (kt + 1 < 16) {
            fat_loadkv(sb + (uint32_t)((kt + 1) & 1) * FAT_STAGE, tid, kvbase,
                       (kt + 1) * 64, khi, vhi, vlo);
            asm volatile("cp.async.wait_group 1;" ::: "memory");
        } else {
            asm volatile("cp.async.wait_group 0;" ::: "memory");
        }
        __syncthreads();

        // ---- S = Q.K^T (1 MMA per tile pair)
        float s[8][4];
#pragma unroll
        for (int j = 0; j < 8; j++)
#pragma unroll
            for (int q = 0; q < 4; q++) s[j][q] = 0.f;
#pragma unroll
        for (int ks = 0; ks < 4; ks++) {
            uint32_t qao = SWZ((uint32_t)((mb + (lane & 15)) * 128 +
                                          (lane >> 4) * 16 + ks * 32));
            uint32_t qh4[4];
            ldsm4(qh4, sb + FAT_QOFF + qao);
            uint32_t brow = (uint32_t)(((lane & 7) + ((lane >> 4) & 1) * 8) * 128 +
                                       ((lane >> 3) & 1) * 16 + ks * 32);
#pragma unroll
            for (int np = 0; np < 4; np++) {
                uint32_t bo = SWZ(brow + (uint32_t)(np * 16 * 128));
                uint32_t kh4[4];
                ldsm4(kh4, cur + bo);
#pragma unroll
                for (int half = 0; half < 2; half++) {
                    int j = np * 2 + half;
                    const uint32_t bhh[2] = {kh4[half * 2], kh4[half * 2 + 1]};
                    mma16816(s[j], qh4, bhh);
                }
            }
        }

        // ---- online softmax (rows r=lane>>2 and r+8; quads share rows)
        float mx0 = -1e30f, mx1 = -1e30f;
#pragma unroll
        for (int j = 0; j < 8; j++) {
            mx0 = fmaxf(mx0, fmaxf(s[j][0], s[j][1]));
            mx1 = fmaxf(mx1, fmaxf(s[j][2], s[j][3]));
        }
        mx0 = fmaxf(mx0, __shfl_xor_sync(0xffffffffu, mx0, 1));
        mx0 = fmaxf(mx0, __shfl_xor_sync(0xffffffffu, mx0, 2));
        mx1 = fmaxf(mx1, __shfl_xor_sync(0xffffffffu, mx1, 1));
        mx1 = fmaxf(mx1, __shfl_xor_sync(0xffffffffu, mx1, 2));
        float mn0 = fmaxf(m0, mx0), mn1 = fmaxf(m1, mx1);
        float al0 = __expf(m0 - mn0), al1 = __expf(m1 - mn1);
        float sum0 = 0.f, sum1 = 0.f;
#pragma unroll
        for (int j = 0; j < 8; j++) {
            s[j][0] = __expf(s[j][0] - mn0);
            s[j][1] = __expf(s[j][1] - mn0);
            s[j][2] = __expf(s[j][2] - mn1);
            s[j][3] = __expf(s[j][3] - mn1);
            sum0 += s[j][0] + s[j][1];
            sum1 += s[j][2] + s[j][3];
        }
        sum0 += __shfl_xor_sync(0xffffffffu, sum0, 1);
        sum0 += __shfl_xor_sync(0xffffffffu, sum0, 2);
        sum1 += __shfl_xor_sync(0xffffffffu, sum1, 1);
        sum1 += __shfl_xor_sync(0xffffffffu, sum1, 2);
        l0 = l0 * al0 + sum0; l1 = l1 * al1 + sum1;
        m0 = mn0; m1 = mn1;
#pragma unroll
        for (int j = 0; j < 8; j++) {
            o[j][0] *= al0; o[j][1] *= al0;
            o[j][2] *= al1; o[j][3] *= al1;
        }

        // ---- O += P.V (3-term fp16 ~ exact); P frags packed from S frags
#pragma unroll
        for (int ks = 0; ks < 4; ks++) {
            int j0 = 2 * ks, j1 = 2 * ks + 1;
            uint32_t ph[4], pl[4];
            split2(s[j0][0], s[j0][1], ph[0], pl[0]);
            split2(s[j0][2], s[j0][3], ph[1], pl[1]);
            split2(s[j1][0], s[j1][1], ph[2], pl[2]);
            split2(s[j1][2], s[j1][3], ph[3], pl[3]);
            uint32_t vrow = (uint32_t)((ks * 16 + (lane & 7) + ((lane >> 3) & 1) * 8) * 128 +
                                       ((lane >> 4) & 1) * 16);
#pragma unroll
            for (int np = 0; np < 4; np++) {
                uint32_t vo = SWZ(vrow + (uint32_t)(np * 32));
                uint32_t vh4[4], vl4[4];
                ldsm4t(vh4, cur +  8192u + vo);
                ldsm4t(vl4, cur + 16384u + vo);
#pragma unroll
                for (int half = 0; half < 2; half++) {
                    int j = np * 2 + half;
                    const uint32_t bvh[2] = {vh4[half * 2], vh4[half * 2 + 1]};
                    const uint32_t bvl[2] = {vl4[half * 2], vl4[half * 2 + 1]};
                    mma16816(o[j], ph, bvh);
                    mma16816(o[j], ph, bvl);
                    mma16816(o[j], pl, bvh);
                }
            }
        }
        __syncthreads();
    }

    float inv0 = 1.f / l0, inv1 = 1.f / l1;
    int r0 = lane >> 2, cc = (lane & 3) * 2;
    int row0 = q0 + mb + r0, row1 = row0 + 8;
#pragma unroll
    for (int j = 0; j < 8; j++) {
        int col = h * DH_ + j * 8 + cc;
        size_t off0 = ((size_t)(b * HW_ + row0)) * C_ + col;
        size_t off1 = ((size_t)(b * HW_ + row1)) * C_ + col;
        uint32_t hi, lo;
        split2(o[j][0] * inv0, o[j][1] * inv0, hi, lo);
        *(uint32_t*)&ohi[off0] = hi; *(uint32_t*)&olo[off0] = lo;
        split2(o[j][2] * inv1, o[j][3] * inv1, hi, lo);
        *(uint32_t*)&ohi[off1] = hi; *(uint32_t*)&olo[off1] = lo;
    }
}

// ---------------- LayerNorm over C + residual + transpose to [B,C,HW] -------
__global__ void ln_residual_kernel(const float* __restrict__ ob,
                                   const float* __restrict__ x,
                                   const float* __restrict__ g,
                                   const float* __restrict__ be,
                                   float* __restrict__ y) {
    int row = blockIdx.x;
    int b = row >> 10, n = row & 1023;
    const float* pr = ob + (size_t)row * C_;
    int tid = threadIdx.x;
    float v0 = pr[tid], v1 = pr[tid + 256];
    __shared__ float red[256];
    red[tid] = v0 + v1; __syncthreads();
    for (int s = 128; s > 0; s >>= 1) {
        if (tid < s) red[tid] += red[tid + s];
        __syncthreads();
    }
    float mean = red[0] * (1.0f / C_);
    __syncthreads();
    float d0 = v0 - mean, d1 = v1 - mean;
    red[tid] = d0 * d0 + d1 * d1; __syncthreads();
    for (int s = 128; s > 0; s >>= 1) {
        if (tid < s) red[tid] += red[tid + s];
        __syncthreads();
    }
    float rstd = rsqrtf(red[0] * (1.0f / C_) + 1e-5f);
    int c0 = tid, c1 = tid + 256;
    size_t i0 = ((size_t)b * C_ + c0) * HW_ + n;
    size_t i1 = ((size_t)b * C_ + c1) * HW_ + n;
    y[i0] = d0 * rstd * g[c0] + be[c0] + x[i0];
    y[i1] = d1 * rstd * g[c1] + be[c1] + x[i1];
}

// ---------------- fused depthwise 3x3 + transpose + split --------------------
__global__ void dwt_kernel(const float* __restrict__ y,
                           const float* __restrict__ w,
                           const float* __restrict__ bias,
                           h16* __restrict__ hi, h16* __restrict__ lo) {
    __shared__ float yt[32][3][33];
    __shared__ float ot[32][33];   // [w][c]
    int hh = blockIdx.x, c0 = blockIdx.y * 32, b = blockIdx.z;
    int tid = threadIdx.x;
    int c = tid >> 3, wg = (tid & 7) * 4;

#pragma unroll
    for (int r = 0; r < 3; r++) {
        int ih = hh + r - 1;
        float4 v = make_float4(0.f, 0.f, 0.f, 0.f);
        if (ih >= 0 && ih < H_)
            v = *(const float4*)&y[((size_t)(b * C_ + c0 + c)) * HW_ + ih * W_ + wg];
        yt[c][r][wg + 0] = v.x; yt[c][r][wg + 1] = v.y;
        yt[c][r][wg + 2] = v.z; yt[c][r][wg + 3] = v.w;
    }
    float wc[9];
#pragma unroll
    for (int i = 0; i < 9; i++) wc[i] = w[(c0 + c) * 9 + i];
    float bs = bias[c0 + c];
    __syncthreads();

#pragma unroll
    for (int j = 0; j < 4; j++) {
        int ww = wg + j;
        float acc = bs;
#pragma unroll
        for (int ki = 0; ki < 3; ki++)
#pragma unroll
            for (int kj = 0; kj < 3; kj++) {
                int iw = ww + kj - 1;
                if (iw >= 0 && iw < W_) acc += wc[ki * 3 + kj] * yt[c][ki][iw];
            }
        ot[ww][c] = acc;
    }
    __syncthreads();

    int w2 = tid >> 3, cg = (tid & 7) * 4;
    int token = hh * W_ + w2;
    size_t base = ((size_t)b * HW_ + token) * C_ + c0 + cg;
    float a0 = ot[w2][cg], a1 = ot[w2][cg + 1];
    float a2 = ot[w2][cg + 2], a3 = ot[w2][cg + 3];
    uint32_t h0, l0, h1, l1;
    split2(a0, a1, h0, l0);
    split2(a2, a3, h1, l1);
    *(uint32_t*)&hi[base]     = h0; *(uint32_t*)&hi[base + 2] = h1;
    *(uint32_t*)&lo[base]     = l0; *(uint32_t*)&lo[base + 2] = l1;
}

// ---------------- launch ------------------------------------------------------
extern "C" void kernel_launch(void* const* d_in, const int* in_sizes, int n_in,
                              void* d_out, int out_size) {
    const float* x      = (const float*)d_in[0];
    const float* qkv_w  = (const float*)d_in[1];
    const float* proj_w = (const float*)d_in[2];
    const float* proj_b = (const float*)d_in[3];
    const float* temper = (const float*)d_in[4];
    const float* ln_g   = (const float*)d_in[5];
    const float* ln_b   = (const float*)d_in[6];
    const float* pos    = (const float*)d_in[7];
    const float* dw_w   = (const float*)d_in[8];
    const float* dw_b   = (const float*)d_in[9];
    const float* pw_w   = (const float*)d_in[10];
    const float* pw_b   = (const float*)d_in[11];
    float* out = (float*)d_out;

    h16 *thi, *tlo, *w1hi, *w1lo, *w2hi, *w2lo, *w3hi, *w3lo;
    h16 *ohi, *olo, *dThi, *dTlo, *qhi, *qlo, *khi, *vhi, *vlo;
    float *rs, *ob, *y, *psq, *psk;
    cudaGetSymbolAddress((void**)&thi,  g_thi);
    cudaGetSymbolAddress((void**)&tlo,  g_tlo);
    cudaGetSymbolAddress((void**)&w1hi, g_w1hi);
    cudaGetSymbolAddress((void**)&w1lo, g_w1lo);
    cudaGetSymbolAddress((void**)&w2hi, g_w2hi);
    cudaGetSymbolAddress((void**)&w2lo, g_w2lo);
    cudaGetSymbolAddress((void**)&w3hi, g_w3hi);
    cudaGetSymbolAddress((void**)&w3lo, g_w3lo);
    cudaGetSymbolAddress((void**)&ohi,  g_ohi);
    cudaGetSymbolAddress((void**)&olo,  g_olo);
    cudaGetSymbolAddress((void**)&dThi, g_dThi);
    cudaGetSymbolAddress((void**)&dTlo, g_dTlo);
    cudaGetSymbolAddress((void**)&qhi,  g_qhi);
    cudaGetSymbolAddress((void**)&qlo,  g_qlo);
    cudaGetSymbolAddress((void**)&khi,  g_khi);
    cudaGetSymbolAddress((void**)&vhi,  g_vhi);
    cudaGetSymbolAddress((void**)&vlo,  g_vlo);
    cudaGetSymbolAddress((void**)&rs,   g_rs);
    cudaGetSymbolAddress((void**)&psq,  g_psq);
    cudaGetSymbolAddress((void**)&psk,  g_psk);
    cudaGetSymbolAddress((void**)&ob,   g_ob);
    cudaGetSymbolAddress((void**)&y,    g_y);

    cudaFuncSetAttribute(fat_kernel,
                         cudaFuncAttributeMaxDynamicSharedMemorySize, FAT_SMEM);
    cudaFuncSetAttribute(gemm_tc,
                         cudaFuncAttributeMaxDynamicSharedMemorySize, GSMEM);

    // fused weight splits
    splitw_kernel<<<(NW1 + 2*NW2 + 255)/256, 256>>>(qkv_w, proj_w, pw_w);
    // t = transpose(x) + pos (fp16 split)
    build_t_kernel<<<dim3(HW_/32, C_/32, B_), dim3(32, 8)>>>(x, pos, thi, tlo);
    // qkv GEMM: q,k cols 1-term fp16; v cols 3-term; split head-major output
    gemm_tc<<<dim3(C3_/128, (B_*HW_)/128, 1), 256, GSMEM>>>(
        thi, tlo, w1hi, w1lo, nullptr, nullptr, nullptr, C_, 0, 0, 0,
        1 /*mode=qkv*/, 1 /*ntLow*/, 1024 /*n3start: v cols*/);
    // rs two-stage reduction (parallel, deterministic, hi-only)
    rs1_kernel<<<B_*NH_*16, 256>>>(psq, psk);
    rs2_kernel<<<B_*NH_, 64>>>(psq, psk, temper, rs);
    // tensor-core fused attention -> o (fp16 split)
    fat_kernel<<<dim3(HW_/128, B_*NH_), 256, FAT_SMEM>>>(
        qhi, qlo, rs, khi, vhi, vlo, ohi, olo);
    // proj = o @ proj_w^T + proj_b (3-term fp16 ~ exact)
    gemm_tc<<<dim3(C_/128, (B_*HW_)/128, 1), 256, GSMEM>>>(
        ohi, olo, w2hi, w2lo, proj_b, nullptr, ob, C_, C_, 0, 0, 0, 3, 0);
    // LN + residual + transpose to [B,C,HW]
    ln_residual_kernel<<<B_*HW_, 256>>>(ob, x, ln_g, ln_b, y);
    // fused depthwise 3x3 + transpose + split
    dwt_kernel<<<dim3(H_, C_/32, B_), 256>>>(y, dw_w, dw_b, dThi, dTlo);
    // pointwise (1-term fp16: conv term ~3% of output) + bias + residual
    gemm_tc<<<dim3(HW_/128, C_/128, B_), 256, GSMEM>>>(
        w3hi, w3lo, dThi, dTlo, pw_b, y, out, C_, HW_,
        (long)HW_*C_, (long)C_*HW_, 0, 1, 1 << 30);
}

// round 10
// speedup vs baseline: 1.3469x; 1.1747x over previous
#include <cuda_runtime.h>
#include <cuda_fp16.h>
#include <cstdint>

#define B_  8
#define C_  512
#define H_  32
#define W_  32
#define NH_ 8
#define DH_ 64
#define HW_ 1024
#define C3_ (3*C_)

typedef __half h16;

// ---------------- scratch (device globals; no allocation allowed) ----------
__device__ h16   g_thi[(size_t)B_*HW_*C_];
__device__ h16   g_w1hi[(size_t)C3_*C_];
__device__ h16   g_w1lo[(size_t)C3_*C_];
__device__ h16   g_w2hi[(size_t)C_*C_];
__device__ h16   g_w2lo[(size_t)C_*C_];
__device__ h16   g_w3hi[(size_t)C_*C_];
__device__ float g_rs [(size_t)B_*NH_*DH_];
__device__ float g_psq[(size_t)B_*NH_*16*DH_];
__device__ float g_psk[(size_t)B_*NH_*16*DH_];
__device__ h16   g_qhi[(size_t)B_*NH_*HW_*DH_];
__device__ h16   g_khi[(size_t)B_*NH_*HW_*DH_];
__device__ h16   g_vhi[(size_t)B_*NH_*HW_*DH_];
__device__ h16   g_ohi[(size_t)B_*HW_*C_];
__device__ float g_ob [(size_t)B_*HW_*C_];
__device__ float g_y  [(size_t)B_*C_*HW_];
__device__ h16   g_dThi[(size_t)B_*HW_*C_];

// ---------------- small PTX helpers -----------------------------------------
__device__ __forceinline__ uint32_t smem_u32(const void* p) {
    uint32_t a;
    asm("{ .reg .u64 t; cvta.to.shared.u64 t, %1; cvt.u32.u64 %0, t; }"
        : "=r"(a) : "l"(p));
    return a;
}
__device__ __forceinline__ void cp16(uint32_t s, const void* g) {
    asm volatile("cp.async.cg.shared.global [%0], [%1], 16;" :: "r"(s), "l"(g));
}
#define SWZ(x) ((x) ^ (((x) >> 3) & 0x70u))

__device__ __forceinline__ void ldsm4(uint32_t* r, uint32_t addr) {
    asm volatile("ldmatrix.sync.aligned.m8n8.x4.shared.b16 {%0,%1,%2,%3}, [%4];"
                 : "=r"(r[0]), "=r"(r[1]), "=r"(r[2]), "=r"(r[3]) : "r"(addr));
}
__device__ __forceinline__ void ldsm4t(uint32_t* r, uint32_t addr) {
    asm volatile("ldmatrix.sync.aligned.m8n8.x4.trans.shared.b16 {%0,%1,%2,%3}, [%4];"
                 : "=r"(r[0]), "=r"(r[1]), "=r"(r[2]), "=r"(r[3]) : "r"(addr));
}
__device__ __forceinline__ void mma16816(float* c, const uint32_t* a,
                                         const uint32_t* b) {
    asm volatile(
        "mma.sync.aligned.m16n8k16.row.col.f32.f16.f16.f32 "
        "{%0,%1,%2,%3}, {%4,%5,%6,%7}, {%8,%9}, {%0,%1,%2,%3};"
        : "+f"(c[0]), "+f"(c[1]), "+f"(c[2]), "+f"(c[3])
        : "r"(a[0]), "r"(a[1]), "r"(a[2]), "r"(a[3]), "r"(b[0]), "r"(b[1]));
}
__device__ __forceinline__ void split2(float a, float b, uint32_t& hi, uint32_t& lo) {
    __half ha = __float2half(a), hb = __float2half(b);
    __half2 h; h.x = ha; h.y = hb;
    hi = *(uint32_t*)&h;
    __half2 l;
    l.x = __float2half(a - __half2float(ha));
    l.y = __float2half(b - __half2float(hb));
    lo = *(uint32_t*)&l;
}
__device__ __forceinline__ uint32_t pack2(float a, float b) {
    __half2 h; h.x = __float2half(a); h.y = __float2half(b);
    return *(uint32_t*)&h;
}

// ---------------- HMMA GEMM: D[128,128] = A @ B^T via fp16 hi/lo split ------
// nt per CTA: 1 = ahi*bhi; 2 = + ahi*blo.  nt = (n0 >= nHiStart) ? ntHigh : ntLow.
#define GTB   16384u
#define GSMEM (1024 + 8 * 16384)

__device__ __forceinline__ void load_chunk(
    uint32_t dst, int tid, int m0, int n0, int K, int kc, int nt,
    const h16* __restrict__ Ahi,
    const h16* __restrict__ Bhi, const h16* __restrict__ Blo) {
#pragma unroll
    for (int it = 0; it < 4; it++) {
        int idx = it * 256 + tid;
        int r = idx >> 3, cg = idx & 7;
        uint32_t so = SWZ((uint32_t)(r * 128 + cg * 16));
        size_t ga = (size_t)(m0 + r) * K + kc + cg * 8;
        size_t gb = (size_t)(n0 + r) * K + kc + cg * 8;
        cp16(dst            + so, Ahi + ga);
        cp16(dst + 2u * GTB + so, Bhi + gb);
        if (nt >= 2) cp16(dst + 3u * GTB + so, Blo + gb);
    }
    asm volatile("cp.async.commit_group;" ::: "memory");
}

__global__ __launch_bounds__(256, 1)
void gemm_tc(const h16* __restrict__ Ahi,
             const h16* __restrict__ Bhi, const h16* __restrict__ Blo,
             const float* __restrict__ bias, const float* __restrict__ resid,
             float* __restrict__ Cout, int K, int Nld,
             long bBatch, long cBatch, int mode,
             int ntLow, int ntHigh, int nHiStart) {
    extern __shared__ char smc[];
    uint32_t sb = smem_u32(smc);
    int tid = threadIdx.x, wid = tid >> 5, lane = tid & 31;
    int m0 = blockIdx.y * 128, n0 = blockIdx.x * 128;
    const int nt = (n0 >= nHiStart) ? ntHigh : ntLow;
    Bhi += (size_t)blockIdx.z * bBatch;
    Blo += (size_t)blockIdx.z * bBatch;
    if (Cout) Cout += (size_t)blockIdx.z * cBatch;
    const float* res = resid ? resid + (size_t)blockIdx.z * cBatch : nullptr;

    float* bsm = (float*)smc;
    if (tid < 128) bsm[tid] = bias ? bias[n0 + tid] : 0.f;

    const uint32_t t0 = sb + 1024;
    const int nchunk = K >> 6;
    const int mb = (wid & 3) * 32;
    const int nb = (wid >> 2) * 64;

    float acc[2][8][4];
#pragma unroll
    for (int i = 0; i < 2; i++)
#pragma unroll
        for (int j = 0; j < 8; j++)
#pragma unroll
            for (int q = 0; q < 4; q++) acc[i][j][q] = 0.f;

    load_chunk(t0, tid, m0, n0, K, 0, nt, Ahi, Bhi, Blo);
    for (int c = 0; c < nchunk; c++) {
        if (c + 1 < nchunk) {
            load_chunk(t0 + (uint32_t)((c + 1) & 1) * (4u * GTB), tid, m0, n0, K,
                       (c + 1) << 6, nt, Ahi, Bhi, Blo);
            asm volatile("cp.async.wait_group 1;" ::: "memory");
        } else {
            asm volatile("cp.async.wait_group 0;" ::: "memory");
        }
        __syncthreads();
        uint32_t bufA = t0 + (uint32_t)(c & 1) * (4u * GTB);
#pragma unroll
        for (int ks = 0; ks < 4; ks++) {
            int kb = ks * 32;
            uint32_t ao = SWZ((uint32_t)((mb + (lane & 15)) * 128 +
                                         (lane >> 4) * 16 + kb));
            uint32_t ahi[4];
            ldsm4(ahi, bufA + ao);
            uint32_t ao2 = SWZ((uint32_t)((mb + 16 + (lane & 15)) * 128 +
                                          (lane >> 4) * 16 + kb));
            uint32_t ahi2[4];
            ldsm4(ahi2, bufA + ao2);
            uint32_t brow = (uint32_t)((nb + (lane & 7) + ((lane >> 4) & 1) * 8) * 128 +
                                       ((lane >> 3) & 1) * 16 + kb);
#pragma unroll
            for (int ntp = 0; ntp < 4; ntp++) {
                uint32_t bo = SWZ(brow + (uint32_t)(ntp * 16 * 128));
                uint32_t bhi[4], blo[4];
                ldsm4(bhi, bufA + 2u * GTB + bo);
                if (nt >= 2) ldsm4(blo, bufA + 3u * GTB + bo);
#pragma unroll
                for (int half = 0; half < 2; half++) {
                    int ntile = ntp * 2 + half;
                    const uint32_t bh[2] = {bhi[half * 2], bhi[half * 2 + 1]};
                    mma16816(acc[0][ntile], ahi, bh);
                    mma16816(acc[1][ntile], ahi2, bh);
                    if (nt >= 2) {
                        const uint32_t bl[2] = {blo[half * 2], blo[half * 2 + 1]};
                        mma16816(acc[0][ntile], ahi, bl);
                        mma16816(acc[1][ntile], ahi2, bl);
                    }
                }
            }
        }
        __syncthreads();
    }

    int rbase = m0 + mb + (lane >> 2);
    int cbase = nb + (lane & 3) * 2;
#pragma unroll
    for (int mt = 0; mt < 2; mt++) {
#pragma unroll
        for (int ntile = 0; ntile < 8; ntile++) {
            int ncol = cbase + ntile * 8;
            int gcol = n0 + ncol;
#pragma unroll
            for (int rr = 0; rr < 2; rr++) {
                int row = rbase + mt * 16 + rr * 8;
                float v0 = acc[mt][ntile][rr * 2 + 0];
                float v1 = acc[mt][ntile][rr * 2 + 1];
                if (mode == 0) {
                    v0 += bsm[ncol]; v1 += bsm[ncol + 1];
                    size_t idx = (size_t)row * Nld + gcol;
                    if (res) {
                        float2 q = *(const float2*)(res + idx);
                        v0 += q.x; v1 += q.y;
                    }
                    float2 o; o.x = v0; o.y = v1;
                    *(float2*)(Cout + idx) = o;
                } else {
                    // qkv output: [bh][token][64] head-major, fp16 hi only
                    int b = row >> 10, tok = row & 1023;
                    int region = gcol >> 9;        // 0=q 1=k 2=v
                    int hd = gcol & 511;
                    int h = hd >> 6, d = hd & 63;
                    size_t dst = (((size_t)(b * NH_ + h) * HW_) + tok) * DH_ + d;
                    h16* ph = (region == 0) ? g_qhi : (region == 1) ? g_khi : g_vhi;
                    *(uint32_t*)&ph[dst] = pack2(v0, v1);
                }
            }
        }
    }
}

// ---------------- 1) t = transpose(x) + pos -> fp16 -------------------------
__global__ void build_t_kernel(const float* __restrict__ x,
                               const float* __restrict__ pos,
                               h16* __restrict__ thi) {
    __shared__ float tile[32][33];
    int b  = blockIdx.z;
    int n0 = blockIdx.x * 32;
    int c0 = blockIdx.y * 32;
    int tx = threadIdx.x, ty = threadIdx.y;
#pragma unroll
    for (int i = 0; i < 4; i++) {
        int c = c0 + ty + i * 8;
        tile[ty + i * 8][tx] = x[((size_t)b * C_ + c) * HW_ + n0 + tx];
    }
    __syncthreads();
#pragma unroll
    for (int i = 0; i < 4; i++) {
        int n = n0 + ty + i * 8;
        int c = c0 + tx;
        float v = tile[tx][ty + i * 8] + pos[(size_t)n * C_ + c];
        thi[((size_t)b * HW_ + n) * C_ + c] = __float2half(v);
    }
}

// ---------------- fused weight splits ----------------------------------------
// w1, w2: hi+lo split (B operands of 2-term GEMMs). w3: hi only.
#define NW1 (C3_*C_)
#define NW2 (C_*C_)
__global__ void splitw_kernel(const float* __restrict__ w1,
                              const float* __restrict__ w2,
                              const float* __restrict__ w3) {
    int i = blockIdx.x * 256 + threadIdx.x;
    if (i < NW1) {
        float v = w1[i];
        __half h = __float2half(v);
        g_w1hi[i] = h;
        g_w1lo[i] = __float2half(v - __half2float(h));
    } else if (i < NW1 + NW2) {
        int idx = i - NW1;
        float v = w2[idx];
        __half h = __float2half(v);
        g_w2hi[idx] = h;
        g_w2lo[idx] = __float2half(v - __half2float(h));
    } else if (i < NW1 + 2 * NW2) {
        int idx = i - NW1 - NW2;
        g_w3hi[idx] = __float2half(w3[idx]);
    }
}

// ---------------- rs two-stage reduction -------------------------------------
__global__ void rs1_kernel(float* __restrict__ psq, float* __restrict__ psk) {
    int bx = blockIdx.x;
    int bh = bx >> 4, part = bx & 15;
    int tid = threadIdx.x;
    int d = tid & 63, sub = tid >> 6;
    size_t base = (size_t)bh * HW_ * DH_ + d;
    int n0 = part * 64 + sub * 16;
    float sq = 0.f, sk = 0.f;
#pragma unroll
    for (int n = 0; n < 16; n++) {
        size_t off = base + (size_t)(n0 + n) * DH_;
        float qv = __half2float(g_qhi[off]);
        float kv = __half2float(g_khi[off]);
        sq += qv * qv;
        sk += kv * kv;
    }
    __shared__ float smq[4][64], smk[4][64];
    smq[sub][d] = sq; smk[sub][d] = sk;
    __syncthreads();
    if (tid < 64) {
        float q = (smq[0][d] + smq[1][d]) + (smq[2][d] + smq[3][d]);
        float k = (smk[0][d] + smk[1][d]) + (smk[2][d] + smk[3][d]);
        psq[((size_t)bh * 16 + part) * 64 + d] = q;
        psk[((size_t)bh * 16 + part) * 64 + d] = k;
    }
}

__global__ void rs2_kernel(const float* __restrict__ psq,
                           const float* __restrict__ psk,
                           const float* __restrict__ temp,
                           float* __restrict__ rs) {
    int bh = blockIdx.x, d = threadIdx.x;
    int h = bh % NH_;
    float q = 0.f, k = 0.f;
#pragma unroll
    for (int p = 0; p < 16; p++) {
        q += psq[((size_t)bh * 16 + p) * 64 + d];
        k += psk[((size_t)bh * 16 + p) * 64 + d];
    }
    float qn = fmaxf(sqrtf(q), 1e-12f);
    float kn = fmaxf(sqrtf(k), 1e-12f);
    rs[(size_t)bh * DH_ + d] = temp[h] / (qn * kn);
}

// ---------------- tensor-core fused flash attention --------------------------
// S = Qhi.Khi (1 MMA). O = (Phi+Plo).Vhi (2 MMA; V truncation averages out
// across ~1024 near-uniform attention weights). Stage = K(8KB)+V(8KB)=16KB.
#define FAT_STAGE 16384u
#define FAT_QOFF  32768u
#define FAT_SMEM  (32768 + 16384 + 256)

__device__ __forceinline__ void fat_loadkv(
    uint32_t buf, int tid, size_t kvbase, int kc,
    const h16* __restrict__ khi, const h16* __restrict__ vhi) {
#pragma unroll
    for (int it = 0; it < 2; it++) {
        int idx = it * 256 + tid;
        int r = idx >> 3, cg = idx & 7;
        uint32_t so = SWZ((uint32_t)(r * 128 + cg * 16));
        size_t g = kvbase + (size_t)(kc + r) * DH_ + cg * 8;
        cp16(buf +    0u + so, khi + g);
        cp16(buf + 8192u + so, vhi + g);
    }
    asm volatile("cp.async.commit_group;" ::: "memory");
}

__global__ __launch_bounds__(256, 2)
void fat_kernel(const h16* __restrict__ qhi,
                const float* __restrict__ rs,
                const h16* __restrict__ khi, const h16* __restrict__ vhi,
                h16* __restrict__ ohi) {
    extern __shared__ char smc[];
    uint32_t sb = smem_u32(smc);
    float* rss = (float*)(smc + FAT_QOFF + 16384);
    int bh = blockIdx.y;
    int b = bh >> 3, h = bh & 7;
    int q0 = blockIdx.x * 128;
    int tid = threadIdx.x, wid = tid >> 5, lane = tid & 31;
    int mb = wid * 16;

    if (tid < 64) rss[tid] = rs[bh * DH_ + tid];
    __syncthreads();

    // stage Q (scaled by rs) fp16 into persistent smem
#pragma unroll
    for (int v = 0; v < 8; v++) {
        int idx = v * 256 + tid;
        int row = idx >> 4, dq = (idx & 15) * 4;
        size_t qoff = ((size_t)bh * HW_ + q0 + row) * DH_ + dq;
        __half2 ha = *(const __half2*)&qhi[qoff];
        __half2 hb = *(const __half2*)&qhi[qoff + 2];
        float qx = __half2float(ha.x) * rss[dq];
        float qy = __half2float(ha.y) * rss[dq + 1];
        float qz = __half2float(hb.x) * rss[dq + 2];
        float qw = __half2float(hb.y) * rss[dq + 3];
        uint32_t off = SWZ((uint32_t)(row * 128 + dq * 2));
        *(uint32_t*)(smc + FAT_QOFF + off)     = pack2(qx, qy);
        *(uint32_t*)(smc + FAT_QOFF + off + 4) = pack2(qz, qw);
    }
    __syncthreads();

    float o[8][4];
#pragma unroll
    for (int j = 0; j < 8; j++)
#pragma unroll
        for (int q = 0; q < 4; q++) o[j][q] = 0.f;
    float m0 = -1e30f, m1 = -1e30f, l0 = 0.f, l1 = 0.f;
    const size_t kvbase = (size_t)bh * HW_ * DH_;

    fat_loadkv(sb, tid, kvbase, 0, khi, vhi);
    for (int kt = 0; kt < 16; kt++) {
        uint32_t cur = sb + (uint32_t)(kt & 1) * FAT_STAGE;
        if (kt + 1 < 16) {
            fat_loadkv(sb + (uint32_t)((kt + 1) & 1) * FAT_STAGE, tid, kvbase,
                       (kt + 1) * 64, khi, vhi);
            asm volatile("cp.async.wait_group 1;" ::: "memory");
        } else {
            asm volatile("cp.async.wait_group 0;" ::: "memory");
        }
        __syncthreads();

        // ---- S = Q.K^T (1 MMA per 16x8 tile)
        float s[8][4];
#pragma unroll
        for (int j = 0; j < 8; j++)
#pragma unroll
            for (int q = 0; q < 4; q++) s[j][q] = 0.f;
#pragma unroll
        for (int ks = 0; ks < 4; ks++) {
            uint32_t qao = SWZ((uint32_t)((mb + (lane & 15)) * 128 +
                                          (lane >> 4) * 16 + ks * 32));
            uint32_t qh4[4];
            ldsm4(qh4, sb + FAT_QOFF + qao);
            uint32_t brow = (uint32_t)(((lane & 7) + ((lane >> 4) & 1) * 8) * 128 +
                                       ((lane >> 3) & 1) * 16 + ks * 32);
#pragma unroll
            for (int np = 0; np < 4; np++) {
                uint32_t bo = SWZ(brow + (uint32_t)(np * 16 * 128));
                uint32_t kh4[4];
                ldsm4(kh4, cur + bo);
#pragma unroll
                for (int half = 0; half < 2; half++) {
                    int j = np * 2 + half;
                    const uint32_t bhh[2] = {kh4[half * 2], kh4[half * 2 + 1]};
                    mma16816(s[j], qh4, bhh);
                }
            }
        }

        // ---- online softmax (rows r=lane>>2 and r+8)
        float mx0 = -1e30f, mx1 = -1e30f;
#pragma unroll
        for (int j = 0; j < 8; j++) {
            mx0 = fmaxf(mx0, fmaxf(s[j][0], s[j][1]));
            mx1 = fmaxf(mx1, fmaxf(s[j][2], s[j][3]));
        }
        mx0 = fmaxf(mx0, __shfl_xor_sync(0xffffffffu, mx0, 1));
        mx0 = fmaxf(mx0, __shfl_xor_sync(0xffffffffu, mx0, 2));
        mx1 = fmaxf(mx1, __shfl_xor_sync(0xffffffffu, mx1, 1));
        mx1 = fmaxf(mx1, __shfl_xor_sync(0xffffffffu, mx1, 2));
        float mn0 = fmaxf(m0, mx0), mn1 = fmaxf(m1, mx1);
        float al0 = __expf(m0 - mn0), al1 = __expf(m1 - mn1);
        float sum0 = 0.f, sum1 = 0.f;
#pragma unroll
        for (int j = 0; j < 8; j++) {
            s[j][0] = __expf(s[j][0] - mn0);
            s[j][1] = __expf(s[j][1] - mn0);
            s[j][2] = __expf(s[j][2] - mn1);
            s[j][3] = __expf(s[j][3] - mn1);
            sum0 += s[j][0] + s[j][1];
            sum1 += s[j][2] + s[j][3];
        }
        sum0 += __shfl_xor_sync(0xffffffffu, sum0, 1);
        sum0 += __shfl_xor_sync(0xffffffffu, sum0, 2);
        sum1 += __shfl_xor_sync(0xffffffffu, sum1, 1);
        sum1 += __shfl_xor_sync(0xffffffffu, sum1, 2);
        l0 = l0 * al0 + sum0; l1 = l1 * al1 + sum1;
        m0 = mn0; m1 = mn1;
#pragma unroll
        for (int j = 0; j < 8; j++) {
            o[j][0] *= al0; o[j][1] *= al0;
            o[j][2] *= al1; o[j][3] *= al1;
        }

        // ---- O += (Phi + Plo).Vhi (P exact to 2^-22; 2 MMAs)
#pragma unroll
        for (int ks = 0; ks < 4; ks++) {
            int j0 = 2 * ks, j1 = 2 * ks + 1;
            uint32_t ph[4], pl[4];
            split2(s[j0][0], s[j0][1], ph[0], pl[0]);
            split2(s[j0][2], s[j0][3], ph[1], pl[1]);
            split2(s[j1][0], s[j1][1], ph[2], pl[2]);
            split2(s[j1][2], s[j1][3], ph[3], pl[3]);
            uint32_t vrow = (uint32_t)((ks * 16 + (lane & 7) + ((lane >> 3) & 1) * 8) * 128 +
                                       ((lane >> 4) & 1) * 16);
#pragma unroll
            for (int np = 0; np < 4; np++) {
                uint32_t vo = SWZ(vrow + (uint32_t)(np * 32));
                uint32_t vh4[4];
                ldsm4t(vh4, cur + 8192u + vo);
#pragma unroll
                for (int half = 0; half < 2; half++) {
                    int j = np * 2 + half;
                    const uint32_t bvh[2] = {vh4[half * 2], vh4[half * 2 + 1]};
                    mma16816(o[j], ph, bvh);
                    mma16816(o[j], pl, bvh);
                }
            }
        }
        __syncthreads();
    }

    // epilogue: normalize, store fp16 hi only
    float inv0 = 1.f / l0, inv1 = 1.f / l1;
    int r0 = lane >> 2, cc = (lane & 3) * 2;
    int row0 = q0 + mb + r0, row1 = row0 + 8;
#pragma unroll
    for (int j = 0; j < 8; j++) {
        int col = h * DH_ + j * 8 + cc;
        size_t off0 = ((size_t)(b * HW_ + row0)) * C_ + col;
        size_t off1 = ((size_t)(b * HW_ + row1)) * C_ + col;
        *(uint32_t*)&ohi[off0] = pack2(o[j][0] * inv0, o[j][1] * inv0);
        *(uint32_t*)&ohi[off1] = pack2(o[j][2] * inv1, o[j][3] * inv1);
    }
}

// ---------------- LayerNorm over C + residual + transpose to [B,C,HW] -------
__global__ void ln_residual_kernel(const float* __restrict__ ob,
                                   const float* __restrict__ x,
                                   const float* __restrict__ g,
                                   const float* __restrict__ be,
                                   float* __restrict__ y) {
    int row = blockIdx.x;
    int b = row >> 10, n = row & 1023;
    const float* pr = ob + (size_t)row * C_;
    int tid = threadIdx.x;
    float v0 = pr[tid], v1 = pr[tid + 256];
    __shared__ float red[256];
    red[tid] = v0 + v1; __syncthreads();
    for (int s = 128; s > 0; s >>= 1) {
        if (tid < s) red[tid] += red[tid + s];
        __syncthreads();
    }
    float mean = red[0] * (1.0f / C_);
    __syncthreads();
    float d0 = v0 - mean, d1 = v1 - mean;
    red[tid] = d0 * d0 + d1 * d1; __syncthreads();
    for (int s = 128; s > 0; s >>= 1) {
        if (tid < s) red[tid] += red[tid + s];
        __syncthreads();
    }
    float rstd = rsqrtf(red[0] * (1.0f / C_) + 1e-5f);
    int c0 = tid, c1 = tid + 256;
    size_t i0 = ((size_t)b * C_ + c0) * HW_ + n;
    size_t i1 = ((size_t)b * C_ + c1) * HW_ + n;
    y[i0] = d0 * rstd * g[c0] + be[c0] + x[i0];
    y[i1] = d1 * rstd * g[c1] + be[c1] + x[i1];
}

// ---------------- fused depthwise 3x3 + transpose -> fp16 --------------------
__global__ void dwt_kernel(const float* __restrict__ y,
                           const float* __restrict__ w,
                           const float* __restrict__ bias,
                           h16* __restrict__ hi) {
    __shared__ float yt[32][3][33];
    __shared__ float ot[32][33];   // [w][c]
    int hh = blockIdx.x, c0 = blockIdx.y * 32, b = blockIdx.z;
    int tid = threadIdx.x;
    int c = tid >> 3, wg = (tid & 7) * 4;

#pragma unroll
    for (int r = 0; r < 3; r++) {
        int ih = hh + r - 1;
        float4 v = make_float4(0.f, 0.f, 0.f, 0.f);
        if (ih >= 0 && ih < H_)
            v = *(const float4*)&y[((size_t)(b * C_ + c0 + c)) * HW_ + ih * W_ + wg];
        yt[c][r][wg + 0] = v.x; yt[c][r][wg + 1] = v.y;
        yt[c][r][wg + 2] = v.z; yt[c][r][wg + 3] = v.w;
    }
    float wc[9];
#pragma unroll
    for (int i = 0; i < 9; i++) wc[i] = w[(c0 + c) * 9 + i];
    float bs = bias[c0 + c];
    __syncthreads();

#pragma unroll
    for (int j = 0; j < 4; j++) {
        int ww = wg + j;
        float acc = bs;
#pragma unroll
        for (int ki = 0; ki < 3; ki++)
#pragma unroll
            for (int kj = 0; kj < 3; kj++) {
                int iw = ww + kj - 1;
                if (iw >= 0 && iw < W_) acc += wc[ki * 3 + kj] * yt[c][ki][iw];
            }
        ot[ww][c] = acc;
    }
    __syncthreads();

    int w2 = tid >> 3, cg = (tid & 7) * 4;
    int token = hh * W_ + w2;
    size_t base = ((size_t)b * HW_ + token) * C_ + c0 + cg;
    *(uint32_t*)&hi[base]     = pack2(ot[w2][cg],     ot[w2][cg + 1]);
    *(uint32_t*)&hi[base + 2] = pack2(ot[w2][cg + 2], ot[w2][cg + 3]);
}

// ---------------- launch ------------------------------------------------------
extern "C" void kernel_launch(void* const* d_in, const int* in_sizes, int n_in,
                              void* d_out, int out_size) {
    const float* x      = (const float*)d_in[0];
    const float* qkv_w  = (const float*)d_in[1];
    const float* proj_w = (const float*)d_in[2];
    const float* proj_b = (const float*)d_in[3];
    const float* temper = (const float*)d_in[4];
    const float* ln_g   = (const float*)d_in[5];
    const float* ln_b   = (const float*)d_in[6];
    const float* pos    = (const float*)d_in[7];
    const float* dw_w   = (const float*)d_in[8];
    const float* dw_b   = (const float*)d_in[9];
    const float* pw_w   = (const float*)d_in[10];
    const float* pw_b   = (const float*)d_in[11];
    float* out = (float*)d_out;

    h16 *thi, *w1hi, *w1lo, *w2hi, *w2lo, *w3hi;
    h16 *ohi, *dThi, *qhi, *khi, *vhi;
    float *rs, *ob, *y, *psq, *psk;
    cudaGetSymbolAddress((void**)&thi,  g_thi);
    cudaGetSymbolAddress((void**)&w1hi, g_w1hi);
    cudaGetSymbolAddress((void**)&w1lo, g_w1lo);
    cudaGetSymbolAddress((void**)&w2hi, g_w2hi);
    cudaGetSymbolAddress((void**)&w2lo, g_w2lo);
    cudaGetSymbolAddress((void**)&w3hi, g_w3hi);
    cudaGetSymbolAddress((void**)&ohi,  g_ohi);
    cudaGetSymbolAddress((void**)&dThi, g_dThi);
    cudaGetSymbolAddress((void**)&qhi,  g_qhi);
    cudaGetSymbolAddress((void**)&khi,  g_khi);
    cudaGetSymbolAddress((void**)&vhi,  g_vhi);
    cudaGetSymbolAddress((void**)&rs,   g_rs);
    cudaGetSymbolAddress((void**)&psq,  g_psq);
    cudaGetSymbolAddress((void**)&psk,  g_psk);
    cudaGetSymbolAddress((void**)&ob,   g_ob);
    cudaGetSymbolAddress((void**)&y,    g_y);

    cudaFuncSetAttribute(fat_kernel,
                         cudaFuncAttributeMaxDynamicSharedMemorySize, FAT_SMEM);
    cudaFuncSetAttribute(gemm_tc,
                         cudaFuncAttributeMaxDynamicSharedMemorySize, GSMEM);

    // fused weight splits
    splitw_kernel<<<(NW1 + 2*NW2 + 255)/256, 256>>>(qkv_w, proj_w, pw_w);
    // t = transpose(x) + pos (fp16)
    build_t_kernel<<<dim3(HW_/32, C_/32, B_), dim3(32, 8)>>>(x, pos, thi);
    // qkv GEMM: q,k cols 1-term; v cols 2-term; fp16 head-major output
    gemm_tc<<<dim3(C3_/128, (B_*HW_)/128, 1), 256, GSMEM>>>(
        thi, w1hi, w1lo, nullptr, nullptr, nullptr, C_, 0, 0, 0,
        1 /*mode=qkv*/, 1 /*ntLow*/, 2 /*ntHigh*/, 1024 /*v cols*/);
    // rs two-stage reduction
    rs1_kernel<<<B_*NH_*16, 256>>>(psq, psk);
    rs2_kernel<<<B_*NH_, 64>>>(psq, psk, temper, rs);
    // tensor-core fused attention -> ohi
    fat_kernel<<<dim3(HW_/128, B_*NH_), 256, FAT_SMEM>>>(
        qhi, rs, khi, vhi, ohi);
    // proj = o @ proj_w^T + proj_b (2-term: ohi x (w2hi + w2lo))
    gemm_tc<<<dim3(C_/128, (B_*HW_)/128, 1), 256, GSMEM>>>(
        ohi, w2hi, w2lo, proj_b, nullptr, ob, C_, C_, 0, 0,
        0, 2, 2, 1 << 30);
    // LN + residual + transpose to [B,C,HW]
    ln_residual_kernel<<<B_*HW_, 256>>>(ob, x, ln_g, ln_b, y);
    // fused depthwise 3x3 + transpose (fp16)
    dwt_kernel<<<dim3(H_, C_/32, B_), 256>>>(y, dw_w, dw_b, dThi);
    // pointwise (1-term) + bias + residual -> out
    gemm_tc<<<dim3(HW_/128, C_/128, B_), 256, GSMEM>>>(
        w3hi, dThi, dThi, pw_b, y, out, C_, HW_,
        (long)HW_*C_, (long)C_*HW_, 0, 1, 1, 1 << 30);
}

// round 11
// speedup vs baseline: 1.4117x; 1.0481x over previous
#include <cuda_runtime.h>
#include <cuda_fp16.h>
#include <cstdint>

#define B_  8
#define C_  512
#define H_  32
#define W_  32
#define NH_ 8
#define DH_ 64
#define HW_ 1024
#define C3_ (3*C_)

typedef __half h16;

// ---------------- scratch (device globals; no allocation allowed) ----------
__device__ h16   g_thi[(size_t)B_*HW_*C_];
__device__ h16   g_w1hi[(size_t)C3_*C_];
__device__ h16   g_w1lo[(size_t)C3_*C_];
__device__ h16   g_w2hi[(size_t)C_*C_];
__device__ h16   g_w2lo[(size_t)C_*C_];
__device__ h16   g_w3hi[(size_t)C_*C_];
__device__ float g_rs [(size_t)B_*NH_*DH_];
__device__ float g_psq[(size_t)B_*NH_*16*DH_];
__device__ float g_psk[(size_t)B_*NH_*16*DH_];
__device__ h16   g_qhi[(size_t)B_*NH_*HW_*DH_];
__device__ h16   g_khi[(size_t)B_*NH_*HW_*DH_];
__device__ h16   g_vhi[(size_t)B_*NH_*HW_*DH_];
__device__ h16   g_ohi[(size_t)B_*HW_*C_];
__device__ h16   g_olo[(size_t)B_*HW_*C_];
__device__ float g_ob [(size_t)B_*HW_*C_];
__device__ float g_y  [(size_t)B_*C_*HW_];
__device__ h16   g_dThi[(size_t)B_*HW_*C_];

// ---------------- small PTX helpers -----------------------------------------
__device__ __forceinline__ uint32_t smem_u32(const void* p) {
    uint32_t a;
    asm("{ .reg .u64 t; cvta.to.shared.u64 t, %1; cvt.u32.u64 %0, t; }"
        : "=r"(a) : "l"(p));
    return a;
}
__device__ __forceinline__ void cp16(uint32_t s, const void* g) {
    asm volatile("cp.async.cg.shared.global [%0], [%1], 16;" :: "r"(s), "l"(g));
}
#define SWZ(x) ((x) ^ (((x) >> 3) & 0x70u))

__device__ __forceinline__ void ldsm4(uint32_t* r, uint32_t addr) {
    asm volatile("ldmatrix.sync.aligned.m8n8.x4.shared.b16 {%0,%1,%2,%3}, [%4];"
                 : "=r"(r[0]), "=r"(r[1]), "=r"(r[2]), "=r"(r[3]) : "r"(addr));
}
__device__ __forceinline__ void ldsm4t(uint32_t* r, uint32_t addr) {
    asm volatile("ldmatrix.sync.aligned.m8n8.x4.trans.shared.b16 {%0,%1,%2,%3}, [%4];"
                 : "=r"(r[0]), "=r"(r[1]), "=r"(r[2]), "=r"(r[3]) : "r"(addr));
}
__device__ __forceinline__ void mma16816(float* c, const uint32_t* a,
                                         const uint32_t* b) {
    asm volatile(
        "mma.sync.aligned.m16n8k16.row.col.f32.f16.f16.f32 "
        "{%0,%1,%2,%3}, {%4,%5,%6,%7}, {%8,%9}, {%0,%1,%2,%3};"
        : "+f"(c[0]), "+f"(c[1]), "+f"(c[2]), "+f"(c[3])
        : "r"(a[0]), "r"(a[1]), "r"(a[2]), "r"(a[3]), "r"(b[0]), "r"(b[1]));
}
__device__ __forceinline__ void split2(float a, float b, uint32_t& hi, uint32_t& lo) {
    __half ha = __float2half(a), hb = __float2half(b);
    __half2 h; h.x = ha; h.y = hb;
    hi = *(uint32_t*)&h;
    __half2 l;
    l.x = __float2half(a - __half2float(ha));
    l.y = __float2half(b - __half2float(hb));
    lo = *(uint32_t*)&l;
}
__device__ __forceinline__ uint32_t pack2(float a, float b) {
    __half2 h; h.x = __float2half(a); h.y = __float2half(b);
    return *(uint32_t*)&h;
}

// ---------------- HMMA GEMM: D[128,128] = A @ B^T via fp16 hi/lo split ------
// nt per CTA: 1 = ahi*bhi; 2 = + ahi*blo; 3 = + alo*bhi (~fp32 exact).
// nt = (n0 >= nHiStart) ? ntHigh : ntLow.
#define GTB   16384u
#define GSMEM (1024 + 8 * 16384)

__device__ __forceinline__ void load_chunk(
    uint32_t dst, int tid, int m0, int n0, int K, int kc, int nt,
    const h16* __restrict__ Ahi, const h16* __restrict__ Alo,
    const h16* __restrict__ Bhi, const h16* __restrict__ Blo) {
#pragma unroll
    for (int it = 0; it < 4; it++) {
        int idx = it * 256 + tid;
        int r = idx >> 3, cg = idx & 7;
        uint32_t so = SWZ((uint32_t)(r * 128 + cg * 16));
        size_t ga = (size_t)(m0 + r) * K + kc + cg * 8;
        size_t gb = (size_t)(n0 + r) * K + kc + cg * 8;
        cp16(dst            + so, Ahi + ga);
        if (nt == 3) cp16(dst + GTB + so, Alo + ga);
        cp16(dst + 2u * GTB + so, Bhi + gb);
        if (nt >= 2) cp16(dst + 3u * GTB + so, Blo + gb);
    }
    asm volatile("cp.async.commit_group;" ::: "memory");
}

__global__ __launch_bounds__(256, 1)
void gemm_tc(const h16* __restrict__ Ahi, const h16* __restrict__ Alo,
             const h16* __restrict__ Bhi, const h16* __restrict__ Blo,
             const float* __restrict__ bias, const float* __restrict__ resid,
             float* __restrict__ Cout, int K, int Nld,
             long bBatch, long cBatch, int mode,
             int ntLow, int ntHigh, int nHiStart) {
    extern __shared__ char smc[];
    uint32_t sb = smem_u32(smc);
    int tid = threadIdx.x, wid = tid >> 5, lane = tid & 31;
    int m0 = blockIdx.y * 128, n0 = blockIdx.x * 128;
    const int nt = (n0 >= nHiStart) ? ntHigh : ntLow;
    Bhi += (size_t)blockIdx.z * bBatch;
    Blo += (size_t)blockIdx.z * bBatch;
    if (Cout) Cout += (size_t)blockIdx.z * cBatch;
    const float* res = resid ? resid + (size_t)blockIdx.z * cBatch : nullptr;

    float* bsm = (float*)smc;
    if (tid < 128) bsm[tid] = bias ? bias[n0 + tid] : 0.f;

    const uint32_t t0 = sb + 1024;
    const int nchunk = K >> 6;
    const int mb = (wid & 3) * 32;
    const int nb = (wid >> 2) * 64;

    float acc[2][8][4];
#pragma unroll
    for (int i = 0; i < 2; i++)
#pragma unroll
        for (int j = 0; j < 8; j++)
#pragma unroll
            for (int q = 0; q < 4; q++) acc[i][j][q] = 0.f;

    load_chunk(t0, tid, m0, n0, K, 0, nt, Ahi, Alo, Bhi, Blo);
    for (int c = 0; c < nchunk; c++) {
        if (c + 1 < nchunk) {
            load_chunk(t0 + (uint32_t)((c + 1) & 1) * (4u * GTB), tid, m0, n0, K,
                       (c + 1) << 6, nt, Ahi, Alo, Bhi, Blo);
            asm volatile("cp.async.wait_group 1;" ::: "memory");
        } else {
            asm volatile("cp.async.wait_group 0;" ::: "memory");
        }
        __syncthreads();
        uint32_t bufA = t0 + (uint32_t)(c & 1) * (4u * GTB);
#pragma unroll
        for (int ks = 0; ks < 4; ks++) {
            int kb = ks * 32;
            uint32_t ao = SWZ((uint32_t)((mb + (lane & 15)) * 128 +
                                         (lane >> 4) * 16 + kb));
            uint32_t ahi[4], alo[4];
            ldsm4(ahi, bufA + ao);
            if (nt == 3) ldsm4(alo, bufA + GTB + ao);
            uint32_t ao2 = SWZ((uint32_t)((mb + 16 + (lane & 15)) * 128 +
                                          (lane >> 4) * 16 + kb));
            uint32_t ahi2[4], alo2[4];
            ldsm4(ahi2, bufA + ao2);
            if (nt == 3) ldsm4(alo2, bufA + GTB + ao2);
            uint32_t brow = (uint32_t)((nb + (lane & 7) + ((lane >> 4) & 1) * 8) * 128 +
                                       ((lane >> 3) & 1) * 16 + kb);
#pragma unroll
            for (int ntp = 0; ntp < 4; ntp++) {
                uint32_t bo = SWZ(brow + (uint32_t)(ntp * 16 * 128));
                uint32_t bhi[4], blo[4];
                ldsm4(bhi, bufA + 2u * GTB + bo);
                if (nt >= 2) ldsm4(blo, bufA + 3u * GTB + bo);
#pragma unroll
                for (int half = 0; half < 2; half++) {
                    int ntile = ntp * 2 + half;
                    const uint32_t bh[2] = {bhi[half * 2], bhi[half * 2 + 1]};
                    mma16816(acc[0][ntile], ahi, bh);
                    mma16816(acc[1][ntile], ahi2, bh);
                    if (nt >= 2) {
                        const uint32_t bl[2] = {blo[half * 2], blo[half * 2 + 1]};
                        mma16816(acc[0][ntile], ahi, bl);
                        mma16816(acc[1][ntile], ahi2, bl);
                    }
                    if (nt == 3) {
                        mma16816(acc[0][ntile], alo, bh);
                        mma16816(acc[1][ntile], alo2, bh);
                    }
                }
            }
        }
        __syncthreads();
    }

    int rbase = m0 + mb + (lane >> 2);
    int cbase = nb + (lane & 3) * 2;
#pragma unroll
    for (int mt = 0; mt < 2; mt++) {
#pragma unroll
        for (int ntile = 0; ntile < 8; ntile++) {
            int ncol = cbase + ntile * 8;
            int gcol = n0 + ncol;
#pragma unroll
            for (int rr = 0; rr < 2; rr++) {
                int row = rbase + mt * 16 + rr * 8;
                float v0 = acc[mt][ntile][rr * 2 + 0];
                float v1 = acc[mt][ntile][rr * 2 + 1];
                if (mode == 0) {
                    v0 += bsm[ncol]; v1 += bsm[ncol + 1];
                    size_t idx = (size_t)row * Nld + gcol;
                    if (res) {
                        float2 q = *(const float2*)(res + idx);
                        v0 += q.x; v1 += q.y;
                    }
                    float2 o; o.x = v0; o.y = v1;
                    *(float2*)(Cout + idx) = o;
                } else {
                    // qkv output: [bh][token][64] head-major, fp16 hi only
                    int b = row >> 10, tok = row & 1023;
                    int region = gcol >> 9;        // 0=q 1=k 2=v
                    int hd = gcol & 511;
                    int h = hd >> 6, d = hd & 63;
                    size_t dst = (((size_t)(b * NH_ + h) * HW_) + tok) * DH_ + d;
                    h16* ph = (region == 0) ? g_qhi : (region == 1) ? g_khi : g_vhi;
                    *(uint32_t*)&ph[dst] = pack2(v0, v1);
                }
            }
        }
    }
}

// ---------------- 1) t = transpose(x) + pos -> fp16 -------------------------
__global__ void build_t_kernel(const float* __restrict__ x,
                               const float* __restrict__ pos,
                               h16* __restrict__ thi) {
    __shared__ float tile[32][33];
    int b  = blockIdx.z;
    int n0 = blockIdx.x * 32;
    int c0 = blockIdx.y * 32;
    int tx = threadIdx.x, ty = threadIdx.y;
#pragma unroll
    for (int i = 0; i < 4; i++) {
        int c = c0 + ty + i * 8;
        tile[ty + i * 8][tx] = x[((size_t)b * C_ + c) * HW_ + n0 + tx];
    }
    __syncthreads();
#pragma unroll
    for (int i = 0; i < 4; i++) {
        int n = n0 + ty + i * 8;
        int c = c0 + tx;
        float v = tile[tx][ty + i * 8] + pos[(size_t)n * C_ + c];
        thi[((size_t)b * HW_ + n) * C_ + c] = __float2half(v);
    }
}

// ---------------- fused weight splits ----------------------------------------
#define NW1 (C3_*C_)
#define NW2 (C_*C_)
__global__ void splitw_kernel(const float* __restrict__ w1,
                              const float* __restrict__ w2,
                              const float* __restrict__ w3) {
    int i = blockIdx.x * 256 + threadIdx.x;
    if (i < NW1) {
        float v = w1[i];
        __half h = __float2half(v);
        g_w1hi[i] = h;
        g_w1lo[i] = __float2half(v - __half2float(h));
    } else if (i < NW1 + NW2) {
        int idx = i - NW1;
        float v = w2[idx];
        __half h = __float2half(v);
        g_w2hi[idx] = h;
        g_w2lo[idx] = __float2half(v - __half2float(h));
    } else if (i < NW1 + 2 * NW2) {
        int idx = i - NW1 - NW2;
        g_w3hi[idx] = __float2half(w3[idx]);
    }
}

// ---------------- rs two-stage reduction -------------------------------------
__global__ void rs1_kernel(float* __restrict__ psq, float* __restrict__ psk) {
    int bx = blockIdx.x;
    int bh = bx >> 4, part = bx & 15;
    int tid = threadIdx.x;
    int d = tid & 63, sub = tid >> 6;
    size_t base = (size_t)bh * HW_ * DH_ + d;
    int n0 = part * 64 + sub * 16;
    float sq = 0.f, sk = 0.f;
#pragma unroll
    for (int n = 0; n < 16; n++) {
        size_t off = base + (size_t)(n0 + n) * DH_;
        float qv = __half2float(g_qhi[off]);
        float kv = __half2float(g_khi[off]);
        sq += qv * qv;
        sk += kv * kv;
    }
    __shared__ float smq[4][64], smk[4][64];
    smq[sub][d] = sq; smk[sub][d] = sk;
    __syncthreads();
    if (tid < 64) {
        float q = (smq[0][d] + smq[1][d]) + (smq[2][d] + smq[3][d]);
        float k = (smk[0][d] + smk[1][d]) + (smk[2][d] + smk[3][d]);
        psq[((size_t)bh * 16 + part) * 64 + d] = q;
        psk[((size_t)bh * 16 + part) * 64 + d] = k;
    }
}

__global__ void rs2_kernel(const float* __restrict__ psq,
                           const float* __restrict__ psk,
                           const float* __restrict__ temp,
                           float* __restrict__ rs) {
    int bh = blockIdx.x, d = threadIdx.x;
    int h = bh % NH_;
    float q = 0.f, k = 0.f;
#pragma unroll
    for (int p = 0; p < 16; p++) {
        q += psq[((size_t)bh * 16 + p) * 64 + d];
        k += psk[((size_t)bh * 16 + p) * 64 + d];
    }
    float qn = fmaxf(sqrtf(q), 1e-12f);
    float kn = fmaxf(sqrtf(k), 1e-12f);
    rs[(size_t)bh * DH_ + d] = temp[h] / (qn * kn);
}

// ---------------- tensor-core fused flash attention --------------------------
// S = Qhi.Khi (1 MMA). O = Phi.Vhi (1 MMA; P & V truncations average out
// across ~1024 near-uniform attention weights). Output o stored hi/lo.
#define FAT_STAGE 16384u
#define FAT_QOFF  32768u
#define FAT_SMEM  (32768 + 16384 + 256)

__device__ __forceinline__ void fat_loadkv(
    uint32_t buf, int tid, size_t kvbase, int kc,
    const h16* __restrict__ khi, const h16* __restrict__ vhi) {
#pragma unroll
    for (int it = 0; it < 2; it++) {
        int idx = it * 256 + tid;
        int r = idx >> 3, cg = idx & 7;
        uint32_t so = SWZ((uint32_t)(r * 128 + cg * 16));
        size_t g = kvbase + (size_t)(kc + r) * DH_ + cg * 8;
        cp16(buf +    0u + so, khi + g);
        cp16(buf + 8192u + so, vhi + g);
    }
    asm volatile("cp.async.commit_group;" ::: "memory");
}

__global__ __launch_bounds__(256, 2)
void fat_kernel(const h16* __restrict__ qhi,
                const float* __restrict__ rs,
                const h16* __restrict__ khi, const h16* __restrict__ vhi,
                h16* __restrict__ ohi, h16* __restrict__ olo) {
    extern __shared__ char smc[];
    uint32_t sb = smem_u32(smc);
    float* rss = (float*)(smc + FAT_QOFF + 16384);
    int bh = blockIdx.y;
    int b = bh >> 3, h = bh & 7;
    int q0 = blockIdx.x * 128;
    int tid = threadIdx.x, wid = tid >> 5, lane = tid & 31;
    int mb = wid * 16;

    if (tid < 64) rss[tid] = rs[bh * DH_ + tid];
    __syncthreads();

    // stage Q (scaled by rs) fp16 into persistent smem
#pragma unroll
    for (int v = 0; v < 8; v++) {
        int idx = v * 256 + tid;
        int row = idx >> 4, dq = (idx & 15) * 4;
        size_t qoff = ((size_t)bh * HW_ + q0 + row) * DH_ + dq;
        __half2 ha = *(const __half2*)&qhi[qoff];
        __half2 hb = *(const __half2*)&qhi[qoff + 2];
        float qx = __half2float(ha.x) * rss[dq];
        float qy = __half2float(ha.y) * rss[dq + 1];
        float qz = __half2float(hb.x) * rss[dq + 2];
        float qw = __half2float(hb.y) * rss[dq + 3];
        uint32_t off = SWZ((uint32_t)(row * 128 + dq * 2));
        *(uint32_t*)(smc + FAT_QOFF + off)     = pack2(qx, qy);
        *(uint32_t*)(smc + FAT_QOFF + off + 4) = pack2(qz, qw);
    }
    __syncthreads();

    float o[8][4];
#pragma unroll
    for (int j = 0; j < 8; j++)
#pragma unroll
        for (int q = 0; q < 4; q++) o[j][q] = 0.f;
    float m0 = -1e30f, m1 = -1e30f, l0 = 0.f, l1 = 0.f;
    const size_t kvbase = (size_t)bh * HW_ * DH_;

    fat_loadkv(sb, tid, kvbase, 0, khi, vhi);
    for (int kt = 0; kt < 16; kt++) {
        uint32_t cur = sb + (uint32_t)(kt & 1) * FAT_STAGE;
        if (kt + 1 < 16) {
            fat_loadkv(sb + (uint32_t)((kt + 1) & 1) * FAT_STAGE, tid, kvbase,
                       (kt + 1) * 64, khi, vhi);
            asm volatile("cp.async.wait_group 1;" ::: "memory");
        } else {
            asm volatile("cp.async.wait_group 0;" ::: "memory");
        }
        __syncthreads();

        // ---- S = Q.K^T (1 MMA per 16x8 tile)
        float s[8][4];
#pragma unroll
        for (int j = 0; j < 8; j++)
#pragma unroll
            for (int q = 0; q < 4; q++) s[j][q] = 0.f;
#pragma unroll
        for (int ks = 0; ks < 4; ks++) {
            uint32_t qao = SWZ((uint32_t)((mb + (lane & 15)) * 128 +
                                          (lane >> 4) * 16 + ks * 32));
            uint32_t qh4[4];
            ldsm4(qh4, sb + FAT_QOFF + qao);
            uint32_t brow = (uint32_t)(((lane & 7) + ((lane >> 4) & 1) * 8) * 128 +
                                       ((lane >> 3) & 1) * 16 + ks * 32);
#pragma unroll
            for (int np = 0; np < 4; np++) {
                uint32_t bo = SWZ(brow + (uint32_t)(np * 16 * 128));
                uint32_t kh4[4];
                ldsm4(kh4, cur + bo);
#pragma unroll
                for (int half = 0; half < 2; half++) {
                    int j = np * 2 + half;
                    const uint32_t bhh[2] = {kh4[half * 2], kh4[half * 2 + 1]};
                    mma16816(s[j], qh4, bhh);
                }
            }
        }

        // ---- online softmax (rows r=lane>>2 and r+8)
        float mx0 = -1e30f, mx1 = -1e30f;
#pragma unroll
        for (int j = 0; j < 8; j++) {
            mx0 = fmaxf(mx0, fmaxf(s[j][0], s[j][1]));
            mx1 = fmaxf(mx1, fmaxf(s[j][2], s[j][3]));
        }
        mx0 = fmaxf(mx0, __shfl_xor_sync(0xffffffffu, mx0, 1));
        mx0 = fmaxf(mx0, __shfl_xor_sync(0xffffffffu, mx0, 2));
        mx1 = fmaxf(mx1, __shfl_xor_sync(0xffffffffu, mx1, 1));
        mx1 = fmaxf(mx1, __shfl_xor_sync(0xffffffffu, mx1, 2));
        float mn0 = fmaxf(m0, mx0), mn1 = fmaxf(m1, mx1);
        float al0 = __expf(m0 - mn0), al1 = __expf(m1 - mn1);
        float sum0 = 0.f, sum1 = 0.f;
#pragma unroll
        for (int j = 0; j < 8; j++) {
            s[j][0] = __expf(s[j][0] - mn0);
            s[j][1] = __expf(s[j][1] - mn0);
            s[j][2] = __expf(s[j][2] - mn1);
            s[j][3] = __expf(s[j][3] - mn1);
            sum0 += s[j][0] + s[j][1];
            sum1 += s[j][2] + s[j][3];
        }
        sum0 += __shfl_xor_sync(0xffffffffu, sum0, 1);
        sum0 += __shfl_xor_sync(0xffffffffu, sum0, 2);
        sum1 += __shfl_xor_sync(0xffffffffu, sum1, 1);
        sum1 += __shfl_xor_sync(0xffffffffu, sum1, 2);
        l0 = l0 * al0 + sum0; l1 = l1 * al1 + sum1;
        m0 = mn0; m1 = mn1;
#pragma unroll
        for (int j = 0; j < 8; j++) {
            o[j][0] *= al0; o[j][1] *= al0;
            o[j][2] *= al1; o[j][3] *= al1;
        }

        // ---- O += Phi.Vhi (1 MMA; truncation noise averages out)
#pragma unroll
        for (int ks = 0; ks < 4; ks++) {
            int j0 = 2 * ks, j1 = 2 * ks + 1;
            uint32_t ph[4];
            ph[0] = pack2(s[j0][0], s[j0][1]);
            ph[1] = pack2(s[j0][2], s[j0][3]);
            ph[2] = pack2(s[j1][0], s[j1][1]);
            ph[3] = pack2(s[j1][2], s[j1][3]);
            uint32_t vrow = (uint32_t)((ks * 16 + (lane & 7) + ((lane >> 3) & 1) * 8) * 128 +
                                       ((lane >> 4) & 1) * 16);
#pragma unroll
            for (int np = 0; np < 4; np++) {
                uint32_t vo = SWZ(vrow + (uint32_t)(np * 32));
                uint32_t vh4[4];
                ldsm4t(vh4, cur + 8192u + vo);
#pragma unroll
                for (int half = 0; half < 2; half++) {
                    int j = np * 2 + half;
                    const uint32_t bvh[2] = {vh4[half * 2], vh4[half * 2 + 1]};
                    mma16816(o[j], ph, bvh);
                }
            }
        }
        __syncthreads();
    }

    // epilogue: normalize, store o hi/lo (proj needs full precision input)
    float inv0 = 1.f / l0, inv1 = 1.f / l1;
    int r0 = lane >> 2, cc = (lane & 3) * 2;
    int row0 = q0 + mb + r0, row1 = row0 + 8;
#pragma unroll
    for (int j = 0; j < 8; j++) {
        int col = h * DH_ + j * 8 + cc;
        size_t off0 = ((size_t)(b * HW_ + row0)) * C_ + col;
        size_t off1 = ((size_t)(b * HW_ + row1)) * C_ + col;
        uint32_t hi, lo;
        split2(o[j][0] * inv0, o[j][1] * inv0, hi, lo);
        *(uint32_t*)&ohi[off0] = hi; *(uint32_t*)&olo[off0] = lo;
        split2(o[j][2] * inv1, o[j][3] * inv1, hi, lo);
        *(uint32_t*)&ohi[off1] = hi; *(uint32_t*)&olo[off1] = lo;
    }
}

// ---------------- LayerNorm over C + residual + transpose (warp-reduced) ----
__global__ void ln_residual_kernel(const float* __restrict__ ob,
                                   const float* __restrict__ x,
                                   const float* __restrict__ g,
                                   const float* __restrict__ be,
                                   float* __restrict__ y) {
    int row = blockIdx.x;
    int b = row >> 10, n = row & 1023;
    const float* pr = ob + (size_t)row * C_;
    int tid = threadIdx.x, lane = tid & 31, wid = tid >> 5;
    float v0 = pr[tid], v1 = pr[tid + 256];
    __shared__ float red[8];
    __shared__ float bc[2];

    float s = v0 + v1;
#pragma unroll
    for (int off = 16; off; off >>= 1) s += __shfl_xor_sync(0xffffffffu, s, off);
    if (lane == 0) red[wid] = s;
    __syncthreads();
    if (tid == 0) {
        float t = 0.f;
#pragma unroll
        for (int i = 0; i < 8; i++) t += red[i];
        bc[0] = t * (1.0f / C_);
    }
    __syncthreads();
    float mean = bc[0];
    float d0 = v0 - mean, d1 = v1 - mean;
    s = d0 * d0 + d1 * d1;
#pragma unroll
    for (int off = 16; off; off >>= 1) s += __shfl_xor_sync(0xffffffffu, s, off);
    if (lane == 0) red[wid] = s;
    __syncthreads();
    if (tid == 0) {
        float t = 0.f;
#pragma unroll
        for (int i = 0; i < 8; i++) t += red[i];
        bc[1] = rsqrtf(t * (1.0f / C_) + 1e-5f);
    }
    __syncthreads();
    float rstd = bc[1];
    int c0 = tid, c1 = tid + 256;
    size_t i0 = ((size_t)b * C_ + c0) * HW_ + n;
    size_t i1 = ((size_t)b * C_ + c1) * HW_ + n;
    y[i0] = d0 * rstd * g[c0] + be[c0] + x[i0];
    y[i1] = d1 * rstd * g[c1] + be[c1] + x[i1];
}

// ---------------- fused depthwise 3x3 + transpose -> fp16 --------------------
__global__ void dwt_kernel(const float* __restrict__ y,
                           const float* __restrict__ w,
                           const float* __restrict__ bias,
                           h16* __restrict__ hi) {
    __shared__ float yt[32][3][33];
    __shared__ float ot[32][33];   // [w][c]
    int hh = blockIdx.x, c0 = blockIdx.y * 32, b = blockIdx.z;
    int tid = threadIdx.x;
    int c = tid >> 3, wg = (tid & 7) * 4;

#pragma unroll
    for (int r = 0; r < 3; r++) {
        int ih = hh + r - 1;
        float4 v = make_float4(0.f, 0.f, 0.f, 0.f);
        if (ih >= 0 && ih < H_)
            v = *(const float4*)&y[((size_t)(b * C_ + c0 + c)) * HW_ + ih * W_ + wg];
        yt[c][r][wg + 0] = v.x; yt[c][r][wg + 1] = v.y;
        yt[c][r][wg + 2] = v.z; yt[c][r][wg + 3] = v.w;
    }
    float wc[9];
#pragma unroll
    for (int i = 0; i < 9; i++) wc[i] = w[(c0 + c) * 9 + i];
    float bs = bias[c0 + c];
    __syncthreads();

#pragma unroll
    for (int j = 0; j < 4; j++) {
        int ww = wg + j;
        float acc = bs;
#pragma unroll
        for (int ki = 0; ki < 3; ki++)
#pragma unroll
            for (int kj = 0; kj < 3; kj++) {
                int iw = ww + kj - 1;
                if (iw >= 0 && iw < W_) acc += wc[ki * 3 + kj] * yt[c][ki][iw];
            }
        ot[ww][c] = acc;
    }
    __syncthreads();

    int w2 = tid >> 3, cg = (tid & 7) * 4;
    int token = hh * W_ + w2;
    size_t base = ((size_t)b * HW_ + token) * C_ + c0 + cg;
    *(uint32_t*)&hi[base]     = pack2(ot[w2][cg],     ot[w2][cg + 1]);
    *(uint32_t*)&hi[base + 2] = pack2(ot[w2][cg + 2], ot[w2][cg + 3]);
}

// ---------------- launch ------------------------------------------------------
extern "C" void kernel_launch(void* const* d_in, const int* in_sizes, int n_in,
                              void* d_out, int out_size) {
    const float* x      = (const float*)d_in[0];
    const float* qkv_w  = (const float*)d_in[1];
    const float* proj_w = (const float*)d_in[2];
    const float* proj_b = (const float*)d_in[3];
    const float* temper = (const float*)d_in[4];
    const float* ln_g   = (const float*)d_in[5];
    const float* ln_b   = (const float*)d_in[6];
    const float* pos    = (const float*)d_in[7];
    const float* dw_w   = (const float*)d_in[8];
    const float* dw_b   = (const float*)d_in[9];
    const float* pw_w   = (const float*)d_in[10];
    const float* pw_b   = (const float*)d_in[11];
    float* out = (float*)d_out;

    h16 *thi, *w1hi, *w1lo, *w2hi, *w2lo, *w3hi;
    h16 *ohi, *olo, *dThi, *qhi, *khi, *vhi;
    float *rs, *ob, *y, *psq, *psk;
    cudaGetSymbolAddress((void**)&thi,  g_thi);
    cudaGetSymbolAddress((void**)&w1hi, g_w1hi);
    cudaGetSymbolAddress((void**)&w1lo, g_w1lo);
    cudaGetSymbolAddress((void**)&w2hi, g_w2hi);
    cudaGetSymbolAddress((void**)&w2lo, g_w2lo);
    cudaGetSymbolAddress((void**)&w3hi, g_w3hi);
    cudaGetSymbolAddress((void**)&ohi,  g_ohi);
    cudaGetSymbolAddress((void**)&olo,  g_olo);
    cudaGetSymbolAddress((void**)&dThi, g_dThi);
    cudaGetSymbolAddress((void**)&qhi,  g_qhi);
    cudaGetSymbolAddress((void**)&khi,  g_khi);
    cudaGetSymbolAddress((void**)&vhi,  g_vhi);
    cudaGetSymbolAddress((void**)&rs,   g_rs);
    cudaGetSymbolAddress((void**)&psq,  g_psq);
    cudaGetSymbolAddress((void**)&psk,  g_psk);
    cudaGetSymbolAddress((void**)&ob,   g_ob);
    cudaGetSymbolAddress((void**)&y,    g_y);

    cudaFuncSetAttribute(fat_kernel,
                         cudaFuncAttributeMaxDynamicSharedMemorySize, FAT_SMEM);
    cudaFuncSetAttribute(gemm_tc,
                         cudaFuncAttributeMaxDynamicSharedMemorySize, GSMEM);

    // fused weight splits
    splitw_kernel<<<(NW1 + 2*NW2 + 255)/256, 256>>>(qkv_w, proj_w, pw_w);
    // t = transpose(x) + pos (fp16)
    build_t_kernel<<<dim3(HW_/32, C_/32, B_), dim3(32, 8)>>>(x, pos, thi);
    // qkv GEMM: q,k cols 1-term; v cols 2-term; fp16 head-major output
    gemm_tc<<<dim3(C3_/128, (B_*HW_)/128, 1), 256, GSMEM>>>(
        thi, thi, w1hi, w1lo, nullptr, nullptr, nullptr, C_, 0, 0, 0,
        1 /*mode=qkv*/, 1 /*ntLow*/, 2 /*ntHigh*/, 1024 /*v cols*/);
    // rs two-stage reduction
    rs1_kernel<<<B_*NH_*16, 256>>>(psq, psk);
    rs2_kernel<<<B_*NH_, 64>>>(psq, psk, temper, rs);
    // tensor-core fused attention -> o (hi/lo)
    fat_kernel<<<dim3(HW_/128, B_*NH_), 256, FAT_SMEM>>>(
        qhi, rs, khi, vhi, ohi, olo);
    // proj = o @ proj_w^T + proj_b (3-term: ~exact given o hi/lo)
    gemm_tc<<<dim3(C_/128, (B_*HW_)/128, 1), 256, GSMEM>>>(
        ohi, olo, w2hi, w2lo, proj_b, nullptr, ob, C_, C_, 0, 0,
        0, 3, 3, 0);
    // LN + residual + transpose to [B,C,HW]
    ln_residual_kernel<<<B_*HW_, 256>>>(ob, x, ln_g, ln_b, y);
    // fused depthwise 3x3 + transpose (fp16)
    dwt_kernel<<<dim3(H_, C_/32, B_), 256>>>(y, dw_w, dw_b, dThi);
    // pointwise (1-term) + bias + residual -> out
    gemm_tc<<<dim3(HW_/128, C_/128, B_), 256, GSMEM>>>(
        w3hi, w3hi, dThi, dThi, pw_b, y, out, C_, HW_,
        (long)HW_*C_, (long)C_*HW_, 0, 1, 1, 1 << 30);
}

// round 12
// speedup vs baseline: 1.7049x; 1.2077x over previous
#include <cuda_runtime.h>
#include <cuda_fp16.h>
#include <cstdint>

#define B_  8
#define C_  512
#define H_  32
#define W_  32
#define NH_ 8
#define DH_ 64
#define HW_ 1024
#define C3_ (3*C_)

typedef __half h16;

// ---------------- scratch (device globals; no allocation allowed) ----------
__device__ h16   g_thi[(size_t)B_*HW_*C_];
__device__ h16   g_w1hi[(size_t)C3_*C_];
__device__ h16   g_w2hi[(size_t)C_*C_];
__device__ h16   g_w2lo[(size_t)C_*C_];
__device__ h16   g_w3hi[(size_t)C_*C_];
__device__ float g_rs [(size_t)B_*NH_*DH_];
__device__ float g_psq[(size_t)B_*NH_*16*DH_];
__device__ float g_psk[(size_t)B_*NH_*16*DH_];
__device__ h16   g_qhi[(size_t)B_*NH_*HW_*DH_];
__device__ h16   g_khi[(size_t)B_*NH_*HW_*DH_];
__device__ h16   g_vhi[(size_t)B_*NH_*HW_*DH_];
__device__ h16   g_ohi[(size_t)B_*HW_*C_];
__device__ h16   g_olo[(size_t)B_*HW_*C_];
__device__ float g_ob [(size_t)B_*HW_*C_];
__device__ float g_y  [(size_t)B_*C_*HW_];
__device__ h16   g_dThi[(size_t)B_*HW_*C_];

// ---------------- small PTX helpers -----------------------------------------
__device__ __forceinline__ uint32_t smem_u32(const void* p) {
    uint32_t a;
    asm("{ .reg .u64 t; cvta.to.shared.u64 t, %1; cvt.u32.u64 %0, t; }"
        : "=r"(a) : "l"(p));
    return a;
}
__device__ __forceinline__ void cp16(uint32_t s, const void* g) {
    asm volatile("cp.async.cg.shared.global [%0], [%1], 16;" :: "r"(s), "l"(g));
}
#define SWZ(x) ((x) ^ (((x) >> 3) & 0x70u))

__device__ __forceinline__ void ldsm4(uint32_t* r, uint32_t addr) {
    asm volatile("ldmatrix.sync.aligned.m8n8.x4.shared.b16 {%0,%1,%2,%3}, [%4];"
                 : "=r"(r[0]), "=r"(r[1]), "=r"(r[2]), "=r"(r[3]) : "r"(addr));
}
__device__ __forceinline__ void ldsm4t(uint32_t* r, uint32_t addr) {
    asm volatile("ldmatrix.sync.aligned.m8n8.x4.trans.shared.b16 {%0,%1,%2,%3}, [%4];"
                 : "=r"(r[0]), "=r"(r[1]), "=r"(r[2]), "=r"(r[3]) : "r"(addr));
}
__device__ __forceinline__ void mma16816(float* c, const uint32_t* a,
                                         const uint32_t* b) {
    asm volatile(
        "mma.sync.aligned.m16n8k16.row.col.f32.f16.f16.f32 "
        "{%0,%1,%2,%3}, {%4,%5,%6,%7}, {%8,%9}, {%0,%1,%2,%3};"
        : "+f"(c[0]), "+f"(c[1]), "+f"(c[2]), "+f"(c[3])
        : "r"(a[0]), "r"(a[1]), "r"(a[2]), "r"(a[3]), "r"(b[0]), "r"(b[1]));
}
__device__ __forceinline__ void split2(float a, float b, uint32_t& hi, uint32_t& lo) {
    __half ha = __float2half(a), hb = __float2half(b);
    __half2 h; h.x = ha; h.y = hb;
    hi = *(uint32_t*)&h;
    __half2 l;
    l.x = __float2half(a - __half2float(ha));
    l.y = __float2half(b - __half2float(hb));
    lo = *(uint32_t*)&l;
}
__device__ __forceinline__ uint32_t pack2(float a, float b) {
    __half2 h; h.x = __float2half(a); h.y = __float2half(b);
    return *(uint32_t*)&h;
}

// ---------------- HMMA GEMM templated on split-term count --------------------
// NT=1: Ahi*Bhi.  NT=2: + Ahi*Blo.  NT=3: + Alo*Bhi (~fp32 exact).
// Stage buffers (16KB each): [Ahi][Bhi][Blo?][Alo?], stride (NT+1)*GTB.
#define GTB 16384u

template<int NT>
__device__ __forceinline__ void load_chunk(
    uint32_t dst, int tid, int m0, int n0, int K, int kc,
    const h16* __restrict__ Ahi, const h16* __restrict__ Alo,
    const h16* __restrict__ Bhi, const h16* __restrict__ Blo) {
#pragma unroll
    for (int it = 0; it < 4; it++) {
        int idx = it * 256 + tid;
        int r = idx >> 3, cg = idx & 7;
        uint32_t so = SWZ((uint32_t)(r * 128 + cg * 16));
        size_t ga = (size_t)(m0 + r) * K + kc + cg * 8;
        size_t gb = (size_t)(n0 + r) * K + kc + cg * 8;
        cp16(dst       + so, Ahi + ga);
        cp16(dst + GTB + so, Bhi + gb);
        if (NT >= 2) cp16(dst + 2u * GTB + so, Blo + gb);
        if (NT >= 3) cp16(dst + 3u * GTB + so, Alo + ga);
    }
    asm volatile("cp.async.commit_group;" ::: "memory");
}

template<int NT>
__global__ __launch_bounds__(256, (NT <= 2 ? 2 : 1))
void gemm_tc(const h16* __restrict__ Ahi, const h16* __restrict__ Alo,
             const h16* __restrict__ Bhi, const h16* __restrict__ Blo,
             const float* __restrict__ bias, const float* __restrict__ resid,
             float* __restrict__ Cout, int K, int Nld,
             long bBatch, long cBatch, int mode) {
    extern __shared__ char smc[];
    uint32_t sb = smem_u32(smc);
    int tid = threadIdx.x, wid = tid >> 5, lane = tid & 31;
    int m0 = blockIdx.y * 128, n0 = blockIdx.x * 128;
    const uint32_t SS = (NT + 1) * GTB;   // stage stride
    Bhi += (size_t)blockIdx.z * bBatch;
    if (NT >= 2) Blo += (size_t)blockIdx.z * bBatch;
    if (Cout) Cout += (size_t)blockIdx.z * cBatch;
    const float* res = resid ? resid + (size_t)blockIdx.z * cBatch : nullptr;

    float* bsm = (float*)smc;
    if (tid < 128) bsm[tid] = bias ? bias[n0 + tid] : 0.f;

    const uint32_t t0 = sb + 1024;
    const int nchunk = K >> 6;
    const int mb = (wid & 3) * 32;
    const int nb = (wid >> 2) * 64;

    float acc[2][8][4];
#pragma unroll
    for (int i = 0; i < 2; i++)
#pragma unroll
        for (int j = 0; j < 8; j++)
#pragma unroll
            for (int q = 0; q < 4; q++) acc[i][j][q] = 0.f;

    load_chunk<NT>(t0, tid, m0, n0, K, 0, Ahi, Alo, Bhi, Blo);
    for (int c = 0; c < nchunk; c++) {
        if (c + 1 < nchunk) {
            load_chunk<NT>(t0 + (uint32_t)((c + 1) & 1) * SS, tid, m0, n0, K,
                           (c + 1) << 6, Ahi, Alo, Bhi, Blo);
            asm volatile("cp.async.wait_group 1;" ::: "memory");
        } else {
            asm volatile("cp.async.wait_group 0;" ::: "memory");
        }
        __syncthreads();
        uint32_t bufA = t0 + (uint32_t)(c & 1) * SS;
#pragma unroll
        for (int ks = 0; ks < 4; ks++) {
            int kb = ks * 32;
            uint32_t ao = SWZ((uint32_t)((mb + (lane & 15)) * 128 +
                                         (lane >> 4) * 16 + kb));
            uint32_t ahi[4], alo[4];
            ldsm4(ahi, bufA + ao);
            if (NT >= 3) ldsm4(alo, bufA + 3u * GTB + ao);
            uint32_t ao2 = SWZ((uint32_t)((mb + 16 + (lane & 15)) * 128 +
                                          (lane >> 4) * 16 + kb));
            uint32_t ahi2[4], alo2[4];
            ldsm4(ahi2, bufA + ao2);
            if (NT >= 3) ldsm4(alo2, bufA + 3u * GTB + ao2);
            uint32_t brow = (uint32_t)((nb + (lane & 7) + ((lane >> 4) & 1) * 8) * 128 +
                                       ((lane >> 3) & 1) * 16 + kb);
#pragma unroll
            for (int ntp = 0; ntp < 4; ntp++) {
                uint32_t bo = SWZ(brow + (uint32_t)(ntp * 16 * 128));
                uint32_t bhi[4], blo[4];
                ldsm4(bhi, bufA + GTB + bo);
                if (NT >= 2) ldsm4(blo, bufA + 2u * GTB + bo);
#pragma unroll
                for (int half = 0; half < 2; half++) {
                    int ntile = ntp * 2 + half;
                    const uint32_t bh[2] = {bhi[half * 2], bhi[half * 2 + 1]};
                    mma16816(acc[0][ntile], ahi, bh);
                    mma16816(acc[1][ntile], ahi2, bh);
                    if (NT >= 2) {
                        const uint32_t bl[2] = {blo[half * 2], blo[half * 2 + 1]};
                        mma16816(acc[0][ntile], ahi, bl);
                        mma16816(acc[1][ntile], ahi2, bl);
                    }
                    if (NT >= 3) {
                        mma16816(acc[0][ntile], alo, bh);
                        mma16816(acc[1][ntile], alo2, bh);
                    }
                }
            }
        }
        __syncthreads();
    }

    int rbase = m0 + mb + (lane >> 2);
    int cbase = nb + (lane & 3) * 2;
#pragma unroll
    for (int mt = 0; mt < 2; mt++) {
#pragma unroll
        for (int ntile = 0; ntile < 8; ntile++) {
            int ncol = cbase + ntile * 8;
            int gcol = n0 + ncol;
#pragma unroll
            for (int rr = 0; rr < 2; rr++) {
                int row = rbase + mt * 16 + rr * 8;
                float v0 = acc[mt][ntile][rr * 2 + 0];
                float v1 = acc[mt][ntile][rr * 2 + 1];
                if (mode == 0) {
                    v0 += bsm[ncol]; v1 += bsm[ncol + 1];
                    size_t idx = (size_t)row * Nld + gcol;
                    if (res) {
                        float2 q = *(const float2*)(res + idx);
                        v0 += q.x; v1 += q.y;
                    }
                    float2 o; o.x = v0; o.y = v1;
                    *(float2*)(Cout + idx) = o;
                } else {
                    // qkv output: [bh][token][64] head-major, fp16 hi only
                    int b = row >> 10, tok = row & 1023;
                    int region = gcol >> 9;        // 0=q 1=k 2=v
                    int hd = gcol & 511;
                    int h = hd >> 6, d = hd & 63;
                    size_t dst = (((size_t)(b * NH_ + h) * HW_) + tok) * DH_ + d;
                    h16* ph = (region == 0) ? g_qhi : (region == 1) ? g_khi : g_vhi;
                    *(uint32_t*)&ph[dst] = pack2(v0, v1);
                }
            }
        }
    }
}

#define GS1 (1024 + 2 * 2 * 16384)
#define GS3 (1024 + 2 * 4 * 16384)

// ---------------- 1) t = transpose(x) + pos -> fp16 -------------------------
__global__ void build_t_kernel(const float* __restrict__ x,
                               const float* __restrict__ pos,
                               h16* __restrict__ thi) {
    __shared__ float tile[32][33];
    int b  = blockIdx.z;
    int n0 = blockIdx.x * 32;
    int c0 = blockIdx.y * 32;
    int tx = threadIdx.x, ty = threadIdx.y;
#pragma unroll
    for (int i = 0; i < 4; i++) {
        int c = c0 + ty + i * 8;
        tile[ty + i * 8][tx] = x[((size_t)b * C_ + c) * HW_ + n0 + tx];
    }
    __syncthreads();
#pragma unroll
    for (int i = 0; i < 4; i++) {
        int n = n0 + ty + i * 8;
        int c = c0 + tx;
        float v = tile[tx][ty + i * 8] + pos[(size_t)n * C_ + c];
        thi[((size_t)b * HW_ + n) * C_ + c] = __float2half(v);
    }
}

// ---------------- fused weight splits ----------------------------------------
// w1: hi only (qkv 1-term). w2: hi+lo (proj 3-term). w3: hi only.
#define NW1 (C3_*C_)
#define NW2 (C_*C_)
__global__ void splitw_kernel(const float* __restrict__ w1,
                              const float* __restrict__ w2,
                              const float* __restrict__ w3) {
    int i = blockIdx.x * 256 + threadIdx.x;
    if (i < NW1) {
        g_w1hi[i] = __float2half(w1[i]);
    } else if (i < NW1 + NW2) {
        int idx = i - NW1;
        float v = w2[idx];
        __half h = __float2half(v);
        g_w2hi[idx] = h;
        g_w2lo[idx] = __float2half(v - __half2float(h));
    } else if (i < NW1 + 2 * NW2) {
        int idx = i - NW1 - NW2;
        g_w3hi[idx] = __float2half(w3[idx]);
    }
}

// ---------------- rs two-stage reduction (half2-vectorized) ------------------
__global__ void rs1_kernel(float* __restrict__ psq, float* __restrict__ psk) {
    int bx = blockIdx.x;
    int bh = bx >> 4, part = bx & 15;
    int tid = threadIdx.x;
    int d2 = (tid & 31) * 2;
    int sub = tid >> 5;               // 0..7, each covers 8 tokens
    size_t base = (size_t)bh * HW_ * DH_ + d2;
    int n0 = part * 64 + sub * 8;
    float sq0 = 0.f, sq1 = 0.f, sk0 = 0.f, sk1 = 0.f;
#pragma unroll
    for (int n = 0; n < 8; n++) {
        size_t off = base + (size_t)(n0 + n) * DH_;
        __half2 q2 = *(const __half2*)&g_qhi[off];
        __half2 k2 = *(const __half2*)&g_khi[off];
        float qa = __half2float(q2.x), qb = __half2float(q2.y);
        float ka = __half2float(k2.x), kb = __half2float(k2.y);
        sq0 += qa * qa; sq1 += qb * qb;
        sk0 += ka * ka; sk1 += kb * kb;
    }
    __shared__ float smq[8][64], smk[8][64];
    smq[sub][d2] = sq0; smq[sub][d2 + 1] = sq1;
    smk[sub][d2] = sk0; smk[sub][d2 + 1] = sk1;
    __syncthreads();
    if (tid < 64) {
        float q = 0.f, k = 0.f;
#pragma unroll
        for (int s = 0; s < 8; s++) { q += smq[s][tid]; k += smk[s][tid]; }
        psq[((size_t)bh * 16 + part) * 64 + tid] = q;
        psk[((size_t)bh * 16 + part) * 64 + tid] = k;
    }
}

__global__ void rs2_kernel(const float* __restrict__ psq,
                           const float* __restrict__ psk,
                           const float* __restrict__ temp,
                           float* __restrict__ rs) {
    int bh = blockIdx.x, d = threadIdx.x;
    int h = bh % NH_;
    float q = 0.f, k = 0.f;
#pragma unroll
    for (int p = 0; p < 16; p++) {
        q += psq[((size_t)bh * 16 + p) * 64 + d];
        k += psk[((size_t)bh * 16 + p) * 64 + d];
    }
    float qn = fmaxf(sqrtf(q), 1e-12f);
    float kn = fmaxf(sqrtf(k), 1e-12f);
    rs[(size_t)bh * DH_ + d] = temp[h] / (qn * kn);
}

// ---------------- tensor-core fused flash attention --------------------------
// S = Qhi.Khi (1 MMA). O = Phi.Vhi (1 MMA). o stored hi/lo for exact proj.
#define FAT_STAGE 16384u
#define FAT_QOFF  32768u
#define FAT_SMEM  (32768 + 16384 + 256)

__device__ __forceinline__ void fat_loadkv(
    uint32_t buf, int tid, size_t kvbase, int kc,
    const h16* __restrict__ khi, const h16* __restrict__ vhi) {
#pragma unroll
    for (int it = 0; it < 2; it++) {
        int idx = it * 256 + tid;
        int r = idx >> 3, cg = idx & 7;
        uint32_t so = SWZ((uint32_t)(r * 128 + cg * 16));
        size_t g = kvbase + (size_t)(kc + r) * DH_ + cg * 8;
        cp16(buf +    0u + so, khi + g);
        cp16(buf + 8192u + so, vhi + g);
    }
    asm volatile("cp.async.commit_group;" ::: "memory");
}

__global__ __launch_bounds__(256, 2)
void fat_kernel(const h16* __restrict__ qhi,
                const float* __restrict__ rs,
                const h16* __restrict__ khi, const h16* __restrict__ vhi,
                h16* __restrict__ ohi, h16* __restrict__ olo) {
    extern __shared__ char smc[];
    uint32_t sb = smem_u32(smc);
    float* rss = (float*)(smc + FAT_QOFF + 16384);
    int bh = blockIdx.y;
    int b = bh >> 3, h = bh & 7;
    int q0 = blockIdx.x * 128;
    int tid = threadIdx.x, wid = tid >> 5, lane = tid & 31;
    int mb = wid * 16;

    if (tid < 64) rss[tid] = rs[bh * DH_ + tid];
    __syncthreads();

#pragma unroll
    for (int v = 0; v < 8; v++) {
        int idx = v * 256 + tid;
        int row = idx >> 4, dq = (idx & 15) * 4;
        size_t qoff = ((size_t)bh * HW_ + q0 + row) * DH_ + dq;
        __half2 ha = *(const __half2*)&qhi[qoff];
        __half2 hb = *(const __half2*)&qhi[qoff + 2];
        float qx = __half2float(ha.x) * rss[dq];
        float qy = __half2float(ha.y) * rss[dq + 1];
        float qz = __half2float(hb.x) * rss[dq + 2];
        float qw = __half2float(hb.y) * rss[dq + 3];
        uint32_t off = SWZ((uint32_t)(row * 128 + dq * 2));
        *(uint32_t*)(smc + FAT_QOFF + off)     = pack2(qx, qy);
        *(uint32_t*)(smc + FAT_QOFF + off + 4) = pack2(qz, qw);
    }
    __syncthreads();

    float o[8][4];
#pragma unroll
    for (int j = 0; j < 8; j++)
#pragma unroll
        for (int q = 0; q < 4; q++) o[j][q] = 0.f;
    float m0 = -1e30f, m1 = -1e30f, l0 = 0.f, l1 = 0.f;
    const size_t kvbase = (size_t)bh * HW_ * DH_;

    fat_loadkv(sb, tid, kvbase, 0, khi, vhi);
    for (int kt = 0; kt < 16; kt++) {
        uint32_t cur = sb + (uint32_t)(kt & 1) * FAT_STAGE;
        if (kt + 1 < 16) {
            fat_loadkv(sb + (uint32_t)((kt + 1) & 1) * FAT_STAGE, tid, kvbase,
                       (kt + 1) * 64, khi, vhi);
            asm volatile("cp.async.wait_group 1;" ::: "memory");
        } else {
            asm volatile("cp.async.wait_group 0;" ::: "memory");
        }
        __syncthreads();

        float s[8][4];
#pragma unroll
        for (int j = 0; j < 8; j++)
#pragma unroll
            for (int q = 0; q < 4; q++) s[j][q] = 0.f;
#pragma unroll
        for (int ks = 0; ks < 4; ks++) {
            uint32_t qao = SWZ((uint32_t)((mb + (lane & 15)) * 128 +
                                          (lane >> 4) * 16 + ks * 32));
            uint32_t qh4[4];
            ldsm4(qh4, sb + FAT_QOFF + qao);
            uint32_t brow = (uint32_t)(((lane & 7) + ((lane >> 4) & 1) * 8) * 128 +
                                       ((lane >> 3) & 1) * 16 + ks * 32);
#pragma unroll
            for (int np = 0; np < 4; np++) {
                uint32_t bo = SWZ(brow + (uint32_t)(np * 16 * 128));
                uint32_t kh4[4];
                ldsm4(kh4, cur + bo);
#pragma unroll
                for (int half = 0; half < 2; half++) {
                    int j = np * 2 + half;
                    const uint32_t bhh[2] = {kh4[half * 2], kh4[half * 2 + 1]};
                    mma16816(s[j], qh4, bhh);
                }
            }
        }

        float mx0 = -1e30f, mx1 = -1e30f;
#pragma unroll
        for (int j = 0; j < 8; j++) {
            mx0 = fmaxf(mx0, fmaxf(s[j][0], s[j][1]));
            mx1 = fmaxf(mx1, fmaxf(s[j][2], s[j][3]));
        }
        mx0 = fmaxf(mx0, __shfl_xor_sync(0xffffffffu, mx0, 1));
        mx0 = fmaxf(mx0, __shfl_xor_sync(0xffffffffu, mx0, 2));
        mx1 = fmaxf(mx1, __shfl_xor_sync(0xffffffffu, mx1, 1));
        mx1 = fmaxf(mx1, __shfl_xor_sync(0xffffffffu, mx1, 2));
        float mn0 = fmaxf(m0, mx0), mn1 = fmaxf(m1, mx1);
        float al0 = __expf(m0 - mn0), al1 = __expf(m1 - mn1);
        float sum0 = 0.f, sum1 = 0.f;
#pragma unroll
        for (int j = 0; j < 8; j++) {
            s[j][0] = __expf(s[j][0] - mn0);
            s[j][1] = __expf(s[j][1] - mn0);
            s[j][2] = __expf(s[j][2] - mn1);
            s[j][3] = __expf(s[j][3] - mn1);
            sum0 += s[j][0] + s[j][1];
            sum1 += s[j][2] + s[j][3];
        }
        sum0 += __shfl_xor_sync(0xffffffffu, sum0, 1);
        sum0 += __shfl_xor_sync(0xffffffffu, sum0, 2);
        sum1 += __shfl_xor_sync(0xffffffffu, sum1, 1);
        sum1 += __shfl_xor_sync(0xffffffffu, sum1, 2);
        l0 = l0 * al0 + sum0; l1 = l1 * al1 + sum1;
        m0 = mn0; m1 = mn1;
#pragma unroll
        for (int j = 0; j < 8; j++) {
            o[j][0] *= al0; o[j][1] *= al0;
            o[j][2] *= al1; o[j][3] *= al1;
        }

#pragma unroll
        for (int ks = 0; ks < 4; ks++) {
            int j0 = 2 * ks, j1 = 2 * ks + 1;
            uint32_t ph[4];
            ph[0] = pack2(s[j0][0], s[j0][1]);
            ph[1] = pack2(s[j0][2], s[j0][3]);
            ph[2] = pack2(s[j1][0], s[j1][1]);
            ph[3] = pack2(s[j1][2], s[j1][3]);
            uint32_t vrow = (uint32_t)((ks * 16 + (lane & 7) + ((lane >> 3) & 1) * 8) * 128 +
                                       ((lane >> 4) & 1) * 16);
#pragma unroll
            for (int np = 0; np < 4; np++) {
                uint32_t vo = SWZ(vrow + (uint32_t)(np * 32));
                uint32_t vh4[4];
                ldsm4t(vh4, cur + 8192u + vo);
#pragma unroll
                for (int half = 0; half < 2; half++) {
                    int j = np * 2 + half;
                    const uint32_t bvh[2] = {vh4[half * 2], vh4[half * 2 + 1]};
                    mma16816(o[j], ph, bvh);
                }
            }
        }
        __syncthreads();
    }

    float inv0 = 1.f / l0, inv1 = 1.f / l1;
    int r0 = lane >> 2, cc = (lane & 3) * 2;
    int row0 = q0 + mb + r0, row1 = row0 + 8;
#pragma unroll
    for (int j = 0; j < 8; j++) {
        int col = h * DH_ + j * 8 + cc;
        size_t off0 = ((size_t)(b * HW_ + row0)) * C_ + col;
        size_t off1 = ((size_t)(b * HW_ + row1)) * C_ + col;
        uint32_t hi, lo;
        split2(o[j][0] * inv0, o[j][1] * inv0, hi, lo);
        *(uint32_t*)&ohi[off0] = hi; *(uint32_t*)&olo[off0] = lo;
        split2(o[j][2] * inv1, o[j][3] * inv1, hi, lo);
        *(uint32_t*)&ohi[off1] = hi; *(uint32_t*)&olo[off1] = lo;
    }
}

// ---------------- LayerNorm over C + residual + transpose (warp-reduced) ----
__global__ void ln_residual_kernel(const float* __restrict__ ob,
                                   const float* __restrict__ x,
                                   const float* __restrict__ g,
                                   const float* __restrict__ be,
                                   float* __restrict__ y) {
    int row = blockIdx.x;
    int b = row >> 10, n = row & 1023;
    const float* pr = ob + (size_t)row * C_;
    int tid = threadIdx.x, lane = tid & 31, wid = tid >> 5;
    float v0 = pr[tid], v1 = pr[tid + 256];
    __shared__ float red[8];
    __shared__ float bc[2];

    float s = v0 + v1;
#pragma unroll
    for (int off = 16; off; off >>= 1) s += __shfl_xor_sync(0xffffffffu, s, off);
    if (lane == 0) red[wid] = s;
    __syncthreads();
    if (tid == 0) {
        float t = 0.f;
#pragma unroll
        for (int i = 0; i < 8; i++) t += red[i];
        bc[0] = t * (1.0f / C_);
    }
    __syncthreads();
    float mean = bc[0];
    float d0 = v0 - mean, d1 = v1 - mean;
    s = d0 * d0 + d1 * d1;
#pragma unroll
    for (int off = 16; off; off >>= 1) s += __shfl_xor_sync(0xffffffffu, s, off);
    if (lane == 0) red[wid] = s;
    __syncthreads();
    if (tid == 0) {
        float t = 0.f;
#pragma unroll
        for (int i = 0; i < 8; i++) t += red[i];
        bc[1] = rsqrtf(t * (1.0f / C_) + 1e-5f);
    }
    __syncthreads();
    float rstd = bc[1];
    int c0 = tid, c1 = tid + 256;
    size_t i0 = ((size_t)b * C_ + c0) * HW_ + n;
    size_t i1 = ((size_t)b * C_ + c1) * HW_ + n;
    y[i0] = d0 * rstd * g[c0] + be[c0] + x[i0];
    y[i1] = d1 * rstd * g[c1] + be[c1] + x[i1];
}

// ---------------- fused depthwise 3x3 + transpose -> fp16 --------------------
__global__ void dwt_kernel(const float* __restrict__ y,
                           const float* __restrict__ w,
                           const float* __restrict__ bias,
                           h16* __restrict__ hi) {
    __shared__ float yt[32][3][33];
    __shared__ float ot[32][33];   // [w][c]
    int hh = blockIdx.x, c0 = blockIdx.y * 32, b = blockIdx.z;
    int tid = threadIdx.x;
    int c = tid >> 3, wg = (tid & 7) * 4;

#pragma unroll
    for (int r = 0; r < 3; r++) {
        int ih = hh + r - 1;
        float4 v = make_float4(0.f, 0.f, 0.f, 0.f);
        if (ih >= 0 && ih < H_)
            v = *(const float4*)&y[((size_t)(b * C_ + c0 + c)) * HW_ + ih * W_ + wg];
        yt[c][r][wg + 0] = v.x; yt[c][r][wg + 1] = v.y;
        yt[c][r][wg + 2] = v.z; yt[c][r][wg + 3] = v.w;
    }
    float wc[9];
#pragma unroll
    for (int i = 0; i < 9; i++) wc[i] = w[(c0 + c) * 9 + i];
    float bs = bias[c0 + c];
    __syncthreads();

#pragma unroll
    for (int j = 0; j < 4; j++) {
        int ww = wg + j;
        float acc = bs;
#pragma unroll
        for (int ki = 0; ki < 3; ki++)
#pragma unroll
            for (int kj = 0; kj < 3; kj++) {
                int iw = ww + kj - 1;
                if (iw >= 0 && iw < W_) acc += wc[ki * 3 + kj] * yt[c][ki][iw];
            }
        ot[ww][c] = acc;
    }
    __syncthreads();

    int w2 = tid >> 3, cg = (tid & 7) * 4;
    int token = hh * W_ + w2;
    size_t base = ((size_t)b * HW_ + token) * C_ + c0 + cg;
    *(uint32_t*)&hi[base]     = pack2(ot[w2][cg],     ot[w2][cg + 1]);
    *(uint32_t*)&hi[base + 2] = pack2(ot[w2][cg + 2], ot[w2][cg + 3]);
}

// ---------------- launch ------------------------------------------------------
extern "C" void kernel_launch(void* const* d_in, const int* in_sizes, int n_in,
                              void* d_out, int out_size) {
    const float* x      = (const float*)d_in[0];
    const float* qkv_w  = (const float*)d_in[1];
    const float* proj_w = (const float*)d_in[2];
    const float* proj_b = (const float*)d_in[3];
    const float* temper = (const float*)d_in[4];
    const float* ln_g   = (const float*)d_in[5];
    const float* ln_b   = (const float*)d_in[6];
    const float* pos    = (const float*)d_in[7];
    const float* dw_w   = (const float*)d_in[8];
    const float* dw_b   = (const float*)d_in[9];
    const float* pw_w   = (const float*)d_in[10];
    const float* pw_b   = (const float*)d_in[11];
    float* out = (float*)d_out;

    h16 *thi, *w1hi, *w2hi, *w2lo, *w3hi;
    h16 *ohi, *olo, *dThi, *qhi, *khi, *vhi;
    float *rs, *ob, *y, *psq, *psk;
    cudaGetSymbolAddress((void**)&thi,  g_thi);
    cudaGetSymbolAddress((void**)&w1hi, g_w1hi);
    cudaGetSymbolAddress((void**)&w2hi, g_w2hi);
    cudaGetSymbolAddress((void**)&w2lo, g_w2lo);
    cudaGetSymbolAddress((void**)&w3hi, g_w3hi);
    cudaGetSymbolAddress((void**)&ohi,  g_ohi);
    cudaGetSymbolAddress((void**)&olo,  g_olo);
    cudaGetSymbolAddress((void**)&dThi, g_dThi);
    cudaGetSymbolAddress((void**)&qhi,  g_qhi);
    cudaGetSymbolAddress((void**)&khi,  g_khi);
    cudaGetSymbolAddress((void**)&vhi,  g_vhi);
    cudaGetSymbolAddress((void**)&rs,   g_rs);
    cudaGetSymbolAddress((void**)&psq,  g_psq);
    cudaGetSymbolAddress((void**)&psk,  g_psk);
    cudaGetSymbolAddress((void**)&ob,   g_ob);
    cudaGetSymbolAddress((void**)&y,    g_y);

    cudaFuncSetAttribute(fat_kernel,
                         cudaFuncAttributeMaxDynamicSharedMemorySize, FAT_SMEM);
    cudaFuncSetAttribute(gemm_tc<1>,
                         cudaFuncAttributeMaxDynamicSharedMemorySize, GS1);
    cudaFuncSetAttribute(gemm_tc<3>,
                         cudaFuncAttributeMaxDynamicSharedMemorySize, GS3);

    // fused weight splits
    splitw_kernel<<<(NW1 + 2*NW2 + 255)/256, 256>>>(qkv_w, proj_w, pw_w);
    // t = transpose(x) + pos (fp16)
    build_t_kernel<<<dim3(HW_/32, C_/32, B_), dim3(32, 8)>>>(x, pos, thi);
    // qkv GEMM: uniform 1-term fp16, head-major split output (occ 2)
    gemm_tc<1><<<dim3(C3_/128, (B_*HW_)/128, 1), 256, GS1>>>(
        thi, nullptr, w1hi, nullptr, nullptr, nullptr, nullptr, C_, 0, 0, 0, 1);
    // rs two-stage reduction
    rs1_kernel<<<B_*NH_*16, 256>>>(psq, psk);
    rs2_kernel<<<B_*NH_, 64>>>(psq, psk, temper, rs);
    // tensor-core fused attention -> o (hi/lo)
    fat_kernel<<<dim3(HW_/128, B_*NH_), 256, FAT_SMEM>>>(
        qhi, rs, khi, vhi, ohi, olo);
    // proj = o @ proj_w^T + proj_b (3-term ~exact, occ 1)
    gemm_tc<3><<<dim3(C_/128, (B_*HW_)/128, 1), 256, GS3>>>(
        ohi, olo, w2hi, w2lo, proj_b, nullptr, ob, C_, C_, 0, 0, 0);
    // LN + residual + transpose to [B,C,HW]
    ln_residual_kernel<<<B_*HW_, 256>>>(ob, x, ln_g, ln_b, y);
    // fused depthwise 3x3 + transpose (fp16)
    dwt_kernel<<<dim3(H_, C_/32, B_), 256>>>(y, dw_w, dw_b, dThi);
    // pointwise (1-term, occ 2) + bias + residual -> out
    gemm_tc<1><<<dim3(HW_/128, C_/128, B_), 256, GS1>>>(
        w3hi, nullptr, dThi, nullptr, pw_b, y, out, C_, HW_,
        (long)HW_*C_, (long)C_*HW_, 0);
}

// round 13
// speedup vs baseline: 1.8522x; 1.0864x over previous
#include <cuda_runtime.h>
#include <cuda_fp16.h>
#include <cstdint>

#define B_  8
#define C_  512
#define H_  32
#define W_  32
#define NH_ 8
#define DH_ 64
#define HW_ 1024
#define C3_ (3*C_)

typedef __half h16;

// ---------------- scratch (device globals; no allocation allowed) ----------
__device__ h16   g_thi[(size_t)B_*HW_*C_];
__device__ h16   g_w1hi[(size_t)C3_*C_];
__device__ h16   g_w2hi[(size_t)C_*C_];
__device__ h16   g_w3hi[(size_t)C_*C_];
__device__ float g_rs [(size_t)B_*NH_*DH_];
__device__ float g_psq[(size_t)B_*NH_*16*DH_];
__device__ float g_psk[(size_t)B_*NH_*16*DH_];
__device__ h16   g_qhi[(size_t)B_*NH_*HW_*DH_];
__device__ h16   g_khi[(size_t)B_*NH_*HW_*DH_];
__device__ h16   g_vhi[(size_t)B_*NH_*HW_*DH_];
__device__ h16   g_ohi[(size_t)B_*HW_*C_];
__device__ h16   g_olo[(size_t)B_*HW_*C_];
__device__ float g_ob [(size_t)B_*HW_*C_];
__device__ float g_y  [(size_t)B_*C_*HW_];
__device__ h16   g_dThi[(size_t)B_*HW_*C_];

// ---------------- small PTX helpers -----------------------------------------
__device__ __forceinline__ uint32_t smem_u32(const void* p) {
    uint32_t a;
    asm("{ .reg .u64 t; cvta.to.shared.u64 t, %1; cvt.u32.u64 %0, t; }"
        : "=r"(a) : "l"(p));
    return a;
}
__device__ __forceinline__ void cp16(uint32_t s, const void* g) {
    asm volatile("cp.async.cg.shared.global [%0], [%1], 16;" :: "r"(s), "l"(g));
}
#define SWZ(x) ((x) ^ (((x) >> 3) & 0x70u))

__device__ __forceinline__ void ldsm4(uint32_t* r, uint32_t addr) {
    asm volatile("ldmatrix.sync.aligned.m8n8.x4.shared.b16 {%0,%1,%2,%3}, [%4];"
                 : "=r"(r[0]), "=r"(r[1]), "=r"(r[2]), "=r"(r[3]) : "r"(addr));
}
__device__ __forceinline__ void ldsm4t(uint32_t* r, uint32_t addr) {
    asm volatile("ldmatrix.sync.aligned.m8n8.x4.trans.shared.b16 {%0,%1,%2,%3}, [%4];"
                 : "=r"(r[0]), "=r"(r[1]), "=r"(r[2]), "=r"(r[3]) : "r"(addr));
}
__device__ __forceinline__ void mma16816(float* c, const uint32_t* a,
                                         const uint32_t* b) {
    asm volatile(
        "mma.sync.aligned.m16n8k16.row.col.f32.f16.f16.f32 "
        "{%0,%1,%2,%3}, {%4,%5,%6,%7}, {%8,%9}, {%0,%1,%2,%3};"
        : "+f"(c[0]), "+f"(c[1]), "+f"(c[2]), "+f"(c[3])
        : "r"(a[0]), "r"(a[1]), "r"(a[2]), "r"(a[3]), "r"(b[0]), "r"(b[1]));
}
__device__ __forceinline__ void split2(float a, float b, uint32_t& hi, uint32_t& lo) {
    __half ha = __float2half(a), hb = __float2half(b);
    __half2 h; h.x = ha; h.y = hb;
    hi = *(uint32_t*)&h;
    __half2 l;
    l.x = __float2half(a - __half2float(ha));
    l.y = __float2half(b - __half2float(hb));
    lo = *(uint32_t*)&l;
}
__device__ __forceinline__ uint32_t pack2(float a, float b) {
    __half2 h; h.x = __float2half(a); h.y = __float2half(b);
    return *(uint32_t*)&h;
}

// ---------------- HMMA GEMM templated on split mode ---------------------------
// NT=1: Ahi*Bhi.                 stages: [Ahi][Bhi]        stride 2*GTB, occ2
// NT=3: + Ahi*Blo + Alo*Bhi.     stages: [Ahi][Bhi][Blo][Alo], occ1 (unused now)
// NT=4: (Ahi+Alo)*Bhi (2 MMAs).  stages: [Ahi][Bhi][Alo]   stride 3*GTB, occ2
#define GTB 16384u

template<int NT>
__device__ __forceinline__ void load_chunk(
    uint32_t dst, int tid, int m0, int n0, int K, int kc,
    const h16* __restrict__ Ahi, const h16* __restrict__ Alo,
    const h16* __restrict__ Bhi, const h16* __restrict__ Blo) {
#pragma unroll
    for (int it = 0; it < 4; it++) {
        int idx = it * 256 + tid;
        int r = idx >> 3, cg = idx & 7;
        uint32_t so = SWZ((uint32_t)(r * 128 + cg * 16));
        size_t ga = (size_t)(m0 + r) * K + kc + cg * 8;
        size_t gb = (size_t)(n0 + r) * K + kc + cg * 8;
        cp16(dst       + so, Ahi + ga);
        cp16(dst + GTB + so, Bhi + gb);
        if (NT == 3) cp16(dst + 2u * GTB + so, Blo + gb);
        if (NT == 3) cp16(dst + 3u * GTB + so, Alo + ga);
        if (NT == 4) cp16(dst + 2u * GTB + so, Alo + ga);
    }
    asm volatile("cp.async.commit_group;" ::: "memory");
}

template<int NT>
__global__ __launch_bounds__(256, (NT == 3 ? 1 : 2))
void gemm_tc(const h16* __restrict__ Ahi, const h16* __restrict__ Alo,
             const h16* __restrict__ Bhi, const h16* __restrict__ Blo,
             const float* __restrict__ bias, const float* __restrict__ resid,
             float* __restrict__ Cout, int K, int Nld,
             long bBatch, long cBatch, int mode) {
    extern __shared__ char smc[];
    uint32_t sb = smem_u32(smc);
    int tid = threadIdx.x, wid = tid >> 5, lane = tid & 31;
    int m0 = blockIdx.y * 128, n0 = blockIdx.x * 128;
    const uint32_t SS = (NT == 1 ? 2u : NT == 4 ? 3u : 4u) * GTB;
    Bhi += (size_t)blockIdx.z * bBatch;
    if (NT == 3) Blo += (size_t)blockIdx.z * bBatch;
    if (Cout) Cout += (size_t)blockIdx.z * cBatch;
    const float* res = resid ? resid + (size_t)blockIdx.z * cBatch : nullptr;

    float* bsm = (float*)smc;
    if (tid < 128) bsm[tid] = bias ? bias[n0 + tid] : 0.f;

    const uint32_t t0 = sb + 1024;
    const int nchunk = K >> 6;
    const int mb = (wid & 3) * 32;
    const int nb = (wid >> 2) * 64;

    float acc[2][8][4];
#pragma unroll
    for (int i = 0; i < 2; i++)
#pragma unroll
        for (int j = 0; j < 8; j++)
#pragma unroll
            for (int q = 0; q < 4; q++) acc[i][j][q] = 0.f;

    load_chunk<NT>(t0, tid, m0, n0, K, 0, Ahi, Alo, Bhi, Blo);
    for (int c = 0; c < nchunk; c++) {
        if (c + 1 < nchunk) {
            load_chunk<NT>(t0 + (uint32_t)((c + 1) & 1) * SS, tid, m0, n0, K,
                           (c + 1) << 6, Ahi, Alo, Bhi, Blo);
            asm volatile("cp.async.wait_group 1;" ::: "memory");
        } else {
            asm volatile("cp.async.wait_group 0;" ::: "memory");
        }
        __syncthreads();
        uint32_t bufA = t0 + (uint32_t)(c & 1) * SS;
        const uint32_t aloOff = (NT == 4) ? 2u * GTB : 3u * GTB;
#pragma unroll
        for (int ks = 0; ks < 4; ks++) {
            int kb = ks * 32;
            uint32_t ao = SWZ((uint32_t)((mb + (lane & 15)) * 128 +
                                         (lane >> 4) * 16 + kb));
            uint32_t ahi[4], alo[4];
            ldsm4(ahi, bufA + ao);
            if (NT >= 3) ldsm4(alo, bufA + aloOff + ao);
            uint32_t ao2 = SWZ((uint32_t)((mb + 16 + (lane & 15)) * 128 +
                                          (lane >> 4) * 16 + kb));
            uint32_t ahi2[4], alo2[4];
            ldsm4(ahi2, bufA + ao2);
            if (NT >= 3) ldsm4(alo2, bufA + aloOff + ao2);
            uint32_t brow = (uint32_t)((nb + (lane & 7) + ((lane >> 4) & 1) * 8) * 128 +
                                       ((lane >> 3) & 1) * 16 + kb);
#pragma unroll
            for (int ntp = 0; ntp < 4; ntp++) {
                uint32_t bo = SWZ(brow + (uint32_t)(ntp * 16 * 128));
                uint32_t bhi[4], blo[4];
                ldsm4(bhi, bufA + GTB + bo);
                if (NT == 3) ldsm4(blo, bufA + 2u * GTB + bo);
#pragma unroll
                for (int half = 0; half < 2; half++) {
                    int ntile = ntp * 2 + half;
                    const uint32_t bh[2] = {bhi[half * 2], bhi[half * 2 + 1]};
                    mma16816(acc[0][ntile], ahi, bh);
                    mma16816(acc[1][ntile], ahi2, bh);
                    if (NT == 3) {
                        const uint32_t bl[2] = {blo[half * 2], blo[half * 2 + 1]};
                        mma16816(acc[0][ntile], ahi, bl);
                        mma16816(acc[1][ntile], ahi2, bl);
                    }
                    if (NT >= 3) {
                        mma16816(acc[0][ntile], alo, bh);
                        mma16816(acc[1][ntile], alo2, bh);
                    }
                }
            }
        }
        __syncthreads();
    }

    int rbase = m0 + mb + (lane >> 2);
    int cbase = nb + (lane & 3) * 2;
#pragma unroll
    for (int mt = 0; mt < 2; mt++) {
#pragma unroll
        for (int ntile = 0; ntile < 8; ntile++) {
            int ncol = cbase + ntile * 8;
            int gcol = n0 + ncol;
#pragma unroll
            for (int rr = 0; rr < 2; rr++) {
                int row = rbase + mt * 16 + rr * 8;
                float v0 = acc[mt][ntile][rr * 2 + 0];
                float v1 = acc[mt][ntile][rr * 2 + 1];
                if (mode == 0) {
                    v0 += bsm[ncol]; v1 += bsm[ncol + 1];
                    size_t idx = (size_t)row * Nld + gcol;
                    if (res) {
                        float2 q = *(const float2*)(res + idx);
                        v0 += q.x; v1 += q.y;
                    }
                    float2 o; o.x = v0; o.y = v1;
                    *(float2*)(Cout + idx) = o;
                } else {
                    // qkv output: [bh][token][64] head-major, fp16 hi only
                    int b = row >> 10, tok = row & 1023;
                    int region = gcol >> 9;        // 0=q 1=k 2=v
                    int hd = gcol & 511;
                    int h = hd >> 6, d = hd & 63;
                    size_t dst = (((size_t)(b * NH_ + h) * HW_) + tok) * DH_ + d;
                    h16* ph = (region == 0) ? g_qhi : (region == 1) ? g_khi : g_vhi;
                    *(uint32_t*)&ph[dst] = pack2(v0, v1);
                }
            }
        }
    }
}

#define GS1 (1024 + 2 * 2 * 16384)
#define GS4 (1024 + 2 * 3 * 16384)

// ---------------- 1) t = transpose(x) + pos -> fp16 -------------------------
__global__ void build_t_kernel(const float* __restrict__ x,
                               const float* __restrict__ pos,
                               h16* __restrict__ thi) {
    __shared__ float tile[32][33];
    int b  = blockIdx.z;
    int n0 = blockIdx.x * 32;
    int c0 = blockIdx.y * 32;
    int tx = threadIdx.x, ty = threadIdx.y;
#pragma unroll
    for (int i = 0; i < 4; i++) {
        int c = c0 + ty + i * 8;
        tile[ty + i * 8][tx] = x[((size_t)b * C_ + c) * HW_ + n0 + tx];
    }
    __syncthreads();
#pragma unroll
    for (int i = 0; i < 4; i++) {
        int n = n0 + ty + i * 8;
        int c = c0 + tx;
        float v = tile[tx][ty + i * 8] + pos[(size_t)n * C_ + c];
        thi[((size_t)b * HW_ + n) * C_ + c] = __float2half(v);
    }
}

// ---------------- fused weight conversions (all hi-only now) -----------------
#define NW1 (C3_*C_)
#define NW2 (C_*C_)
__global__ void splitw_kernel(const float* __restrict__ w1,
                              const float* __restrict__ w2,
                              const float* __restrict__ w3) {
    int i = blockIdx.x * 256 + threadIdx.x;
    if (i < NW1) {
        g_w1hi[i] = __float2half(w1[i]);
    } else if (i < NW1 + NW2) {
        int idx = i - NW1;
        g_w2hi[idx] = __float2half(w2[idx]);
    } else if (i < NW1 + 2 * NW2) {
        int idx = i - NW1 - NW2;
        g_w3hi[idx] = __float2half(w3[idx]);
    }
}

// ---------------- rs two-stage reduction (half2-vectorized) ------------------
__global__ void rs1_kernel(float* __restrict__ psq, float* __restrict__ psk) {
    int bx = blockIdx.x;
    int bh = bx >> 4, part = bx & 15;
    int tid = threadIdx.x;
    int d2 = (tid & 31) * 2;
    int sub = tid >> 5;
    size_t base = (size_t)bh * HW_ * DH_ + d2;
    int n0 = part * 64 + sub * 8;
    float sq0 = 0.f, sq1 = 0.f, sk0 = 0.f, sk1 = 0.f;
#pragma unroll
    for (int n = 0; n < 8; n++) {
        size_t off = base + (size_t)(n0 + n) * DH_;
        __half2 q2 = *(const __half2*)&g_qhi[off];
        __half2 k2 = *(const __half2*)&g_khi[off];
        float qa = __half2float(q2.x), qb = __half2float(q2.y);
        float ka = __half2float(k2.x), kb = __half2float(k2.y);
        sq0 += qa * qa; sq1 += qb * qb;
        sk0 += ka * ka; sk1 += kb * kb;
    }
    __shared__ float smq[8][64], smk[8][64];
    smq[sub][d2] = sq0; smq[sub][d2 + 1] = sq1;
    smk[sub][d2] = sk0; smk[sub][d2 + 1] = sk1;
    __syncthreads();
    if (tid < 64) {
        float q = 0.f, k = 0.f;
#pragma unroll
        for (int s = 0; s < 8; s++) { q += smq[s][tid]; k += smk[s][tid]; }
        psq[((size_t)bh * 16 + part) * 64 + tid] = q;
        psk[((size_t)bh * 16 + part) * 64 + tid] = k;
    }
}

__global__ void rs2_kernel(const float* __restrict__ psq,
                           const float* __restrict__ psk,
                           const float* __restrict__ temp,
                           float* __restrict__ rs) {
    int bh = blockIdx.x, d = threadIdx.x;
    int h = bh % NH_;
    float q = 0.f, k = 0.f;
#pragma unroll
    for (int p = 0; p < 16; p++) {
        q += psq[((size_t)bh * 16 + p) * 64 + d];
        k += psk[((size_t)bh * 16 + p) * 64 + d];
    }
    float qn = fmaxf(sqrtf(q), 1e-12f);
    float kn = fmaxf(sqrtf(k), 1e-12f);
    rs[(size_t)bh * DH_ + d] = temp[h] / (qn * kn);
}

// ---------------- tensor-core fused flash attention --------------------------
// S = Qhi.Khi (1 MMA). P = exp(S) directly (logits bounded post-l2norm; no
// online max needed). O = Phi.Vhi (1 MMA). o stored hi/lo for proj.
#define FAT_STAGE 16384u
#define FAT_QOFF  32768u
#define FAT_SMEM  (32768 + 16384 + 256)

__device__ __forceinline__ void fat_loadkv(
    uint32_t buf, int tid, size_t kvbase, int kc,
    const h16* __restrict__ khi, const h16* __restrict__ vhi) {
#pragma unroll
    for (int it = 0; it < 2; it++) {
        int idx = it * 256 + tid;
        int r = idx >> 3, cg = idx & 7;
        uint32_t so = SWZ((uint32_t)(r * 128 + cg * 16));
        size_t g = kvbase + (size_t)(kc + r) * DH_ + cg * 8;
        cp16(buf +    0u + so, khi + g);
        cp16(buf + 8192u + so, vhi + g);
    }
    asm volatile("cp.async.commit_group;" ::: "memory");
}

__global__ __launch_bounds__(256, 2)
void fat_kernel(const h16* __restrict__ qhi,
                const float* __restrict__ rs,
                const h16* __restrict__ khi, const h16* __restrict__ vhi,
                h16* __restrict__ ohi, h16* __restrict__ olo) {
    extern __shared__ char smc[];
    uint32_t sb = smem_u32(smc);
    float* rss = (float*)(smc + FAT_QOFF + 16384);
    int bh = blockIdx.y;
    int b = bh >> 3, h = bh & 7;
    int q0 = blockIdx.x * 128;
    int tid = threadIdx.x, wid = tid >> 5, lane = tid & 31;
    int mb = wid * 16;

    if (tid < 64) rss[tid] = rs[bh * DH_ + tid];
    __syncthreads();

#pragma unroll
    for (int v = 0; v < 8; v++) {
        int idx = v * 256 + tid;
        int row = idx >> 4, dq = (idx & 15) * 4;
        size_t qoff = ((size_t)bh * HW_ + q0 + row) * DH_ + dq;
        __half2 ha = *(const __half2*)&qhi[qoff];
        __half2 hb = *(const __half2*)&qhi[qoff + 2];
        float qx = __half2float(ha.x) * rss[dq];
        float qy = __half2float(ha.y) * rss[dq + 1];
        float qz = __half2float(hb.x) * rss[dq + 2];
        float qw = __half2float(hb.y) * rss[dq + 3];
        uint32_t off = SWZ((uint32_t)(row * 128 + dq * 2));
        *(uint32_t*)(smc + FAT_QOFF + off)     = pack2(qx, qy);
        *(uint32_t*)(smc + FAT_QOFF + off + 4) = pack2(qz, qw);
    }
    __syncthreads();

    float o[8][4];
#pragma unroll
    for (int j = 0; j < 8; j++)
#pragma unroll
        for (int q = 0; q < 4; q++) o[j][q] = 0.f;
    float l0 = 0.f, l1 = 0.f;
    const size_t kvbase = (size_t)bh * HW_ * DH_;

    fat_loadkv(sb, tid, kvbase, 0, khi, vhi);
    for (int kt = 0; kt < 16; kt++) {
        uint32_t cur = sb + (uint32_t)(kt & 1) * FAT_STAGE;
        if (kt + 1 < 16) {
            fat_loadkv(sb + (uint32_t)((kt + 1) & 1) * FAT_STAGE, tid, kvbase,
                       (kt + 1) * 64, khi, vhi);
            asm volatile("cp.async.wait_group 1;" ::: "memory");
        } else {
            asm volatile("cp.async.wait_group 0;" ::: "memory");
        }
        __syncthreads();

        // ---- S = Q.K^T
        float s[8][4];
#pragma unroll
        for (int j = 0; j < 8; j++)
#pragma unroll
            for (int q = 0; q < 4; q++) s[j][q] = 0.f;
#pragma unroll
        for (int ks = 0; ks < 4; ks++) {
            uint32_t qao = SWZ((uint32_t)((mb + (lane & 15)) * 128 +
                                          (lane >> 4) * 16 + ks * 32));
            uint32_t qh4[4];
            ldsm4(qh4, sb + FAT_QOFF + qao);
            uint32_t brow = (uint32_t)(((lane & 7) + ((lane >> 4) & 1) * 8) * 128 +
                                       ((lane >> 3) & 1) * 16 + ks * 32);
#pragma unroll
            for (int np = 0; np < 4; np++) {
                uint32_t bo = SWZ(brow + (uint32_t)(np * 16 * 128));
                uint32_t kh4[4];
                ldsm4(kh4, cur + bo);
#pragma unroll
                for (int half = 0; half < 2; half++) {
                    int j = np * 2 + half;
                    const uint32_t bhh[2] = {kh4[half * 2], kh4[half * 2 + 1]};
                    mma16816(s[j], qh4, bhh);
                }
            }
        }

        // ---- P = exp(S); accumulate row sums (no max shift: logits bounded)
        float sum0 = 0.f, sum1 = 0.f;
#pragma unroll
        for (int j = 0; j < 8; j++) {
            s[j][0] = __expf(s[j][0]);
            s[j][1] = __expf(s[j][1]);
            s[j][2] = __expf(s[j][2]);
            s[j][3] = __expf(s[j][3]);
            sum0 += s[j][0] + s[j][1];
            sum1 += s[j][2] + s[j][3];
        }
        l0 += sum0; l1 += sum1;

        // ---- O += Phi.Vhi
#pragma unroll
        for (int ks = 0; ks < 4; ks++) {
            int j0 = 2 * ks, j1 = 2 * ks + 1;
            uint32_t ph[4];
            ph[0] = pack2(s[j0][0], s[j0][1]);
            ph[1] = pack2(s[j0][2], s[j0][3]);
            ph[2] = pack2(s[j1][0], s[j1][1]);
            ph[3] = pack2(s[j1][2], s[j1][3]);
            uint32_t vrow = (uint32_t)((ks * 16 + (lane & 7) + ((lane >> 3) & 1) * 8) * 128 +
                                       ((lane >> 4) & 1) * 16);
#pragma unroll
            for (int np = 0; np < 4; np++) {
                uint32_t vo = SWZ(vrow + (uint32_t)(np * 32));
                uint32_t vh4[4];
                ldsm4t(vh4, cur + 8192u + vo);
#pragma unroll
                for (int half = 0; half < 2; half++) {
                    int j = np * 2 + half;
                    const uint32_t bvh[2] = {vh4[half * 2], vh4[half * 2 + 1]};
                    mma16816(o[j], ph, bvh);
                }
            }
        }
        __syncthreads();
    }

    // finalize row sums across the quad, normalize, store o hi/lo
    l0 += __shfl_xor_sync(0xffffffffu, l0, 1);
    l0 += __shfl_xor_sync(0xffffffffu, l0, 2);
    l1 += __shfl_xor_sync(0xffffffffu, l1, 1);
    l1 += __shfl_xor_sync(0xffffffffu, l1, 2);
    float inv0 = 1.f / l0, inv1 = 1.f / l1;
    int r0 = lane >> 2, cc = (lane & 3) * 2;
    int row0 = q0 + mb + r0, row1 = row0 + 8;
#pragma unroll
    for (int j = 0; j < 8; j++) {
        int col = h * DH_ + j * 8 + cc;
        size_t off0 = ((size_t)(b * HW_ + row0)) * C_ + col;
        size_t off1 = ((size_t)(b * HW_ + row1)) * C_ + col;
        uint32_t hi, lo;
        split2(o[j][0] * inv0, o[j][1] * inv0, hi, lo);
        *(uint32_t*)&ohi[off0] = hi; *(uint32_t*)&olo[off0] = lo;
        split2(o[j][2] * inv1, o[j][3] * inv1, hi, lo);
        *(uint32_t*)&ohi[off1] = hi; *(uint32_t*)&olo[off1] = lo;
    }
}

// ---------------- LayerNorm over C + residual + transpose (warp-reduced) ----
__global__ void ln_residual_kernel(const float* __restrict__ ob,
                                   const float* __restrict__ x,
                                   const float* __restrict__ g,
                                   const float* __restrict__ be,
                                   float* __restrict__ y) {
    int row = blockIdx.x;
    int b = row >> 10, n = row & 1023;
    const float* pr = ob + (size_t)row * C_;
    int tid = threadIdx.x, lane = tid & 31, wid = tid >> 5;
    float v0 = pr[tid], v1 = pr[tid + 256];
    __shared__ float red[8];
    __shared__ float bc[2];

    float s = v0 + v1;
#pragma unroll
    for (int off = 16; off; off >>= 1) s += __shfl_xor_sync(0xffffffffu, s, off);
    if (lane == 0) red[wid] = s;
    __syncthreads();
    if (tid == 0) {
        float t = 0.f;
#pragma unroll
        for (int i = 0; i < 8; i++) t += red[i];
        bc[0] = t * (1.0f / C_);
    }
    __syncthreads();
    float mean = bc[0];
    float d0 = v0 - mean, d1 = v1 - mean;
    s = d0 * d0 + d1 * d1;
#pragma unroll
    for (int off = 16; off; off >>= 1) s += __shfl_xor_sync(0xffffffffu, s, off);
    if (lane == 0) red[wid] = s;
    __syncthreads();
    if (tid == 0) {
        float t = 0.f;
#pragma unroll
        for (int i = 0; i < 8; i++) t += red[i];
        bc[1] = rsqrtf(t * (1.0f / C_) + 1e-5f);
    }
    __syncthreads();
    float rstd = bc[1];
    int c0 = tid, c1 = tid + 256;
    size_t i0 = ((size_t)b * C_ + c0) * HW_ + n;
    size_t i1 = ((size_t)b * C_ + c1) * HW_ + n;
    y[i0] = d0 * rstd * g[c0] + be[c0] + x[i0];
    y[i1] = d1 * rstd * g[c1] + be[c1] + x[i1];
}

// ---------------- fused depthwise 3x3 + transpose -> fp16 --------------------
__global__ void dwt_kernel(const float* __restrict__ y,
                           const float* __restrict__ w,
                           const float* __restrict__ bias,
                           h16* __restrict__ hi) {
    __shared__ float yt[32][3][33];
    __shared__ float ot[32][33];   // [w][c]
    int hh = blockIdx.x, c0 = blockIdx.y * 32, b = blockIdx.z;
    int tid = threadIdx.x;
    int c = tid >> 3, wg = (tid & 7) * 4;

#pragma unroll
    for (int r = 0; r < 3; r++) {
        int ih = hh + r - 1;
        float4 v = make_float4(0.f, 0.f, 0.f, 0.f);
        if (ih >= 0 && ih < H_)
            v = *(const float4*)&y[((size_t)(b * C_ + c0 + c)) * HW_ + ih * W_ + wg];
        yt[c][r][wg + 0] = v.x; yt[c][r][wg + 1] = v.y;
        yt[c][r][wg + 2] = v.z; yt[c][r][wg + 3] = v.w;
    }
    float wc[9];
#pragma unroll
    for (int i = 0; i < 9; i++) wc[i] = w[(c0 + c) * 9 + i];
    float bs = bias[c0 + c];
    __syncthreads();

#pragma unroll
    for (int j = 0; j < 4; j++) {
        int ww = wg + j;
        float acc = bs;
#pragma unroll
        for (int ki = 0; ki < 3; ki++)
#pragma unroll
            for (int kj = 0; kj < 3; kj++) {
                int iw = ww + kj - 1;
                if (iw >= 0 && iw < W_) acc += wc[ki * 3 + kj] * yt[c][ki][iw];
            }
        ot[ww][c] = acc;
    }
    __syncthreads();

    int w2 = tid >> 3, cg = (tid & 7) * 4;
    int token = hh * W_ + w2;
    size_t base = ((size_t)b * HW_ + token) * C_ + c0 + cg;
    *(uint32_t*)&hi[base]     = pack2(ot[w2][cg],     ot[w2][cg + 1]);
    *(uint32_t*)&hi[base + 2] = pack2(ot[w2][cg + 2], ot[w2][cg + 3]);
}

// ---------------- launch ------------------------------------------------------
extern "C" void kernel_launch(void* const* d_in, const int* in_sizes, int n_in,
                              void* d_out, int out_size) {
    const float* x      = (const float*)d_in[0];
    const float* qkv_w  = (const float*)d_in[1];
    const float* proj_w = (const float*)d_in[2];
    const float* proj_b = (const float*)d_in[3];
    const float* temper = (const float*)d_in[4];
    const float* ln_g   = (const float*)d_in[5];
    const float* ln_b   = (const float*)d_in[6];
    const float* pos    = (const float*)d_in[7];
    const float* dw_w   = (const float*)d_in[8];
    const float* dw_b   = (const float*)d_in[9];
    const float* pw_w   = (const float*)d_in[10];
    const float* pw_b   = (const float*)d_in[11];
    float* out = (float*)d_out;

    h16 *thi, *w1hi, *w2hi, *w3hi;
    h16 *ohi, *olo, *dThi, *qhi, *khi, *vhi;
    float *rs, *ob, *y, *psq, *psk;
    cudaGetSymbolAddress((void**)&thi,  g_thi);
    cudaGetSymbolAddress((void**)&w1hi, g_w1hi);
    cudaGetSymbolAddress((void**)&w2hi, g_w2hi);
    cudaGetSymbolAddress((void**)&w3hi, g_w3hi);
    cudaGetSymbolAddress((void**)&ohi,  g_ohi);
    cudaGetSymbolAddress((void**)&olo,  g_olo);
    cudaGetSymbolAddress((void**)&dThi, g_dThi);
    cudaGetSymbolAddress((void**)&qhi,  g_qhi);
    cudaGetSymbolAddress((void**)&khi,  g_khi);
    cudaGetSymbolAddress((void**)&vhi,  g_vhi);
    cudaGetSymbolAddress((void**)&rs,   g_rs);
    cudaGetSymbolAddress((void**)&psq,  g_psq);
    cudaGetSymbolAddress((void**)&psk,  g_psk);
    cudaGetSymbolAddress((void**)&ob,   g_ob);
    cudaGetSymbolAddress((void**)&y,    g_y);

    cudaFuncSetAttribute(fat_kernel,
                         cudaFuncAttributeMaxDynamicSharedMemorySize, FAT_SMEM);
    cudaFuncSetAttribute(gemm_tc<1>,
                         cudaFuncAttributeMaxDynamicSharedMemorySize, GS1);
    cudaFuncSetAttribute(gemm_tc<4>,
                         cudaFuncAttributeMaxDynamicSharedMemorySize, GS4);

    // fused weight conversions
    splitw_kernel<<<(NW1 + 2*NW2 + 255)/256, 256>>>(qkv_w, proj_w, pw_w);
    // t = transpose(x) + pos (fp16)
    build_t_kernel<<<dim3(HW_/32, C_/32, B_), dim3(32, 8)>>>(x, pos, thi);
    // qkv GEMM: uniform 1-term fp16, head-major split output (occ 2)
    gemm_tc<1><<<dim3(C3_/128, (B_*HW_)/128, 1), 256, GS1>>>(
        thi, nullptr, w1hi, nullptr, nullptr, nullptr, nullptr, C_, 0, 0, 0, 1);
    // rs two-stage reduction
    rs1_kernel<<<B_*NH_*16, 256>>>(psq, psk);
    rs2_kernel<<<B_*NH_, 64>>>(psq, psk, temper, rs);
    // tensor-core fused attention -> o (hi/lo)
    fat_kernel<<<dim3(HW_/128, B_*NH_), 256, FAT_SMEM>>>(
        qhi, rs, khi, vhi, ohi, olo);
    // proj = (ohi+olo) @ w2hi^T + proj_b (2-term, occ 2)
    gemm_tc<4><<<dim3(C_/128, (B_*HW_)/128, 1), 256, GS4>>>(
        ohi, olo, w2hi, nullptr, proj_b, nullptr, ob, C_, C_, 0, 0, 0);
    // LN + residual + transpose to [B,C,HW]
    ln_residual_kernel<<<B_*HW_, 256>>>(ob, x, ln_g, ln_b, y);
    // fused depthwise 3x3 + transpose (fp16)
    dwt_kernel<<<dim3(H_, C_/32, B_), 256>>>(y, dw_w, dw_b, dThi);
    // pointwise (1-term, occ 2) + bias + residual -> out
    gemm_tc<1><<<dim3(HW_/128, C_/128, B_), 256, GS1>>>(
        w3hi, nullptr, dThi, nullptr, pw_b, y, out, C_, HW_,
        (long)HW_*C_, (long)C_*HW_, 0);
}

// round 14
// speedup vs baseline: 1.9799x; 1.0690x over previous
#include <cuda_runtime.h>
#include <cuda_fp16.h>
#include <cstdint>

#define B_  8
#define C_  512
#define H_  32
#define W_  32
#define NH_ 8
#define DH_ 64
#define HW_ 1024
#define C3_ (3*C_)

typedef __half h16;

// ---------------- scratch (device globals; no allocation allowed) ----------
__device__ h16   g_thi[(size_t)B_*HW_*C_];
__device__ h16   g_w1hi[(size_t)C3_*C_];
__device__ h16   g_w2hi[(size_t)C_*C_];
__device__ h16   g_w3hi[(size_t)C_*C_];
__device__ float g_rs [(size_t)B_*NH_*DH_];
__device__ float g_psq[(size_t)B_*NH_*16*DH_];
__device__ float g_psk[(size_t)B_*NH_*16*DH_];
__device__ h16   g_qhi[(size_t)B_*NH_*HW_*DH_];
__device__ h16   g_khi[(size_t)B_*NH_*HW_*DH_];
__device__ h16   g_vhi[(size_t)B_*NH_*HW_*DH_];
__device__ h16   g_ohi[(size_t)B_*HW_*C_];
__device__ float g_ob [(size_t)B_*HW_*C_];
__device__ float g_y  [(size_t)B_*C_*HW_];
__device__ h16   g_dThi[(size_t)B_*HW_*C_];

// ---------------- small PTX helpers -----------------------------------------
__device__ __forceinline__ uint32_t smem_u32(const void* p) {
    uint32_t a;
    asm("{ .reg .u64 t; cvta.to.shared.u64 t, %1; cvt.u32.u64 %0, t; }"
        : "=r"(a) : "l"(p));
    return a;
}
__device__ __forceinline__ void cp16(uint32_t s, const void* g) {
    asm volatile("cp.async.cg.shared.global [%0], [%1], 16;" :: "r"(s), "l"(g));
}
#define SWZ(x) ((x) ^ (((x) >> 3) & 0x70u))

__device__ __forceinline__ void ldsm4(uint32_t* r, uint32_t addr) {
    asm volatile("ldmatrix.sync.aligned.m8n8.x4.shared.b16 {%0,%1,%2,%3}, [%4];"
                 : "=r"(r[0]), "=r"(r[1]), "=r"(r[2]), "=r"(r[3]) : "r"(addr));
}
__device__ __forceinline__ void ldsm4t(uint32_t* r, uint32_t addr) {
    asm volatile("ldmatrix.sync.aligned.m8n8.x4.trans.shared.b16 {%0,%1,%2,%3}, [%4];"
                 : "=r"(r[0]), "=r"(r[1]), "=r"(r[2]), "=r"(r[3]) : "r"(addr));
}
__device__ __forceinline__ void mma16816(float* c, const uint32_t* a,
                                         const uint32_t* b) {
    asm volatile(
        "mma.sync.aligned.m16n8k16.row.col.f32.f16.f16.f32 "
        "{%0,%1,%2,%3}, {%4,%5,%6,%7}, {%8,%9}, {%0,%1,%2,%3};"
        : "+f"(c[0]), "+f"(c[1]), "+f"(c[2]), "+f"(c[3])
        : "r"(a[0]), "r"(a[1]), "r"(a[2]), "r"(a[3]), "r"(b[0]), "r"(b[1]));
}
__device__ __forceinline__ uint32_t pack2(float a, float b) {
    __half2 h; h.x = __float2half(a); h.y = __float2half(b);
    return *(uint32_t*)&h;
}

// ---------------- HMMA GEMM: D = Ahi @ Bhi^T (1-term fp16), occ 2 ------------
#define GTB 16384u
#define GS1 (1024 + 2 * 2 * 16384)

__device__ __forceinline__ void load_chunk1(
    uint32_t dst, int tid, int m0, int n0, int K, int kc,
    const h16* __restrict__ Ahi, const h16* __restrict__ Bhi) {
#pragma unroll
    for (int it = 0; it < 4; it++) {
        int idx = it * 256 + tid;
        int r = idx >> 3, cg = idx & 7;
        uint32_t so = SWZ((uint32_t)(r * 128 + cg * 16));
        cp16(dst       + so, Ahi + (size_t)(m0 + r) * K + kc + cg * 8);
        cp16(dst + GTB + so, Bhi + (size_t)(n0 + r) * K + kc + cg * 8);
    }
    asm volatile("cp.async.commit_group;" ::: "memory");
}

__global__ __launch_bounds__(256, 2)
void gemm_tc(const h16* __restrict__ Ahi, const h16* __restrict__ Bhi,
             const float* __restrict__ bias, const float* __restrict__ resid,
             float* __restrict__ Cout, int K, int Nld,
             long bBatch, long cBatch, int mode) {
    extern __shared__ char smc[];
    uint32_t sb = smem_u32(smc);
    int tid = threadIdx.x, wid = tid >> 5, lane = tid & 31;
    int m0 = blockIdx.y * 128, n0 = blockIdx.x * 128;
    Bhi += (size_t)blockIdx.z * bBatch;
    if (Cout) Cout += (size_t)blockIdx.z * cBatch;
    const float* res = resid ? resid + (size_t)blockIdx.z * cBatch : nullptr;

    float* bsm = (float*)smc;
    if (tid < 128) bsm[tid] = bias ? bias[n0 + tid] : 0.f;

    const uint32_t t0 = sb + 1024;
    const uint32_t SS = 2u * GTB;
    const int nchunk = K >> 6;
    const int mb = (wid & 3) * 32;
    const int nb = (wid >> 2) * 64;

    float acc[2][8][4];
#pragma unroll
    for (int i = 0; i < 2; i++)
#pragma unroll
        for (int j = 0; j < 8; j++)
#pragma unroll
            for (int q = 0; q < 4; q++) acc[i][j][q] = 0.f;

    load_chunk1(t0, tid, m0, n0, K, 0, Ahi, Bhi);
    for (int c = 0; c < nchunk; c++) {
        if (c + 1 < nchunk) {
            load_chunk1(t0 + (uint32_t)((c + 1) & 1) * SS, tid, m0, n0, K,
                        (c + 1) << 6, Ahi, Bhi);
            asm volatile("cp.async.wait_group 1;" ::: "memory");
        } else {
            asm volatile("cp.async.wait_group 0;" ::: "memory");
        }
        __syncthreads();
        uint32_t bufA = t0 + (uint32_t)(c & 1) * SS;
#pragma unroll
        for (int ks = 0; ks < 4; ks++) {
            int kb = ks * 32;
            uint32_t ao = SWZ((uint32_t)((mb + (lane & 15)) * 128 +
                                         (lane >> 4) * 16 + kb));
            uint32_t ahi[4];
            ldsm4(ahi, bufA + ao);
            uint32_t ao2 = SWZ((uint32_t)((mb + 16 + (lane & 15)) * 128 +
                                          (lane >> 4) * 16 + kb));
            uint32_t ahi2[4];
            ldsm4(ahi2, bufA + ao2);
            uint32_t brow = (uint32_t)((nb + (lane & 7) + ((lane >> 4) & 1) * 8) * 128 +
                                       ((lane >> 3) & 1) * 16 + kb);
#pragma unroll
            for (int ntp = 0; ntp < 4; ntp++) {
                uint32_t bo = SWZ(brow + (uint32_t)(ntp * 16 * 128));
                uint32_t bhi[4];
                ldsm4(bhi, bufA + GTB + bo);
#pragma unroll
                for (int half = 0; half < 2; half++) {
                    int ntile = ntp * 2 + half;
                    const uint32_t bh[2] = {bhi[half * 2], bhi[half * 2 + 1]};
                    mma16816(acc[0][ntile], ahi, bh);
                    mma16816(acc[1][ntile], ahi2, bh);
                }
            }
        }
        __syncthreads();
    }

    int rbase = m0 + mb + (lane >> 2);
    int cbase = nb + (lane & 3) * 2;
#pragma unroll
    for (int mt = 0; mt < 2; mt++) {
#pragma unroll
        for (int ntile = 0; ntile < 8; ntile++) {
            int ncol = cbase + ntile * 8;
            int gcol = n0 + ncol;
#pragma unroll
            for (int rr = 0; rr < 2; rr++) {
                int row = rbase + mt * 16 + rr * 8;
                float v0 = acc[mt][ntile][rr * 2 + 0];
                float v1 = acc[mt][ntile][rr * 2 + 1];
                if (mode == 0) {
                    v0 += bsm[ncol]; v1 += bsm[ncol + 1];
                    size_t idx = (size_t)row * Nld + gcol;
                    if (res) {
                        float2 q = *(const float2*)(res + idx);
                        v0 += q.x; v1 += q.y;
                    }
                    float2 o; o.x = v0; o.y = v1;
                    *(float2*)(Cout + idx) = o;
                } else {
                    // qkv output: [bh][token][64] head-major, fp16
                    int b = row >> 10, tok = row & 1023;
                    int region = gcol >> 9;        // 0=q 1=k 2=v
                    int hd = gcol & 511;
                    int h = hd >> 6, d = hd & 63;
                    size_t dst = (((size_t)(b * NH_ + h) * HW_) + tok) * DH_ + d;
                    h16* ph = (region == 0) ? g_qhi : (region == 1) ? g_khi : g_vhi;
                    *(uint32_t*)&ph[dst] = pack2(v0, v1);
                }
            }
        }
    }
}

// ---------------- 1) t = transpose(x) + pos -> fp16 -------------------------
__global__ void build_t_kernel(const float* __restrict__ x,
                               const float* __restrict__ pos,
                               h16* __restrict__ thi) {
    __shared__ float tile[32][33];
    int b  = blockIdx.z;
    int n0 = blockIdx.x * 32;
    int c0 = blockIdx.y * 32;
    int tx = threadIdx.x, ty = threadIdx.y;
#pragma unroll
    for (int i = 0; i < 4; i++) {
        int c = c0 + ty + i * 8;
        tile[ty + i * 8][tx] = x[((size_t)b * C_ + c) * HW_ + n0 + tx];
    }
    __syncthreads();
#pragma unroll
    for (int i = 0; i < 4; i++) {
        int n = n0 + ty + i * 8;
        int c = c0 + tx;
        float v = tile[tx][ty + i * 8] + pos[(size_t)n * C_ + c];
        thi[((size_t)b * HW_ + n) * C_ + c] = __float2half(v);
    }
}

// ---------------- fused weight conversions (all hi-only) ---------------------
#define NW1 (C3_*C_)
#define NW2 (C_*C_)
__global__ void splitw_kernel(const float* __restrict__ w1,
                              const float* __restrict__ w2,
                              const float* __restrict__ w3) {
    int i = blockIdx.x * 256 + threadIdx.x;
    if (i < NW1) {
        g_w1hi[i] = __float2half(w1[i]);
    } else if (i < NW1 + NW2) {
        int idx = i - NW1;
        g_w2hi[idx] = __float2half(w2[idx]);
    } else if (i < NW1 + 2 * NW2) {
        int idx = i - NW1 - NW2;
        g_w3hi[idx] = __float2half(w3[idx]);
    }
}

// ---------------- rs two-stage reduction (half2-vectorized) ------------------
__global__ void rs1_kernel(float* __restrict__ psq, float* __restrict__ psk) {
    int bx = blockIdx.x;
    int bh = bx >> 4, part = bx & 15;
    int tid = threadIdx.x;
    int d2 = (tid & 31) * 2;
    int sub = tid >> 5;
    size_t base = (size_t)bh * HW_ * DH_ + d2;
    int n0 = part * 64 + sub * 8;
    float sq0 = 0.f, sq1 = 0.f, sk0 = 0.f, sk1 = 0.f;
#pragma unroll
    for (int n = 0; n < 8; n++) {
        size_t off = base + (size_t)(n0 + n) * DH_;
        __half2 q2 = *(const __half2*)&g_qhi[off];
        __half2 k2 = *(const __half2*)&g_khi[off];
        float qa = __half2float(q2.x), qb = __half2float(q2.y);
        float ka = __half2float(k2.x), kb = __half2float(k2.y);
        sq0 += qa * qa; sq1 += qb * qb;
        sk0 += ka * ka; sk1 += kb * kb;
    }
    __shared__ float smq[8][64], smk[8][64];
    smq[sub][d2] = sq0; smq[sub][d2 + 1] = sq1;
    smk[sub][d2] = sk0; smk[sub][d2 + 1] = sk1;
    __syncthreads();
    if (tid < 64) {
        float q = 0.f, k = 0.f;
#pragma unroll
        for (int s = 0; s < 8; s++) { q += smq[s][tid]; k += smk[s][tid]; }
        psq[((size_t)bh * 16 + part) * 64 + tid] = q;
        psk[((size_t)bh * 16 + part) * 64 + tid] = k;
    }
}

__global__ void rs2_kernel(const float* __restrict__ psq,
                           const float* __restrict__ psk,
                           const float* __restrict__ temp,
                           float* __restrict__ rs) {
    int bh = blockIdx.x, d = threadIdx.x;
    int h = bh % NH_;
    float q = 0.f, k = 0.f;
#pragma unroll
    for (int p = 0; p < 16; p++) {
        q += psq[((size_t)bh * 16 + p) * 64 + d];
        k += psk[((size_t)bh * 16 + p) * 64 + d];
    }
    float qn = fmaxf(sqrtf(q), 1e-12f);
    float kn = fmaxf(sqrtf(k), 1e-12f);
    rs[(size_t)bh * DH_ + d] = temp[h] / (qn * kn);
}

// ---------------- tensor-core fused flash attention --------------------------
// S = Qhi.Khi (1 MMA). P = exp(S) directly (logits bounded post-l2norm).
// O = Phi.Vhi (1 MMA). o stored fp16 hi-only.
#define FAT_STAGE 16384u
#define FAT_QOFF  32768u
#define FAT_SMEM  (32768 + 16384 + 256)

__device__ __forceinline__ void fat_loadkv(
    uint32_t buf, int tid, size_t kvbase, int kc,
    const h16* __restrict__ khi, const h16* __restrict__ vhi) {
#pragma unroll
    for (int it = 0; it < 2; it++) {
        int idx = it * 256 + tid;
        int r = idx >> 3, cg = idx & 7;
        uint32_t so = SWZ((uint32_t)(r * 128 + cg * 16));
        size_t g = kvbase + (size_t)(kc + r) * DH_ + cg * 8;
        cp16(buf +    0u + so, khi + g);
        cp16(buf + 8192u + so, vhi + g);
    }
    asm volatile("cp.async.commit_group;" ::: "memory");
}

__global__ __launch_bounds__(256, 2)
void fat_kernel(const h16* __restrict__ qhi,
                const float* __restrict__ rs,
                const h16* __restrict__ khi, const h16* __restrict__ vhi,
                h16* __restrict__ ohi) {
    extern __shared__ char smc[];
    uint32_t sb = smem_u32(smc);
    float* rss = (float*)(smc + FAT_QOFF + 16384);
    int bh = blockIdx.y;
    int b = bh >> 3, h = bh & 7;
    int q0 = blockIdx.x * 128;
    int tid = threadIdx.x, wid = tid >> 5, lane = tid & 31;
    int mb = wid * 16;

    if (tid < 64) rss[tid] = rs[bh * DH_ + tid];
    __syncthreads();

#pragma unroll
    for (int v = 0; v < 8; v++) {
        int idx = v * 256 + tid;
        int row = idx >> 4, dq = (idx & 15) * 4;
        size_t qoff = ((size_t)bh * HW_ + q0 + row) * DH_ + dq;
        __half2 ha = *(const __half2*)&qhi[qoff];
        __half2 hb = *(const __half2*)&qhi[qoff + 2];
        float qx = __half2float(ha.x) * rss[dq];
        float qy = __half2float(ha.y) * rss[dq + 1];
        float qz = __half2float(hb.x) * rss[dq + 2];
        float qw = __half2float(hb.y) * rss[dq + 3];
        uint32_t off = SWZ((uint32_t)(row * 128 + dq * 2));
        *(uint32_t*)(smc + FAT_QOFF + off)     = pack2(qx, qy);
        *(uint32_t*)(smc + FAT_QOFF + off + 4) = pack2(qz, qw);
    }
    __syncthreads();

    float o[8][4];
#pragma unroll
    for (int j = 0; j < 8; j++)
#pragma unroll
        for (int q = 0; q < 4; q++) o[j][q] = 0.f;
    float l0 = 0.f, l1 = 0.f;
    const size_t kvbase = (size_t)bh * HW_ * DH_;

    fat_loadkv(sb, tid, kvbase, 0, khi, vhi);
    for (int kt = 0; kt < 16; kt++) {
        uint32_t cur = sb + (uint32_t)(kt & 1) * FAT_STAGE;
        if (kt + 1 < 16) {
            fat_loadkv(sb + (uint32_t)((kt + 1) & 1) * FAT_STAGE, tid, kvbase,
                       (kt + 1) * 64, khi, vhi);
            asm volatile("cp.async.wait_group 1;" ::: "memory");
        } else {
            asm volatile("cp.async.wait_group 0;" ::: "memory");
        }
        __syncthreads();

        // ---- S = Q.K^T
        float s[8][4];
#pragma unroll
        for (int j = 0; j < 8; j++)
#pragma unroll
            for (int q = 0; q < 4; q++) s[j][q] = 0.f;
#pragma unroll
        for (int ks = 0; ks < 4; ks++) {
            uint32_t qao = SWZ((uint32_t)((mb + (lane & 15)) * 128 +
                                          (lane >> 4) * 16 + ks * 32));
            uint32_t qh4[4];
            ldsm4(qh4, sb + FAT_QOFF + qao);
            uint32_t brow = (uint32_t)(((lane & 7) + ((lane >> 4) & 1) * 8) * 128 +
                                       ((lane >> 3) & 1) * 16 + ks * 32);
#pragma unroll
            for (int np = 0; np < 4; np++) {
                uint32_t bo = SWZ(brow + (uint32_t)(np * 16 * 128));
                uint32_t kh4[4];
                ldsm4(kh4, cur + bo);
#pragma unroll
                for (int half = 0; half < 2; half++) {
                    int j = np * 2 + half;
                    const uint32_t bhh[2] = {kh4[half * 2], kh4[half * 2 + 1]};
                    mma16816(s[j], qh4, bhh);
                }
            }
        }

        // ---- P = exp(S); accumulate row sums
        float sum0 = 0.f, sum1 = 0.f;
#pragma unroll
        for (int j = 0; j < 8; j++) {
            s[j][0] = __expf(s[j][0]);
            s[j][1] = __expf(s[j][1]);
            s[j][2] = __expf(s[j][2]);
            s[j][3] = __expf(s[j][3]);
            sum0 += s[j][0] + s[j][1];
            sum1 += s[j][2] + s[j][3];
        }
        l0 += sum0; l1 += sum1;

        // ---- O += Phi.Vhi
#pragma unroll
        for (int ks = 0; ks < 4; ks++) {
            int j0 = 2 * ks, j1 = 2 * ks + 1;
            uint32_t ph[4];
            ph[0] = pack2(s[j0][0], s[j0][1]);
            ph[1] = pack2(s[j0][2], s[j0][3]);
            ph[2] = pack2(s[j1][0], s[j1][1]);
            ph[3] = pack2(s[j1][2], s[j1][3]);
            uint32_t vrow = (uint32_t)((ks * 16 + (lane & 7) + ((lane >> 3) & 1) * 8) * 128 +
                                       ((lane >> 4) & 1) * 16);
#pragma unroll
            for (int np = 0; np < 4; np++) {
                uint32_t vo = SWZ(vrow + (uint32_t)(np * 32));
                uint32_t vh4[4];
                ldsm4t(vh4, cur + 8192u + vo);
#pragma unroll
                for (int half = 0; half < 2; half++) {
                    int j = np * 2 + half;
                    const uint32_t bvh[2] = {vh4[half * 2], vh4[half * 2 + 1]};
                    mma16816(o[j], ph, bvh);
                }
            }
        }
        __syncthreads();
    }

    // finalize row sums across the quad, normalize, store fp16
    l0 += __shfl_xor_sync(0xffffffffu, l0, 1);
    l0 += __shfl_xor_sync(0xffffffffu, l0, 2);
    l1 += __shfl_xor_sync(0xffffffffu, l1, 1);
    l1 += __shfl_xor_sync(0xffffffffu, l1, 2);
    float inv0 = 1.f / l0, inv1 = 1.f / l1;
    int r0 = lane >> 2, cc = (lane & 3) * 2;
    int row0 = q0 + mb + r0, row1 = row0 + 8;
#pragma unroll
    for (int j = 0; j < 8; j++) {
        int col = h * DH_ + j * 8 + cc;
        size_t off0 = ((size_t)(b * HW_ + row0)) * C_ + col;
        size_t off1 = ((size_t)(b * HW_ + row1)) * C_ + col;
        *(uint32_t*)&ohi[off0] = pack2(o[j][0] * inv0, o[j][1] * inv0);
        *(uint32_t*)&ohi[off1] = pack2(o[j][2] * inv1, o[j][3] * inv1);
    }
}

// ---------------- LayerNorm over C + residual + transpose (warp-reduced) ----
__global__ void ln_residual_kernel(const float* __restrict__ ob,
                                   const float* __restrict__ x,
                                   const float* __restrict__ g,
                                   const float* __restrict__ be,
                                   float* __restrict__ y) {
    int row = blockIdx.x;
    int b = row >> 10, n = row & 1023;
    const float* pr = ob + (size_t)row * C_;
    int tid = threadIdx.x, lane = tid & 31, wid = tid >> 5;
    float v0 = pr[tid], v1 = pr[tid + 256];
    __shared__ float red[8];
    __shared__ float bc[2];

    float s = v0 + v1;
#pragma unroll
    for (int off = 16; off; off >>= 1) s += __shfl_xor_sync(0xffffffffu, s, off);
    if (lane == 0) red[wid] = s;
    __syncthreads();
    if (tid == 0) {
        float t = 0.f;
#pragma unroll
        for (int i = 0; i < 8; i++) t += red[i];
        bc[0] = t * (1.0f / C_);
    }
    __syncthreads();
    float mean = bc[0];
    float d0 = v0 - mean, d1 = v1 - mean;
    s = d0 * d0 + d1 * d1;
#pragma unroll
    for (int off = 16; off; off >>= 1) s += __shfl_xor_sync(0xffffffffu, s, off);
    if (lane == 0) red[wid] = s;
    __syncthreads();
    if (tid == 0) {
        float t = 0.f;
#pragma unroll
        for (int i = 0; i < 8; i++) t += red[i];
        bc[1] = rsqrtf(t * (1.0f / C_) + 1e-5f);
    }
    __syncthreads();
    float rstd = bc[1];
    int c0 = tid, c1 = tid + 256;
    size_t i0 = ((size_t)b * C_ + c0) * HW_ + n;
    size_t i1 = ((size_t)b * C_ + c1) * HW_ + n;
    y[i0] = d0 * rstd * g[c0] + be[c0] + x[i0];
    y[i1] = d1 * rstd * g[c1] + be[c1] + x[i1];
}

// ---------------- fused depthwise 3x3 + transpose -> fp16 --------------------
__global__ void dwt_kernel(const float* __restrict__ y,
                           const float* __restrict__ w,
                           const float* __restrict__ bias,
                           h16* __restrict__ hi) {
    __shared__ float yt[32][3][33];
    __shared__ float ot[32][33];   // [w][c]
    int hh = blockIdx.x, c0 = blockIdx.y * 32, b = blockIdx.z;
    int tid = threadIdx.x;
    int c = tid >> 3, wg = (tid & 7) * 4;

#pragma unroll
    for (int r = 0; r < 3; r++) {
        int ih = hh + r - 1;
        float4 v = make_float4(0.f, 0.f, 0.f, 0.f);
        if (ih >= 0 && ih < H_)
            v = *(const float4*)&y[((size_t)(b * C_ + c0 + c)) * HW_ + ih * W_ + wg];
        yt[c][r][wg + 0] = v.x; yt[c][r][wg + 1] = v.y;
        yt[c][r][wg + 2] = v.z; yt[c][r][wg + 3] = v.w;
    }
    float wc[9];
#pragma unroll
    for (int i = 0; i < 9; i++) wc[i] = w[(c0 + c) * 9 + i];
    float bs = bias[c0 + c];
    __syncthreads();

#pragma unroll
    for (int j = 0; j < 4; j++) {
        int ww = wg + j;
        float acc = bs;
#pragma unroll
        for (int ki = 0; ki < 3; ki++)
#pragma unroll
            for (int kj = 0; kj < 3; kj++) {
                int iw = ww + kj - 1;
                if (iw >= 0 && iw < W_) acc += wc[ki * 3 + kj] * yt[c][ki][iw];
            }
        ot[ww][c] = acc;
    }
    __syncthreads();

    int w2 = tid >> 3, cg = (tid & 7) * 4;
    int token = hh * W_ + w2;
    size_t base = ((size_t)b * HW_ + token) * C_ + c0 + cg;
    *(uint32_t*)&hi[base]     = pack2(ot[w2][cg],     ot[w2][cg + 1]);
    *(uint32_t*)&hi[base + 2] = pack2(ot[w2][cg + 2], ot[w2][cg + 3]);
}

// ---------------- launch ------------------------------------------------------
extern "C" void kernel_launch(void* const* d_in, const int* in_sizes, int n_in,
                              void* d_out, int out_size) {
    const float* x      = (const float*)d_in[0];
    const float* qkv_w  = (const float*)d_in[1];
    const float* proj_w = (const float*)d_in[2];
    const float* proj_b = (const float*)d_in[3];
    const float* temper = (const float*)d_in[4];
    const float* ln_g   = (const float*)d_in[5];
    const float* ln_b   = (const float*)d_in[6];
    const float* pos    = (const float*)d_in[7];
    const float* dw_w   = (const float*)d_in[8];
    const float* dw_b   = (const float*)d_in[9];
    const float* pw_w   = (const float*)d_in[10];
    const float* pw_b   = (const float*)d_in[11];
    float* out = (float*)d_out;

    h16 *thi, *w1hi, *w2hi, *w3hi;
    h16 *ohi, *dThi, *qhi, *khi, *vhi;
    float *rs, *ob, *y, *psq, *psk;
    cudaGetSymbolAddress((void**)&thi,  g_thi);
    cudaGetSymbolAddress((void**)&w1hi, g_w1hi);
    cudaGetSymbolAddress((void**)&w2hi, g_w2hi);
    cudaGetSymbolAddress((void**)&w3hi, g_w3hi);
    cudaGetSymbolAddress((void**)&ohi,  g_ohi);
    cudaGetSymbolAddress((void**)&dThi, g_dThi);
    cudaGetSymbolAddress((void**)&qhi,  g_qhi);
    cudaGetSymbolAddress((void**)&khi,  g_khi);
    cudaGetSymbolAddress((void**)&vhi,  g_vhi);
    cudaGetSymbolAddress((void**)&rs,   g_rs);
    cudaGetSymbolAddress((void**)&psq,  g_psq);
    cudaGetSymbolAddress((void**)&psk,  g_psk);
    cudaGetSymbolAddress((void**)&ob,   g_ob);
    cudaGetSymbolAddress((void**)&y,    g_y);

    cudaFuncSetAttribute(fat_kernel,
                         cudaFuncAttributeMaxDynamicSharedMemorySize, FAT_SMEM);
    cudaFuncSetAttribute(gemm_tc,
                         cudaFuncAttributeMaxDynamicSharedMemorySize, GS1);

    // fused weight conversions
    splitw_kernel<<<(NW1 + 2*NW2 + 255)/256, 256>>>(qkv_w, proj_w, pw_w);
    // t = transpose(x) + pos (fp16)
    build_t_kernel<<<dim3(HW_/32, C_/32, B_), dim3(32, 8)>>>(x, pos, thi);
    // qkv GEMM: 1-term fp16, head-major split output (occ 2)
    gemm_tc<<<dim3(C3_/128, (B_*HW_)/128, 1), 256, GS1>>>(
        thi, w1hi, nullptr, nullptr, nullptr, C_, 0, 0, 0, 1);
    // rs two-stage reduction
    rs1_kernel<<<B_*NH_*16, 256>>>(psq, psk);
    rs2_kernel<<<B_*NH_, 64>>>(psq, psk, temper, rs);
    // tensor-core fused attention -> ohi
    fat_kernel<<<dim3(HW_/128, B_*NH_), 256, FAT_SMEM>>>(
        qhi, rs, khi, vhi, ohi);
    // proj = ohi @ w2hi^T + proj_b (1-term, occ 2)
    gemm_tc<<<dim3(C_/128, (B_*HW_)/128, 1), 256, GS1>>>(
        ohi, w2hi, proj_b, nullptr, ob, C_, C_, 0, 0, 0);
    // LN + residual + transpose to [B,C,HW]
    ln_residual_kernel<<<B_*HW_, 256>>>(ob, x, ln_g, ln_b, y);
    // fused depthwise 3x3 + transpose (fp16)
    dwt_kernel<<<dim3(H_, C_/32, B_), 256>>>(y, dw_w, dw_b, dThi);
    // pointwise (1-term, occ 2) + bias + residual -> out
    gemm_tc<<<dim3(HW_/128, C_/128, B_), 256, GS1>>>(
        w3hi, dThi, pw_b, y, out, C_, HW_,
        (long)HW_*C_, (long)C_*HW_, 0);
}

// round 15
// speedup vs baseline: 2.0023x; 1.0113x over previous
#include <cuda_runtime.h>
#include <cuda_fp16.h>
#include <cstdint>

#define B_  8
#define C_  512
#define H_  32
#define W_  32
#define NH_ 8
#define DH_ 64
#define HW_ 1024
#define C3_ (3*C_)

typedef __half h16;

// ---------------- scratch (device globals; no allocation allowed) ----------
__device__ h16   g_thi[(size_t)B_*HW_*C_];
__device__ h16   g_w1hi[(size_t)C3_*C_];
__device__ h16   g_w2hi[(size_t)C_*C_];
__device__ h16   g_w3hi[(size_t)C_*C_];
__device__ float g_rs [(size_t)B_*NH_*DH_];
__device__ float g_psq[(size_t)B_*NH_*16*DH_];
__device__ float g_psk[(size_t)B_*NH_*16*DH_];
__device__ h16   g_qhi[(size_t)B_*NH_*HW_*DH_];
__device__ h16   g_khi[(size_t)B_*NH_*HW_*DH_];
__device__ h16   g_vhi[(size_t)B_*NH_*HW_*DH_];
__device__ h16   g_ohi[(size_t)B_*HW_*C_];
__device__ float g_ob [(size_t)B_*HW_*C_];
__device__ float g_y  [(size_t)B_*C_*HW_];
__device__ h16   g_dThi[(size_t)B_*HW_*C_];

// ---------------- small PTX helpers -----------------------------------------
__device__ __forceinline__ uint32_t smem_u32(const void* p) {
    uint32_t a;
    asm("{ .reg .u64 t; cvta.to.shared.u64 t, %1; cvt.u32.u64 %0, t; }"
        : "=r"(a) : "l"(p));
    return a;
}
__device__ __forceinline__ void cp16(uint32_t s, const void* g) {
    asm volatile("cp.async.cg.shared.global [%0], [%1], 16;" :: "r"(s), "l"(g));
}
#define SWZ(x) ((x) ^ (((x) >> 3) & 0x70u))

__device__ __forceinline__ void ldsm4(uint32_t* r, uint32_t addr) {
    asm volatile("ldmatrix.sync.aligned.m8n8.x4.shared.b16 {%0,%1,%2,%3}, [%4];"
                 : "=r"(r[0]), "=r"(r[1]), "=r"(r[2]), "=r"(r[3]) : "r"(addr));
}
__device__ __forceinline__ void ldsm4t(uint32_t* r, uint32_t addr) {
    asm volatile("ldmatrix.sync.aligned.m8n8.x4.trans.shared.b16 {%0,%1,%2,%3}, [%4];"
                 : "=r"(r[0]), "=r"(r[1]), "=r"(r[2]), "=r"(r[3]) : "r"(addr));
}
__device__ __forceinline__ void mma16816(float* c, const uint32_t* a,
                                         const uint32_t* b) {
    asm volatile(
        "mma.sync.aligned.m16n8k16.row.col.f32.f16.f16.f32 "
        "{%0,%1,%2,%3}, {%4,%5,%6,%7}, {%8,%9}, {%0,%1,%2,%3};"
        : "+f"(c[0]), "+f"(c[1]), "+f"(c[2]), "+f"(c[3])
        : "r"(a[0]), "r"(a[1]), "r"(a[2]), "r"(a[3]), "r"(b[0]), "r"(b[1]));
}
__device__ __forceinline__ uint32_t pack2(float a, float b) {
    __half2 h; h.x = __float2half(a); h.y = __float2half(b);
    return *(uint32_t*)&h;
}

// ---------------- HMMA GEMM: D = Ahi @ Bhi^T (1-term fp16), occ 2 ------------
// Single-sync pipeline: wait(cur) -> sync -> issue(next) -> compute(cur).
#define GTB 16384u
#define GS1 (1024 + 2 * 2 * 16384)

__device__ __forceinline__ void load_chunk1(
    uint32_t dst, int tid, int m0, int n0, int K, int kc,
    const h16* __restrict__ Ahi, const h16* __restrict__ Bhi) {
#pragma unroll
    for (int it = 0; it < 4; it++) {
        int idx = it * 256 + tid;
        int r = idx >> 3, cg = idx & 7;
        uint32_t so = SWZ((uint32_t)(r * 128 + cg * 16));
        cp16(dst       + so, Ahi + (size_t)(m0 + r) * K + kc + cg * 8);
        cp16(dst + GTB + so, Bhi + (size_t)(n0 + r) * K + kc + cg * 8);
    }
    asm volatile("cp.async.commit_group;" ::: "memory");
}

__global__ __launch_bounds__(256, 2)
void gemm_tc(const h16* __restrict__ Ahi, const h16* __restrict__ Bhi,
             const float* __restrict__ bias, const float* __restrict__ resid,
             float* __restrict__ Cout, int K, int Nld,
             long bBatch, long cBatch, int mode) {
    extern __shared__ char smc[];
    uint32_t sb = smem_u32(smc);
    int tid = threadIdx.x, wid = tid >> 5, lane = tid & 31;
    int m0 = blockIdx.y * 128, n0 = blockIdx.x * 128;
    Bhi += (size_t)blockIdx.z * bBatch;
    if (Cout) Cout += (size_t)blockIdx.z * cBatch;
    const float* res = resid ? resid + (size_t)blockIdx.z * cBatch : nullptr;

    float* bsm = (float*)smc;
    if (tid < 128) bsm[tid] = bias ? bias[n0 + tid] : 0.f;

    const uint32_t t0 = sb + 1024;
    const uint32_t SS = 2u * GTB;
    const int nchunk = K >> 6;
    const int mb = (wid & 3) * 32;
    const int nb = (wid >> 2) * 64;

    float acc[2][8][4];
#pragma unroll
    for (int i = 0; i < 2; i++)
#pragma unroll
        for (int j = 0; j < 8; j++)
#pragma unroll
            for (int q = 0; q < 4; q++) acc[i][j][q] = 0.f;

    load_chunk1(t0, tid, m0, n0, K, 0, Ahi, Bhi);
    for (int c = 0; c < nchunk; c++) {
        asm volatile("cp.async.wait_group 0;" ::: "memory");
        __syncthreads();
        if (c + 1 < nchunk)
            load_chunk1(t0 + (uint32_t)((c + 1) & 1) * SS, tid, m0, n0, K,
                        (c + 1) << 6, Ahi, Bhi);
        uint32_t bufA = t0 + (uint32_t)(c & 1) * SS;
#pragma unroll
        for (int ks = 0; ks < 4; ks++) {
            int kb = ks * 32;
            uint32_t ao = SWZ((uint32_t)((mb + (lane & 15)) * 128 +
                                         (lane >> 4) * 16 + kb));
            uint32_t ahi[4];
            ldsm4(ahi, bufA + ao);
            uint32_t ao2 = SWZ((uint32_t)((mb + 16 + (lane & 15)) * 128 +
                                          (lane >> 4) * 16 + kb));
            uint32_t ahi2[4];
            ldsm4(ahi2, bufA + ao2);
            uint32_t brow = (uint32_t)((nb + (lane & 7) + ((lane >> 4) & 1) * 8) * 128 +
                                       ((lane >> 3) & 1) * 16 + kb);
#pragma unroll
            for (int ntp = 0; ntp < 4; ntp++) {
                uint32_t bo = SWZ(brow + (uint32_t)(ntp * 16 * 128));
                uint32_t bhi[4];
                ldsm4(bhi, bufA + GTB + bo);
#pragma unroll
                for (int half = 0; half < 2; half++) {
                    int ntile = ntp * 2 + half;
                    const uint32_t bh[2] = {bhi[half * 2], bhi[half * 2 + 1]};
                    mma16816(acc[0][ntile], ahi, bh);
                    mma16816(acc[1][ntile], ahi2, bh);
                }
            }
        }
    }

    int rbase = m0 + mb + (lane >> 2);
    int cbase = nb + (lane & 3) * 2;
#pragma unroll
    for (int mt = 0; mt < 2; mt++) {
#pragma unroll
        for (int ntile = 0; ntile < 8; ntile++) {
            int ncol = cbase + ntile * 8;
            int gcol = n0 + ncol;
#pragma unroll
            for (int rr = 0; rr < 2; rr++) {
                int row = rbase + mt * 16 + rr * 8;
                float v0 = acc[mt][ntile][rr * 2 + 0];
                float v1 = acc[mt][ntile][rr * 2 + 1];
                if (mode == 0) {
                    v0 += bsm[ncol]; v1 += bsm[ncol + 1];
                    size_t idx = (size_t)row * Nld + gcol;
                    if (res) {
                        float2 q = *(const float2*)(res + idx);
                        v0 += q.x; v1 += q.y;
                    }
                    float2 o; o.x = v0; o.y = v1;
                    *(float2*)(Cout + idx) = o;
                } else {
                    // qkv output: [bh][token][64] head-major, fp16
                    int b = row >> 10, tok = row & 1023;
                    int region = gcol >> 9;        // 0=q 1=k 2=v
                    int hd = gcol & 511;
                    int h = hd >> 6, d = hd & 63;
                    size_t dst = (((size_t)(b * NH_ + h) * HW_) + tok) * DH_ + d;
                    h16* ph = (region == 0) ? g_qhi : (region == 1) ? g_khi : g_vhi;
                    *(uint32_t*)&ph[dst] = pack2(v0, v1);
                }
            }
        }
    }
}

// ---------------- prep: weight fp16 conversion + build_t (merged) ------------
#define NW1 (C3_*C_)
#define NW2 (C_*C_)
#define SPLIT_BLOCKS ((NW1 + 2*NW2) / 256)       // 5120
#define BT_BLOCKS    (B_ * (C_/32) * (HW_/32))   // 4096

__global__ void prep_kernel(const float* __restrict__ w1,
                            const float* __restrict__ w2,
                            const float* __restrict__ w3,
                            const float* __restrict__ x,
                            const float* __restrict__ pos,
                            h16* __restrict__ thi) {
    if (blockIdx.x < SPLIT_BLOCKS) {
        int i = blockIdx.x * 256 + threadIdx.x;
        if (i < NW1) {
            g_w1hi[i] = __float2half(w1[i]);
        } else if (i < NW1 + NW2) {
            int idx = i - NW1;
            g_w2hi[idx] = __float2half(w2[idx]);
        } else {
            int idx = i - NW1 - NW2;
            g_w3hi[idx] = __float2half(w3[idx]);
        }
        return;
    }
    // build_t: transpose(x) + pos -> fp16
    __shared__ float tile[32][33];
    int bi = blockIdx.x - SPLIT_BLOCKS;
    int b  = bi >> 9;
    int rem = bi & 511;
    int c0 = (rem >> 5) * 32;
    int n0 = (rem & 31) * 32;
    int tx = threadIdx.x & 31, ty = threadIdx.x >> 5;  // 32 x 8
#pragma unroll
    for (int i = 0; i < 4; i++) {
        int c = c0 + ty + i * 8;
        tile[ty + i * 8][tx] = x[((size_t)b * C_ + c) * HW_ + n0 + tx];
    }
    __syncthreads();
#pragma unroll
    for (int i = 0; i < 4; i++) {
        int n = n0 + ty + i * 8;
        int c = c0 + tx;
        float v = tile[tx][ty + i * 8] + pos[(size_t)n * C_ + c];
        thi[((size_t)b * HW_ + n) * C_ + c] = __float2half(v);
    }
}

// ---------------- rs two-stage reduction (half2-vectorized) ------------------
__global__ void rs1_kernel(float* __restrict__ psq, float* __restrict__ psk) {
    int bx = blockIdx.x;
    int bh = bx >> 4, part = bx & 15;
    int tid = threadIdx.x;
    int d2 = (tid & 31) * 2;
    int sub = tid >> 5;
    size_t base = (size_t)bh * HW_ * DH_ + d2;
    int n0 = part * 64 + sub * 8;
    float sq0 = 0.f, sq1 = 0.f, sk0 = 0.f, sk1 = 0.f;
#pragma unroll
    for (int n = 0; n < 8; n++) {
        size_t off = base + (size_t)(n0 + n) * DH_;
        __half2 q2 = *(const __half2*)&g_qhi[off];
        __half2 k2 = *(const __half2*)&g_khi[off];
        float qa = __half2float(q2.x), qb = __half2float(q2.y);
        float ka = __half2float(k2.x), kb = __half2float(k2.y);
        sq0 += qa * qa; sq1 += qb * qb;
        sk0 += ka * ka; sk1 += kb * kb;
    }
    __shared__ float smq[8][64], smk[8][64];
    smq[sub][d2] = sq0; smq[sub][d2 + 1] = sq1;
    smk[sub][d2] = sk0; smk[sub][d2 + 1] = sk1;
    __syncthreads();
    if (tid < 64) {
        float q = 0.f, k = 0.f;
#pragma unroll
        for (int s = 0; s < 8; s++) { q += smq[s][tid]; k += smk[s][tid]; }
        psq[((size_t)bh * 16 + part) * 64 + tid] = q;
        psk[((size_t)bh * 16 + part) * 64 + tid] = k;
    }
}

__global__ void rs2_kernel(const float* __restrict__ psq,
                           const float* __restrict__ psk,
                           const float* __restrict__ temp,
                           float* __restrict__ rs) {
    int bh = blockIdx.x, d = threadIdx.x;
    int h = bh % NH_;
    float q = 0.f, k = 0.f;
#pragma unroll
    for (int p = 0; p < 16; p++) {
        q += psq[((size_t)bh * 16 + p) * 64 + d];
        k += psk[((size_t)bh * 16 + p) * 64 + d];
    }
    float qn = fmaxf(sqrtf(q), 1e-12f);
    float kn = fmaxf(sqrtf(k), 1e-12f);
    rs[(size_t)bh * DH_ + d] = temp[h] / (qn * kn);
}

// ---------------- tensor-core fused flash attention --------------------------
// S = Qhi.Khi (1 MMA). P = exp(S) directly (logits bounded post-l2norm).
// O = Phi.Vhi (1 MMA). Single-sync pipeline. o stored fp16.
#define FAT_STAGE 16384u
#define FAT_QOFF  32768u
#define FAT_SMEM  (32768 + 16384 + 256)

__device__ __forceinline__ void fat_loadkv(
    uint32_t buf, int tid, size_t kvbase, int kc,
    const h16* __restrict__ khi, const h16* __restrict__ vhi) {
#pragma unroll
    for (int it = 0; it < 2; it++) {
        int idx = it * 256 + tid;
        int r = idx >> 3, cg = idx & 7;
        uint32_t so = SWZ((uint32_t)(r * 128 + cg * 16));
        size_t g = kvbase + (size_t)(kc + r) * DH_ + cg * 8;
        cp16(buf +    0u + so, khi + g);
        cp16(buf + 8192u + so, vhi + g);
    }
    asm volatile("cp.async.commit_group;" ::: "memory");
}

__global__ __launch_bounds__(256, 2)
void fat_kernel(const h16* __restrict__ qhi,
                const float* __restrict__ rs,
                const h16* __restrict__ khi, const h16* __restrict__ vhi,
                h16* __restrict__ ohi) {
    extern __shared__ char smc[];
    uint32_t sb = smem_u32(smc);
    float* rss = (float*)(smc + FAT_QOFF + 16384);
    int bh = blockIdx.y;
    int b = bh >> 3, h = bh & 7;
    int q0 = blockIdx.x * 128;
    int tid = threadIdx.x, wid = tid >> 5, lane = tid & 31;
    int mb = wid * 16;

    if (tid < 64) rss[tid] = rs[bh * DH_ + tid];
    const size_t kvbase = (size_t)bh * HW_ * DH_;
    fat_loadkv(sb, tid, kvbase, 0, khi, vhi);
    __syncthreads();

#pragma unroll
    for (int v = 0; v < 8; v++) {
        int idx = v * 256 + tid;
        int row = idx >> 4, dq = (idx & 15) * 4;
        size_t qoff = ((size_t)bh * HW_ + q0 + row) * DH_ + dq;
        __half2 ha = *(const __half2*)&qhi[qoff];
        __half2 hb = *(const __half2*)&qhi[qoff + 2];
        float qx = __half2float(ha.x) * rss[dq];
        float qy = __half2float(ha.y) * rss[dq + 1];
        float qz = __half2float(hb.x) * rss[dq + 2];
        float qw = __half2float(hb.y) * rss[dq + 3];
        uint32_t off = SWZ((uint32_t)(row * 128 + dq * 2));
        *(uint32_t*)(smc + FAT_QOFF + off)     = pack2(qx, qy);
        *(uint32_t*)(smc + FAT_QOFF + off + 4) = pack2(qz, qw);
    }

    float o[8][4];
#pragma unroll
    for (int j = 0; j < 8; j++)
#pragma unroll
        for (int q = 0; q < 4; q++) o[j][q] = 0.f;
    float l0 = 0.f, l1 = 0.f;

    for (int kt = 0; kt < 16; kt++) {
        asm volatile("cp.async.wait_group 0;" ::: "memory");
        __syncthreads();
        if (kt + 1 < 16)
            fat_loadkv(sb + (uint32_t)((kt + 1) & 1) * FAT_STAGE, tid, kvbase,
                       (kt + 1) * 64, khi, vhi);
        uint32_t cur = sb + (uint32_t)(kt & 1) * FAT_STAGE;

        // ---- S = Q.K^T
        float s[8][4];
#pragma unroll
        for (int j = 0; j < 8; j++)
#pragma unroll
            for (int q = 0; q < 4; q++) s[j][q] = 0.f;
#pragma unroll
        for (int ks = 0; ks < 4; ks++) {
            uint32_t qao = SWZ((uint32_t)((mb + (lane & 15)) * 128 +
                                          (lane >> 4) * 16 + ks * 32));
            uint32_t qh4[4];
            ldsm4(qh4, sb + FAT_QOFF + qao);
            uint32_t brow = (uint32_t)(((lane & 7) + ((lane >> 4) & 1) * 8) * 128 +
                                       ((lane >> 3) & 1) * 16 + ks * 32);
#pragma unroll
            for (int np = 0; np < 4; np++) {
                uint32_t bo = SWZ(brow + (uint32_t)(np * 16 * 128));
                uint32_t kh4[4];
                ldsm4(kh4, cur + bo);
#pragma unroll
                for (int half = 0; half < 2; half++) {
                    int j = np * 2 + half;
                    const uint32_t bhh[2] = {kh4[half * 2], kh4[half * 2 + 1]};
                    mma16816(s[j], qh4, bhh);
                }
            }
        }

        // ---- P = exp(S); accumulate row sums
        float sum0 = 0.f, sum1 = 0.f;
#pragma unroll
        for (int j = 0; j < 8; j++) {
            s[j][0] = __expf(s[j][0]);
            s[j][1] = __expf(s[j][1]);
            s[j][2] = __expf(s[j][2]);
            s[j][3] = __expf(s[j][3]);
            sum0 += s[j][0] + s[j][1];
            sum1 += s[j][2] + s[j][3];
        }
        l0 += sum0; l1 += sum1;

        // ---- O += Phi.Vhi
#pragma unroll
        for (int ks = 0; ks < 4; ks++) {
            int j0 = 2 * ks, j1 = 2 * ks + 1;
            uint32_t ph[4];
            ph[0] = pack2(s[j0][0], s[j0][1]);
            ph[1] = pack2(s[j0][2], s[j0][3]);
            ph[2] = pack2(s[j1][0], s[j1][1]);
            ph[3] = pack2(s[j1][2], s[j1][3]);
            uint32_t vrow = (uint32_t)((ks * 16 + (lane & 7) + ((lane >> 3) & 1) * 8) * 128 +
                                       ((lane >> 4) & 1) * 16);
#pragma unroll
            for (int np = 0; np < 4; np++) {
                uint32_t vo = SWZ(vrow + (uint32_t)(np * 32));
                uint32_t vh4[4];
                ldsm4t(vh4, cur + 8192u + vo);
#pragma unroll
                for (int half = 0; half < 2; half++) {
                    int j = np * 2 + half;
                    const uint32_t bvh[2] = {vh4[half * 2], vh4[half * 2 + 1]};
                    mma16816(o[j], ph, bvh);
                }
            }
        }
    }

    // finalize row sums across the quad, normalize, store fp16
    l0 += __shfl_xor_sync(0xffffffffu, l0, 1);
    l0 += __shfl_xor_sync(0xffffffffu, l0, 2);
    l1 += __shfl_xor_sync(0xffffffffu, l1, 1);
    l1 += __shfl_xor_sync(0xffffffffu, l1, 2);
    float inv0 = 1.f / l0, inv1 = 1.f / l1;
    int r0 = lane >> 2, cc = (lane & 3) * 2;
    int row0 = q0 + mb + r0, row1 = row0 + 8;
#pragma unroll
    for (int j = 0; j < 8; j++) {
        int col = h * DH_ + j * 8 + cc;
        size_t off0 = ((size_t)(b * HW_ + row0)) * C_ + col;
        size_t off1 = ((size_t)(b * HW_ + row1)) * C_ + col;
        *(uint32_t*)&ohi[off0] = pack2(o[j][0] * inv0, o[j][1] * inv0);
        *(uint32_t*)&ohi[off1] = pack2(o[j][2] * inv1, o[j][3] * inv1);
    }
}

// ---------------- LayerNorm over C + residual + transpose (warp-reduced) ----
__global__ void ln_residual_kernel(const float* __restrict__ ob,
                                   const float* __restrict__ x,
                                   const float* __restrict__ g,
                                   const float* __restrict__ be,
                                   float* __restrict__ y) {
    int row = blockIdx.x;
    int b = row >> 10, n = row & 1023;
    const float* pr = ob + (size_t)row * C_;
    int tid = threadIdx.x, lane = tid & 31, wid = tid >> 5;
    float v0 = pr[tid], v1 = pr[tid + 256];
    __shared__ float red[8];
    __shared__ float bc[2];

    float s = v0 + v1;
#pragma unroll
    for (int off = 16; off; off >>= 1) s += __shfl_xor_sync(0xffffffffu, s, off);
    if (lane == 0) red[wid] = s;
    __syncthreads();
    if (tid == 0) {
        float t = 0.f;
#pragma unroll
        for (int i = 0; i < 8; i++) t += red[i];
        bc[0] = t * (1.0f / C_);
    }
    __syncthreads();
    float mean = bc[0];
    float d0 = v0 - mean, d1 = v1 - mean;
    s = d0 * d0 + d1 * d1;
#pragma unroll
    for (int off = 16; off; off >>= 1) s += __shfl_xor_sync(0xffffffffu, s, off);
    if (lane == 0) red[wid] = s;
    __syncthreads();
    if (tid == 0) {
        float t = 0.f;
#pragma unroll
        for (int i = 0; i < 8; i++) t += red[i];
        bc[1] = rsqrtf(t * (1.0f / C_) + 1e-5f);
    }
    __syncthreads();
    float rstd = bc[1];
    int c0 = tid, c1 = tid + 256;
    size_t i0 = ((size_t)b * C_ + c0) * HW_ + n;
    size_t i1 = ((size_t)b * C_ + c1) * HW_ + n;
    y[i0] = d0 * rstd * g[c0] + be[c0] + x[i0];
    y[i1] = d1 * rstd * g[c1] + be[c1] + x[i1];
}

// ---------------- fused depthwise 3x3 + transpose -> fp16 --------------------
__global__ void dwt_kernel(const float* __restrict__ y,
                           const float* __restrict__ w,
                           const float* __restrict__ bias,
                           h16* __restrict__ hi) {
    __shared__ float yt[32][3][33];
    __shared__ float ot[32][33];   // [w][c]
    int hh = blockIdx.x, c0 = blockIdx.y * 32, b = blockIdx.z;
    int tid = threadIdx.x;
    int c = tid >> 3, wg = (tid & 7) * 4;

#pragma unroll
    for (int r = 0; r < 3; r++) {
        int ih = hh + r - 1;
        float4 v = make_float4(0.f, 0.f, 0.f, 0.f);
        if (ih >= 0 && ih < H_)
            v = *(const float4*)&y[((size_t)(b * C_ + c0 + c)) * HW_ + ih * W_ + wg];
        yt[c][r][wg + 0] = v.x; yt[c][r][wg + 1] = v.y;
        yt[c][r][wg + 2] = v.z; yt[c][r][wg + 3] = v.w;
    }
    float wc[9];
#pragma unroll
    for (int i = 0; i < 9; i++) wc[i] = w[(c0 + c) * 9 + i];
    float bs = bias[c0 + c];
    __syncthreads();

#pragma unroll
    for (int j = 0; j < 4; j++) {
        int ww = wg + j;
        float acc = bs;
#pragma unroll
        for (int ki = 0; ki < 3; ki++)
#pragma unroll
            for (int kj = 0; kj < 3; kj++) {
                int iw = ww + kj - 1;
                if (iw >= 0 && iw < W_) acc += wc[ki * 3 + kj] * yt[c][ki][iw];
            }
        ot[ww][c] = acc;
    }
    __syncthreads();

    int w2 = tid >> 3, cg = (tid & 7) * 4;
    int token = hh * W_ + w2;
    size_t base = ((size_t)b * HW_ + token) * C_ + c0 + cg;
    *(uint32_t*)&hi[base]     = pack2(ot[w2][cg],     ot[w2][cg + 1]);
    *(uint32_t*)&hi[base + 2] = pack2(ot[w2][cg + 2], ot[w2][cg + 3]);
}

// ---------------- launch ------------------------------------------------------
extern "C" void kernel_launch(void* const* d_in, const int* in_sizes, int n_in,
                              void* d_out, int out_size) {
    const float* x      = (const float*)d_in[0];
    const float* qkv_w  = (const float*)d_in[1];
    const float* proj_w = (const float*)d_in[2];
    const float* proj_b = (const float*)d_in[3];
    const float* temper = (const float*)d_in[4];
    const float* ln_g   = (const float*)d_in[5];
    const float* ln_b   = (const float*)d_in[6];
    const float* pos    = (const float*)d_in[7];
    const float* dw_w   = (const float*)d_in[8];
    const float* dw_b   = (const float*)d_in[9];
    const float* pw_w   = (const float*)d_in[10];
    const float* pw_b   = (const float*)d_in[11];
    float* out = (float*)d_out;

    h16 *thi, *w1hi, *w2hi, *w3hi;
    h16 *ohi, *dThi, *qhi, *khi, *vhi;
    float *rs, *ob, *y, *psq, *psk;
    cudaGetSymbolAddress((void**)&thi,  g_thi);
    cudaGetSymbolAddress((void**)&w1hi, g_w1hi);
    cudaGetSymbolAddress((void**)&w2hi, g_w2hi);
    cudaGetSymbolAddress((void**)&w3hi, g_w3hi);
    cudaGetSymbolAddress((void**)&ohi,  g_ohi);
    cudaGetSymbolAddress((void**)&dThi, g_dThi);
    cudaGetSymbolAddress((void**)&qhi,  g_qhi);
    cudaGetSymbolAddress((void**)&khi,  g_khi);
    cudaGetSymbolAddress((void**)&vhi,  g_vhi);
    cudaGetSymbolAddress((void**)&rs,   g_rs);
    cudaGetSymbolAddress((void**)&psq,  g_psq);
    cudaGetSymbolAddress((void**)&psk,  g_psk);
    cudaGetSymbolAddress((void**)&ob,   g_ob);
    cudaGetSymbolAddress((void**)&y,    g_y);

    cudaFuncSetAttribute(fat_kernel,
                         cudaFuncAttributeMaxDynamicSharedMemorySize, FAT_SMEM);
    cudaFuncSetAttribute(gemm_tc,
                         cudaFuncAttributeMaxDynamicSharedMemorySize, GS1);

    // prep: weight conversions + t = transpose(x)+pos (one launch)
    prep_kernel<<<SPLIT_BLOCKS + BT_BLOCKS, 256>>>(qkv_w, proj_w, pw_w,
                                                   x, pos, thi);
    // qkv GEMM: 1-term fp16, head-major split output (occ 2)
    gemm_tc<<<dim3(C3_/128, (B_*HW_)/128, 1), 256, GS1>>>(
        thi, w1hi, nullptr, nullptr, nullptr, C_, 0, 0, 0, 1);
    // rs two-stage reduction
    rs1_kernel<<<B_*NH_*16, 256>>>(psq, psk);
    rs2_kernel<<<B_*NH_, 64>>>(psq, psk, temper, rs);
    // tensor-core fused attention -> ohi
    fat_kernel<<<dim3(HW_/128, B_*NH_), 256, FAT_SMEM>>>(
        qhi, rs, khi, vhi, ohi);
    // proj = ohi @ w2hi^T + proj_b (1-term, occ 2)
    gemm_tc<<<dim3(C_/128, (B_*HW_)/128, 1), 256, GS1>>>(
        ohi, w2hi, proj_b, nullptr, ob, C_, C_, 0, 0, 0);
    // LN + residual + transpose to [B,C,HW]
    ln_residual_kernel<<<B_*HW_, 256>>>(ob, x, ln_g, ln_b, y);
    // fused depthwise 3x3 + transpose (fp16)
    dwt_kernel<<<dim3(H_, C_/32, B_), 256>>>(y, dw_w, dw_b, dThi);
    // pointwise (1-term, occ 2) + bias + residual -> out
    gemm_tc<<<dim3(HW_/128, C_/128, B_), 256, GS1>>>(
        w3hi, dThi, pw_b, y, out, C_, HW_,
        (long)HW_*C_, (long)C_*HW_, 0);
}